// round 10
// baseline (speedup 1.0000x reference)
#include <cuda_runtime.h>
#include <math.h>
#include <stdint.h>

// Problem constants
#define NB   4
#define SEQ  2048
#define DM   1024
#define NH   16
#define HD   64
#define MROWS (NB*SEQ)          // 8192

// Scratch (device globals — no allocation allowed)
__device__ float g_q  [MROWS*DM];
__device__ float g_k  [MROWS*DM];
__device__ float g_v  [MROWS*DM];
__device__ float g_att[MROWS*DM];
__device__ float g_wr [4][DM*DM];   // tf32-rounded weights (natural [k][n] layout)

__device__ __forceinline__ uint32_t tf32r(float x) {
    uint32_t u;
    asm("cvt.rna.tf32.f32 %0, %1;" : "=r"(u) : "f"(x));
    return u;
}
__device__ __forceinline__ float tf32rf(float x) {
    return __uint_as_float(tf32r(x));
}

__device__ __forceinline__ uint32_t smem_u32(const void* p) {
    uint32_t a;
    asm("{ .reg .u64 t; cvta.to.shared.u64 t, %1; cvt.u32.u64 %0, t; }"
        : "=r"(a) : "l"(p));
    return a;
}

#define CP_ASYNC16(dst, src) \
    asm volatile("cp.async.cg.shared.global [%0], [%1], 16;" \
                 :: "r"(dst), "l"(src) : "memory")
#define CP_COMMIT() asm volatile("cp.async.commit_group;" ::: "memory")
#define CP_WAIT0()  asm volatile("cp.async.wait_group 0;" ::: "memory")
#define CP_WAIT1()  asm volatile("cp.async.wait_group 1;" ::: "memory")

#define MMA_TF32(c0, c1, c2, c3, a0, a1, a2, a3, b0, b1) \
    asm volatile("mma.sync.aligned.m16n8k8.row.col.f32.tf32.tf32.f32 " \
        "{%0,%1,%2,%3}, {%4,%5,%6,%7}, {%8,%9}, {%0,%1,%2,%3};" \
        : "+f"(c0), "+f"(c1), "+f"(c2), "+f"(c3) \
        : "r"(a0), "r"(a1), "r"(a2), "r"(a3), "r"(b0), "r"(b1))

// ---------------------------------------------------------------------------
// Weight pre-round: g_wr[i] = tf32_rna(W[i]) elementwise.
// ---------------------------------------------------------------------------
__global__ __launch_bounds__(256) void round_w_k(
    const float* __restrict__ W0, const float* __restrict__ W1,
    const float* __restrict__ W2, const float* __restrict__ W3,
    float* __restrict__ D)
{
    const int n4 = DM * DM / 4;
    for (int i = blockIdx.x * blockDim.x + threadIdx.x; i < 4 * n4;
         i += gridDim.x * blockDim.x) {
        const int w = i / n4, j = i - w * n4;
        const float* W = (w == 0) ? W0 : (w == 1) ? W1 : (w == 2) ? W2 : W3;
        float4 v = *(const float4*)(W + 4 * (size_t)j);
        v.x = tf32rf(v.x); v.y = tf32rf(v.y);
        v.z = tf32rf(v.z); v.w = tf32rf(v.w);
        *(float4*)(D + (size_t)w * DM * DM + 4 * (size_t)j) = v;
    }
}

// ---------------------------------------------------------------------------
// Tensor-core GEMM (tf32 mma.sync), 3-stage cp.async pipeline.
// CTA tile 256x128, 256 threads = 8 warps (4m x 2n), warp 64x64.
// Per chunk per warp: 128 LDS : 128 MMA.
//   As[3][256][36] : A chunk [m][k]  (A-frags: bank 4g+kq, CF)
//   Bs[3][32][136] : W chunk [k][n]  (B-frags: bank 8kq+g, CF)
// ---------------------------------------------------------------------------
#define LDA 36
#define LDB 136
#define GSTG (256 * LDA + 32 * LDB)            // 13568 words/stage
#define GOFF_A(s) ((s) * GSTG)
#define GOFF_B(s) ((s) * GSTG + 256 * LDA)
#define GEMM_SMEM (3 * GSTG * 4)               // 162816 B

__global__ __launch_bounds__(256, 1) void gemm_mma_k(
    const float* __restrict__ A0, const float* __restrict__ A1,
    const float* __restrict__ A2,
    const float* __restrict__ W0, const float* __restrict__ W1,
    const float* __restrict__ W2,
    const float* __restrict__ b0_, const float* __restrict__ b1_,
    const float* __restrict__ b2_,
    float* __restrict__ C0, float* __restrict__ C1, float* __restrict__ C2,
    int roundC)
{
    extern __shared__ uint32_t smg[];
    const uint32_t sbase = smem_u32(smg);

    const int z = blockIdx.z;
    const float* A    = (z == 0) ? A0 : (z == 1) ? A1 : A2;
    const float* W    = (z == 0) ? W0 : (z == 1) ? W1 : W2;
    const float* bias = (z == 0) ? b0_ : (z == 1) ? b1_ : b2_;
    float*       C    = (z == 0) ? C0 : (z == 1) ? C1 : C2;

    const int t    = threadIdx.x;
    const int lane = t & 31;
    const int wid  = t >> 5;           // 0..7
    const int m0   = blockIdx.y * 256;
    const int n0   = blockIdx.x * 128;
    const int wm   = (wid & 3) * 64;   // warp m offset (0..192)
    const int wn   = (wid >> 2) * 64;  // warp n offset (0/64)
    const int g    = lane >> 2;
    const int kq   = lane & 3;

    // cp.async mapping — A: rows ar + i*32 (i=0..7), cols ac4..ac4+3
    const int ar  = t >> 3;            // 0..31
    const int ac4 = (t & 7) << 2;      // 0..28
    // B: rows br + i*8 (i=0..3), cols bc4..bc4+3
    const int br  = t >> 5;            // 0..7
    const int bc4 = (t & 31) << 2;     // 0..124

    float acc[4][8][4];
    #pragma unroll
    for (int mi = 0; mi < 4; mi++)
        #pragma unroll
        for (int nj = 0; nj < 8; nj++)
            #pragma unroll
            for (int r = 0; r < 4; r++) acc[mi][nj][r] = 0.f;

    // ---- Prologue: issue chunks 0 and 1 (separate groups) ----
    #pragma unroll
    for (int pc = 0; pc < 2; pc++) {
        const int kf = pc * 32;
        const float* ap = A + (size_t)(m0 + ar) * DM + kf + ac4;
        #pragma unroll
        for (int i = 0; i < 8; i++)
            CP_ASYNC16(sbase + (GOFF_A(pc) + (ar + i * 32) * LDA + ac4) * 4,
                       ap + (size_t)(i * 32) * DM);
        const float* wp = W + (size_t)(kf + br) * DM + n0 + bc4;
        #pragma unroll
        for (int i = 0; i < 4; i++)
            CP_ASYNC16(sbase + (GOFF_B(pc) + (br + i * 8) * LDB + bc4) * 4,
                       wp + (size_t)(i * 8) * DM);
        CP_COMMIT();
    }

    #pragma unroll 1
    for (int kt = 0; kt < 32; kt++) {
        const int cur = kt % 3;

        if (kt + 1 < 32) CP_WAIT1(); else CP_WAIT0();
        __syncthreads();

        if (kt + 2 < 32) {
            const int stg = (kt + 2) % 3;
            const int kf  = (kt + 2) * 32;
            const float* ap = A + (size_t)(m0 + ar) * DM + kf + ac4;
            #pragma unroll
            for (int i = 0; i < 8; i++)
                CP_ASYNC16(sbase + (GOFF_A(stg) + (ar + i * 32) * LDA + ac4) * 4,
                           ap + (size_t)(i * 32) * DM);
            const float* wp = W + (size_t)(kf + br) * DM + n0 + bc4;
            #pragma unroll
            for (int i = 0; i < 4; i++)
                CP_ASYNC16(sbase + (GOFF_B(stg) + (br + i * 8) * LDB + bc4) * 4,
                           wp + (size_t)(i * 8) * DM);
            CP_COMMIT();
        }

        const uint32_t* As = smg + GOFF_A(cur);
        const uint32_t* Bs = smg + GOFF_B(cur);

        #pragma unroll
        for (int ks = 0; ks < 4; ks++) {
            const int k0 = ks * 8 + kq;
            uint32_t af[4][4];
            #pragma unroll
            for (int mi = 0; mi < 4; mi++) {
                const int row = wm + mi * 16 + g;
                af[mi][0] = As[row * LDA + k0];
                af[mi][1] = As[(row + 8) * LDA + k0];
                af[mi][2] = As[row * LDA + k0 + 4];
                af[mi][3] = As[(row + 8) * LDA + k0 + 4];
            }
            #pragma unroll
            for (int nj = 0; nj < 8; nj++) {
                const int col = wn + nj * 8 + g;
                uint32_t bb0 = Bs[k0 * LDB + col];
                uint32_t bb1 = Bs[(k0 + 4) * LDB + col];
                #pragma unroll
                for (int mi = 0; mi < 4; mi++)
                    MMA_TF32(acc[mi][nj][0], acc[mi][nj][1],
                             acc[mi][nj][2], acc[mi][nj][3],
                             af[mi][0], af[mi][1], af[mi][2], af[mi][3],
                             bb0, bb1);
            }
        }
    }

    #pragma unroll
    for (int mi = 0; mi < 4; mi++) {
        const int row = m0 + wm + mi * 16 + g;
        #pragma unroll
        for (int nj = 0; nj < 8; nj++) {
            const int col = n0 + wn + nj * 8 + kq * 2;
            const float bx = bias[col], by = bias[col + 1];
            float2 v0 = make_float2(acc[mi][nj][0] + bx, acc[mi][nj][1] + by);
            float2 v1 = make_float2(acc[mi][nj][2] + bx, acc[mi][nj][3] + by);
            if (roundC) {
                v0.x = tf32rf(v0.x); v0.y = tf32rf(v0.y);
                v1.x = tf32rf(v1.x); v1.y = tf32rf(v1.y);
            }
            *(float2*)(C + (size_t)row * DM + col)       = v0;
            *(float2*)(C + (size_t)(row + 8) * DM + col) = v1;
        }
    }
}

// ---------------------------------------------------------------------------
// Tensor-core flash attention (tf32 mma.sync), 3-stage cp.async pipeline.
// CTA: (b,h) x 256 q rows, 256 threads = 8 warps; warp owns 32 q rows (mi=2).
// 32 chunks of 64 keys. K/V traffic halves vs 128-row tiles.
// ---------------------------------------------------------------------------
#define KST 68
#define VST 72
#define ASTG (64 * KST + 64 * VST + 64)        // 9024 words/stage
#define OFF_KS(s)   ((s) * ASTG)
#define OFF_VS(s)   ((s) * ASTG + 64 * KST)
#define OFF_MADD(s) ((s) * ASTG + 64 * KST + 64 * VST)
#define OFF_PS (3 * ASTG)                      // 27072
#define ATT_WORDS (OFF_PS + 256 * KST)         // 44480 words
#define ATT_SMEM  (ATT_WORDS * 4)              // 177920 B

__global__ __launch_bounds__(256, 1) void attn_mma_k(
    const float* __restrict__ q, const float* __restrict__ k,
    const float* __restrict__ v, const int* __restrict__ mask,
    float* __restrict__ o)
{
    extern __shared__ uint32_t smu[];
    uint32_t* Ps = smu + OFF_PS;
    const uint32_t sbase = smem_u32(smu);

    const int t    = threadIdx.x;
    const int lane = t & 31;
    const int wid  = t >> 5;           // 0..7
    const int g    = lane >> 2;
    const int kq   = lane & 3;
    const int bh   = blockIdx.x;
    const int b    = bh >> 4;
    const int h    = bh & 15;
    const int qt   = blockIdx.y;

    const int qbase = b * SEQ + qt * 256;
    const int kbase = b * SEQ;
    const int hcol  = h * HD;
    const int wr    = wid * 32;        // warp's first q row

    const int crow = t >> 4;           // 0..15
    const int cc4  = (t & 15) << 2;

    // ---- Stage Q tile (scaled by 1/8, tf32-rounded) into Ps ----
    #pragma unroll
    for (int it = 0; it < 16; it++) {
        int idx = it * 256 + t;
        int r = idx >> 4, c4 = (idx & 15) << 2;
        float4 qv = *(const float4*)(q + (size_t)(qbase + r) * DM + hcol + c4);
        uint32_t* p = &Ps[r * KST + c4];
        p[0] = tf32r(qv.x * 0.125f); p[1] = tf32r(qv.y * 0.125f);
        p[2] = tf32r(qv.z * 0.125f); p[3] = tf32r(qv.w * 0.125f);
    }

    // ---- Prologue: issue K/V for chunks 0 and 1 ----
    #pragma unroll
    for (int pc = 0; pc < 2; pc++) {
        const size_t rb = (size_t)(kbase + pc * 64 + crow) * DM + hcol + cc4;
        const float* kp = k + rb;
        const float* vp = v + rb;
        #pragma unroll
        for (int it = 0; it < 4; it++) {
            const int r = crow + it * 16;
            CP_ASYNC16(sbase + (OFF_KS(pc) + r * KST + cc4) * 4, kp + (size_t)(it * 16) * DM);
            CP_ASYNC16(sbase + (OFF_VS(pc) + r * VST + cc4) * 4, vp + (size_t)(it * 16) * DM);
        }
        CP_COMMIT();
        if (t < 64)
            ((float*)(smu + OFF_MADD(pc)))[t] =
                mask[b * SEQ + pc * 64 + t] ? 0.f : -1e9f;
    }

    __syncthreads();   // Q staging + madd visible

    // Q A-fragments (register-resident for the whole loop)
    uint32_t qf[2][8][4];
    #pragma unroll
    for (int mi = 0; mi < 2; mi++)
        #pragma unroll
        for (int ks = 0; ks < 8; ks++) {
            const int k0 = ks * 8 + kq;
            const int row = wr + mi * 16 + g;
            qf[mi][ks][0] = Ps[row * KST + k0];
            qf[mi][ks][1] = Ps[(row + 8) * KST + k0];
            qf[mi][ks][2] = Ps[row * KST + k0 + 4];
            qf[mi][ks][3] = Ps[(row + 8) * KST + k0 + 4];
        }

    float mx[2][2], lx[2][2];
    #pragma unroll
    for (int mi = 0; mi < 2; mi++) {
        mx[mi][0] = -1e30f; mx[mi][1] = -1e30f;
        lx[mi][0] = 0.f;    lx[mi][1] = 0.f;
    }
    float acc[2][8][4];
    #pragma unroll
    for (int mi = 0; mi < 2; mi++)
        #pragma unroll
        for (int nt = 0; nt < 8; nt++)
            #pragma unroll
            for (int j = 0; j < 4; j++) acc[mi][nt][j] = 0.f;

    #pragma unroll 1
    for (int kt = 0; kt < 32; kt++) {
        const int cur = kt % 3;

        if (kt + 1 < 32) CP_WAIT1(); else CP_WAIT0();
        __syncthreads();

        if (kt + 2 < 32) {
            const int stg = (kt + 2) % 3;
            const size_t rb = (size_t)(kbase + (kt + 2) * 64 + crow) * DM + hcol + cc4;
            const float* kp = k + rb;
            const float* vp = v + rb;
            #pragma unroll
            for (int it = 0; it < 4; it++) {
                const int r = crow + it * 16;
                CP_ASYNC16(sbase + (OFF_KS(stg) + r * KST + cc4) * 4, kp + (size_t)(it * 16) * DM);
                CP_ASYNC16(sbase + (OFF_VS(stg) + r * VST + cc4) * 4, vp + (size_t)(it * 16) * DM);
            }
            CP_COMMIT();
            if (t < 64)
                ((float*)(smu + OFF_MADD(stg)))[t] =
                    mask[b * SEQ + (kt + 2) * 64 + t] ? 0.f : -1e9f;
        }

        const uint32_t* Ks = smu + OFF_KS(cur);
        const uint32_t* Vs = smu + OFF_VS(cur);
        const float* madd  = (const float*)(smu + OFF_MADD(cur));

        // ---- S = (Q/8) K^T ----
        float s[2][8][4];
        #pragma unroll
        for (int mi = 0; mi < 2; mi++)
            #pragma unroll
            for (int nt = 0; nt < 8; nt++)
                #pragma unroll
                for (int j = 0; j < 4; j++) s[mi][nt][j] = 0.f;

        #pragma unroll
        for (int ks = 0; ks < 8; ks++) {
            const int k0 = ks * 8 + kq;
            #pragma unroll
            for (int nt = 0; nt < 8; nt++) {
                uint32_t bb0 = Ks[(nt * 8 + g) * KST + k0];
                uint32_t bb1 = Ks[(nt * 8 + g) * KST + k0 + 4];
                #pragma unroll
                for (int mi = 0; mi < 2; mi++)
                    MMA_TF32(s[mi][nt][0], s[mi][nt][1], s[mi][nt][2], s[mi][nt][3],
                             qf[mi][ks][0], qf[mi][ks][1],
                             qf[mi][ks][2], qf[mi][ks][3], bb0, bb1);
            }
        }

        // ---- Online softmax per mi (rows g, g+8; cols in-warp) ----
        #pragma unroll
        for (int mi = 0; mi < 2; mi++) {
            float rmax0 = -1e30f, rmax1 = -1e30f;
            #pragma unroll
            for (int nt = 0; nt < 8; nt++) {
                float2 md = *(float2*)&madd[nt * 8 + 2 * kq];
                s[mi][nt][0] += md.x; s[mi][nt][1] += md.y;
                s[mi][nt][2] += md.x; s[mi][nt][3] += md.y;
                rmax0 = fmaxf(rmax0, fmaxf(s[mi][nt][0], s[mi][nt][1]));
                rmax1 = fmaxf(rmax1, fmaxf(s[mi][nt][2], s[mi][nt][3]));
            }
            rmax0 = fmaxf(rmax0, __shfl_xor_sync(0xffffffffu, rmax0, 1));
            rmax0 = fmaxf(rmax0, __shfl_xor_sync(0xffffffffu, rmax0, 2));
            rmax1 = fmaxf(rmax1, __shfl_xor_sync(0xffffffffu, rmax1, 1));
            rmax1 = fmaxf(rmax1, __shfl_xor_sync(0xffffffffu, rmax1, 2));

            const float mn0 = fmaxf(mx[mi][0], rmax0);
            const float mn1 = fmaxf(mx[mi][1], rmax1);
            const float a0  = __expf(mx[mi][0] - mn0);
            const float a1  = __expf(mx[mi][1] - mn1);
            float sum0 = 0.f, sum1 = 0.f;

            const int row = wr + mi * 16 + g;
            #pragma unroll
            for (int nt = 0; nt < 8; nt++) {
                float p0 = __expf(s[mi][nt][0] - mn0);
                float p1 = __expf(s[mi][nt][1] - mn0);
                float p2 = __expf(s[mi][nt][2] - mn1);
                float p3 = __expf(s[mi][nt][3] - mn1);
                sum0 += p0 + p1;
                sum1 += p2 + p3;
                uint2 w0 = make_uint2(tf32r(p0), tf32r(p1));
                uint2 w1 = make_uint2(tf32r(p2), tf32r(p3));
                *(uint2*)&Ps[row * KST + nt * 8 + 2 * kq]       = w0;
                *(uint2*)&Ps[(row + 8) * KST + nt * 8 + 2 * kq] = w1;
            }
            sum0 += __shfl_xor_sync(0xffffffffu, sum0, 1);
            sum0 += __shfl_xor_sync(0xffffffffu, sum0, 2);
            sum1 += __shfl_xor_sync(0xffffffffu, sum1, 1);
            sum1 += __shfl_xor_sync(0xffffffffu, sum1, 2);

            lx[mi][0] = lx[mi][0] * a0 + sum0;  mx[mi][0] = mn0;
            lx[mi][1] = lx[mi][1] * a1 + sum1;  mx[mi][1] = mn1;
            #pragma unroll
            for (int nt = 0; nt < 8; nt++) {
                acc[mi][nt][0] *= a0; acc[mi][nt][1] *= a0;
                acc[mi][nt][2] *= a1; acc[mi][nt][3] *= a1;
            }
        }
        __syncwarp();   // P stores visible to own-warp LDS

        // ---- O += P V ----
        #pragma unroll
        for (int ks = 0; ks < 8; ks++) {
            const int k0 = ks * 8 + kq;
            uint32_t pa[2][4];
            #pragma unroll
            for (int mi = 0; mi < 2; mi++) {
                const int row = wr + mi * 16 + g;
                pa[mi][0] = Ps[row * KST + k0];
                pa[mi][1] = Ps[(row + 8) * KST + k0];
                pa[mi][2] = Ps[row * KST + k0 + 4];
                pa[mi][3] = Ps[(row + 8) * KST + k0 + 4];
            }
            #pragma unroll
            for (int nt = 0; nt < 8; nt++) {
                uint32_t bb0 = Vs[(k0) * VST + nt * 8 + g];
                uint32_t bb1 = Vs[(k0 + 4) * VST + nt * 8 + g];
                #pragma unroll
                for (int mi = 0; mi < 2; mi++)
                    MMA_TF32(acc[mi][nt][0], acc[mi][nt][1],
                             acc[mi][nt][2], acc[mi][nt][3],
                             pa[mi][0], pa[mi][1], pa[mi][2], pa[mi][3],
                             bb0, bb1);
            }
        }
    }

    // ---- Finalize (tf32-rounded for the output GEMM) ----
    #pragma unroll
    for (int mi = 0; mi < 2; mi++) {
        const float inv0 = (lx[mi][0] > 0.f) ? 1.f / lx[mi][0] : 0.f;
        const float inv1 = (lx[mi][1] > 0.f) ? 1.f / lx[mi][1] : 0.f;
        const int row0 = qbase + wr + mi * 16 + g;
        #pragma unroll
        for (int nt = 0; nt < 8; nt++) {
            const int col = hcol + nt * 8 + 2 * kq;
            float2 o0 = make_float2(tf32rf(acc[mi][nt][0] * inv0),
                                    tf32rf(acc[mi][nt][1] * inv0));
            float2 o1 = make_float2(tf32rf(acc[mi][nt][2] * inv1),
                                    tf32rf(acc[mi][nt][3] * inv1));
            *(float2*)(o + (size_t)row0 * DM + col)       = o0;
            *(float2*)(o + (size_t)(row0 + 8) * DM + col) = o1;
        }
    }
}

// ---------------------------------------------------------------------------
// Launch: weight pre-round -> QKV GEMMs (fused, rounded out) -> attention
// (rounded out) -> output GEMM (raw fp32 out).
// ---------------------------------------------------------------------------
extern "C" void kernel_launch(void* const* d_in, const int* in_sizes, int n_in,
                              void* d_out, int out_size)
{
    const float* Q    = (const float*)d_in[0];
    const float* K    = (const float*)d_in[1];
    const float* V    = (const float*)d_in[2];
    const int*   mask = (const int*)  d_in[3];
    const float* Wq   = (const float*)d_in[4];
    const float* bq   = (const float*)d_in[5];
    const float* Wk   = (const float*)d_in[6];
    const float* bk   = (const float*)d_in[7];
    const float* Wv   = (const float*)d_in[8];
    const float* bv   = (const float*)d_in[9];
    const float* Wo   = (const float*)d_in[10];
    const float* bo   = (const float*)d_in[11];
    float* out = (float*)d_out;

    float *gq, *gk, *gv, *ga, *gwr;
    cudaGetSymbolAddress((void**)&gq,  g_q);
    cudaGetSymbolAddress((void**)&gk,  g_k);
    cudaGetSymbolAddress((void**)&gv,  g_v);
    cudaGetSymbolAddress((void**)&ga,  g_att);
    cudaGetSymbolAddress((void**)&gwr, g_wr);
    float* wrq = gwr + 0 * (size_t)DM * DM;
    float* wrk = gwr + 1 * (size_t)DM * DM;
    float* wrv = gwr + 2 * (size_t)DM * DM;
    float* wro = gwr + 3 * (size_t)DM * DM;

    cudaFuncSetAttribute(gemm_mma_k, cudaFuncAttributeMaxDynamicSharedMemorySize,
                         GEMM_SMEM);
    cudaFuncSetAttribute(attn_mma_k, cudaFuncAttributeMaxDynamicSharedMemorySize,
                         ATT_SMEM);

    round_w_k<<<1184, 256>>>(Wq, Wk, Wv, Wo, gwr);

    dim3 qkv_grid(DM / 128, MROWS / 256, 3);  // (8, 32, 3)
    dim3 out_grid(DM / 128, MROWS / 256, 1);  // (8, 32, 1)
    dim3 attn_grid(NB * NH, SEQ / 256);       // (64, 8)

    gemm_mma_k<<<qkv_grid, 256, GEMM_SMEM>>>(Q, K, V, wrq, wrk, wrv,
                                             bq, bk, bv, gq, gk, gv, 1);
    attn_mma_k<<<attn_grid, 256, ATT_SMEM>>>(gq, gk, gv, mask, ga);
    gemm_mma_k<<<out_grid, 256, GEMM_SMEM>>>(ga, ga, ga, wro, wro, wro,
                                             bo, bo, bo, out, out, out, 0);
}

// round 11
// speedup vs baseline: 1.0103x; 1.0103x over previous
#include <cuda_runtime.h>
#include <math.h>
#include <stdint.h>

// Problem constants
#define NB   4
#define SEQ  2048
#define DM   1024
#define NH   16
#define HD   64
#define MROWS (NB*SEQ)          // 8192

// Scratch (device globals — no allocation allowed)
__device__ float g_q  [MROWS*DM];
__device__ float g_k  [MROWS*DM];
__device__ float g_v  [MROWS*DM];
__device__ float g_att[MROWS*DM];
__device__ float g_wt [4][DM*DM];   // tf32-rounded TRANSPOSED weights [n][k]

__device__ __forceinline__ uint32_t tf32r(float x) {
    uint32_t u;
    asm("cvt.rna.tf32.f32 %0, %1;" : "=r"(u) : "f"(x));
    return u;
}
__device__ __forceinline__ float tf32rf(float x) {
    return __uint_as_float(tf32r(x));
}

__device__ __forceinline__ uint32_t smem_u32(const void* p) {
    uint32_t a;
    asm("{ .reg .u64 t; cvta.to.shared.u64 t, %1; cvt.u32.u64 %0, t; }"
        : "=r"(a) : "l"(p));
    return a;
}

#define CP_ASYNC16(dst, src) \
    asm volatile("cp.async.cg.shared.global [%0], [%1], 16;" \
                 :: "r"(dst), "l"(src) : "memory")
#define CP_COMMIT() asm volatile("cp.async.commit_group;" ::: "memory")
#define CP_WAIT0()  asm volatile("cp.async.wait_group 0;" ::: "memory")

#define MMA_TF32(c0, c1, c2, c3, a0, a1, a2, a3, b0, b1) \
    asm volatile("mma.sync.aligned.m16n8k8.row.col.f32.tf32.tf32.f32 " \
        "{%0,%1,%2,%3}, {%4,%5,%6,%7}, {%8,%9}, {%0,%1,%2,%3};" \
        : "+f"(c0), "+f"(c1), "+f"(c2), "+f"(c3) \
        : "r"(a0), "r"(a1), "r"(a2), "r"(a3), "r"(b0), "r"(b1))

#define LDSM4(r0, r1, r2, r3, addr) \
    asm volatile("ldmatrix.sync.aligned.m8n8.x4.shared.b16 {%0,%1,%2,%3}, [%4];" \
        : "=r"(r0), "=r"(r1), "=r"(r2), "=r"(r3) : "r"(addr))

// ---------------------------------------------------------------------------
// Weight transpose + tf32 round: D[z][n*DM+k] = tf32_rna(W_z[k*DM+n]).
// grid (DM/32, DM/32, 4), block (32, 8).
// ---------------------------------------------------------------------------
__global__ __launch_bounds__(256) void round_wt_k(
    const float* __restrict__ W0, const float* __restrict__ W1,
    const float* __restrict__ W2, const float* __restrict__ W3,
    float* __restrict__ D)
{
    __shared__ float tile[32][33];
    const int z = blockIdx.z;
    const float* W = (z == 0) ? W0 : (z == 1) ? W1 : (z == 2) ? W2 : W3;
    float* Dw = D + (size_t)z * DM * DM;

    const int tx = threadIdx.x, ty = threadIdx.y;
    const int x = blockIdx.x * 32 + tx;          // n
    #pragma unroll
    for (int j = ty; j < 32; j += 8)
        tile[j][tx] = W[(size_t)(blockIdx.y * 32 + j) * DM + x];
    __syncthreads();
    const int x2 = blockIdx.y * 32 + tx;         // k
    #pragma unroll
    for (int j = ty; j < 32; j += 8)
        Dw[(size_t)(blockIdx.x * 32 + j) * DM + x2] = tf32rf(tile[tx][j]);
}

// ---------------------------------------------------------------------------
// Tensor-core GEMM (tf32 mma.sync), cp.async double-buffered, ldmatrix frags.
// Weights consumed TRANSPOSED [n][k] (from round_wt_k).
// 128 threads = 4 warps (2m x 2n), warp 64x64, CTA 128x128, BK=32.
// Per chunk per warp: 32 ldmatrix : 128 MMA (was 128 LDS : 128 MMA).
//   As[2][128][36] : A chunk [m][k]
//   Bs[2][128][36] : Wt chunk [n][k]
// ldmatrix rows at stride 36 words -> (4r+c) mod 32 covers all banks, CF.
// ---------------------------------------------------------------------------
#define LDA 36
#define GSTG (2 * 128 * LDA)                   // words per stage (A+B)
#define GOFF_A(s) ((s) * GSTG)
#define GOFF_B(s) ((s) * GSTG + 128 * LDA)
#define GEMM_SMEM (2 * GSTG * 4)               // 73728 B

__global__ __launch_bounds__(128, 2) void gemm_mma_k(
    const float* __restrict__ A0, const float* __restrict__ A1,
    const float* __restrict__ A2,
    const float* __restrict__ W0, const float* __restrict__ W1,
    const float* __restrict__ W2,
    const float* __restrict__ b0_, const float* __restrict__ b1_,
    const float* __restrict__ b2_,
    float* __restrict__ C0, float* __restrict__ C1, float* __restrict__ C2,
    int roundC)
{
    extern __shared__ uint32_t smg[];
    const uint32_t sbase = smem_u32(smg);

    const int z = blockIdx.z;
    const float* A    = (z == 0) ? A0 : (z == 1) ? A1 : A2;
    const float* Wt   = (z == 0) ? W0 : (z == 1) ? W1 : W2;
    const float* bias = (z == 0) ? b0_ : (z == 1) ? b1_ : b2_;
    float*       C    = (z == 0) ? C0 : (z == 1) ? C1 : C2;

    const int t    = threadIdx.x;
    const int lane = t & 31;
    const int wid  = t >> 5;           // 0..3
    const int m0   = blockIdx.y * 128;
    const int n0   = blockIdx.x * 128;
    const int wm   = (wid & 1) * 64;
    const int wn   = (wid >> 1) * 64;
    const int g    = lane >> 2;
    const int kq   = lane & 3;

    // ldmatrix lane addressing: matrices {rows0-7,rows8-15} x {cols0-3,cols4-7}
    const int lrow  = lane & 15;                 // row within 16-row group
    const int lcolw = (lane & 16) ? 4 : 0;       // word col offset (0 or 4)
    // per-mi / per-njp word offsets within a stage
    int a_off[4], b_off[4];
    #pragma unroll
    for (int i = 0; i < 4; i++) {
        a_off[i] = (wm + i * 16 + lrow) * LDA + lcolw;
        b_off[i] = (wn + i * 16 + lrow) * LDA + lcolw;
    }

    // cp.async mapping: rows ar + i*16 (i=0..7), cols ac4..ac4+3
    const int ar  = t >> 3;            // 0..15
    const int ac4 = (t & 7) << 2;      // 0..28

    float acc[4][8][4];
    #pragma unroll
    for (int mi = 0; mi < 4; mi++)
        #pragma unroll
        for (int nj = 0; nj < 8; nj++)
            #pragma unroll
            for (int r = 0; r < 4; r++) acc[mi][nj][r] = 0.f;

    // ---- Prologue: issue chunk 0 ----
    {
        const float* ap = A  + (size_t)(m0 + ar) * DM + ac4;
        const float* bp = Wt + (size_t)(n0 + ar) * DM + ac4;
        #pragma unroll
        for (int i = 0; i < 8; i++) {
            CP_ASYNC16(sbase + (GOFF_A(0) + (ar + i * 16) * LDA + ac4) * 4,
                       ap + (size_t)(i * 16) * DM);
            CP_ASYNC16(sbase + (GOFF_B(0) + (ar + i * 16) * LDA + ac4) * 4,
                       bp + (size_t)(i * 16) * DM);
        }
        CP_COMMIT();
    }

    #pragma unroll 1
    for (int kt = 0; kt < 32; kt++) {
        const int cur = kt & 1;
        const int nxt = cur ^ 1;

        CP_WAIT0();
        __syncthreads();

        if (kt + 1 < 32) {
            const int kf = (kt + 1) * 32;
            const float* ap = A  + (size_t)(m0 + ar) * DM + kf + ac4;
            const float* bp = Wt + (size_t)(n0 + ar) * DM + kf + ac4;
            #pragma unroll
            for (int i = 0; i < 8; i++) {
                CP_ASYNC16(sbase + (GOFF_A(nxt) + (ar + i * 16) * LDA + ac4) * 4,
                           ap + (size_t)(i * 16) * DM);
                CP_ASYNC16(sbase + (GOFF_B(nxt) + (ar + i * 16) * LDA + ac4) * 4,
                           bp + (size_t)(i * 16) * DM);
            }
            CP_COMMIT();
        }

        const uint32_t abase = sbase + GOFF_A(cur) * 4;
        const uint32_t bbase = sbase + GOFF_B(cur) * 4;

        #pragma unroll
        for (int ks = 0; ks < 4; ks++) {
            uint32_t af[4][4];
            #pragma unroll
            for (int mi = 0; mi < 4; mi++)
                LDSM4(af[mi][0], af[mi][1], af[mi][2], af[mi][3],
                      abase + (a_off[mi] + ks * 8) * 4);
            #pragma unroll
            for (int njp = 0; njp < 4; njp++) {
                uint32_t b0e, b0o, b1e, b1o;
                LDSM4(b0e, b0o, b1e, b1o, bbase + (b_off[njp] + ks * 8) * 4);
                #pragma unroll
                for (int mi = 0; mi < 4; mi++) {
                    MMA_TF32(acc[mi][2*njp][0],   acc[mi][2*njp][1],
                             acc[mi][2*njp][2],   acc[mi][2*njp][3],
                             af[mi][0], af[mi][1], af[mi][2], af[mi][3],
                             b0e, b1e);
                    MMA_TF32(acc[mi][2*njp+1][0], acc[mi][2*njp+1][1],
                             acc[mi][2*njp+1][2], acc[mi][2*njp+1][3],
                             af[mi][0], af[mi][1], af[mi][2], af[mi][3],
                             b0o, b1o);
                }
            }
        }
    }

    #pragma unroll
    for (int mi = 0; mi < 4; mi++) {
        const int row = m0 + wm + mi * 16 + g;
        #pragma unroll
        for (int nj = 0; nj < 8; nj++) {
            const int col = n0 + wn + nj * 8 + kq * 2;
            const float bx = bias[col], by = bias[col + 1];
            float2 v0 = make_float2(acc[mi][nj][0] + bx, acc[mi][nj][1] + by);
            float2 v1 = make_float2(acc[mi][nj][2] + bx, acc[mi][nj][3] + by);
            if (roundC) {
                v0.x = tf32rf(v0.x); v0.y = tf32rf(v0.y);
                v1.x = tf32rf(v1.x); v1.y = tf32rf(v1.y);
            }
            *(float2*)(C + (size_t)row * DM + col)       = v0;
            *(float2*)(C + (size_t)(row + 8) * DM + col) = v1;
        }
    }
}

// ---------------------------------------------------------------------------
// Tensor-core flash attention (tf32 mma.sync), cp.async double-buffered.
// R9 version verbatim (877us baseline).
// ---------------------------------------------------------------------------
#define KST 68
#define VST 72
#define OFF_KS(buf) ((buf) * 4352)
#define OFF_VS(buf) (8704 + (buf) * 4608)
#define OFF_MADD(buf) (17920 + (buf) * 64)
#define OFF_PS 18048
#define ATT_WORDS (OFF_PS + 128 * KST)        // 26752 words
#define ATT_SMEM  (ATT_WORDS * 4)             // 107008 B

__global__ __launch_bounds__(128, 2) void attn_mma_k(
    const float* __restrict__ q, const float* __restrict__ k,
    const float* __restrict__ v, const int* __restrict__ mask,
    float* __restrict__ o)
{
    extern __shared__ uint32_t smu[];
    uint32_t* Ps = smu + OFF_PS;
    const uint32_t sbase = smem_u32(smu);

    const int t    = threadIdx.x;
    const int lane = t & 31;
    const int wid  = t >> 5;           // 0..3
    const int g    = lane >> 2;
    const int kq   = lane & 3;
    const int bh   = blockIdx.x;
    const int b    = bh >> 4;
    const int h    = bh & 15;
    const int qt   = blockIdx.y;

    const int qbase = b * SEQ + qt * 128;
    const int kbase = b * SEQ;
    const int hcol  = h * HD;
    const int wr    = wid * 32;        // warp's first q row (32 rows)

    const int crow = t >> 4;           // 0..7
    const int cc4  = (t & 15) << 2;

    // ---- Stage Q tile (scaled by 1/8, tf32-rounded) into Ps ----
    #pragma unroll
    for (int it = 0; it < 16; it++) {
        int idx = it * 128 + t;
        int r = idx >> 4, c4 = (idx & 15) << 2;
        float4 qv = *(const float4*)(q + (size_t)(qbase + r) * DM + hcol + c4);
        uint32_t* p = &Ps[r * KST + c4];
        p[0] = tf32r(qv.x * 0.125f); p[1] = tf32r(qv.y * 0.125f);
        p[2] = tf32r(qv.z * 0.125f); p[3] = tf32r(qv.w * 0.125f);
    }

    // ---- Issue cp.async for chunk 0 ----
    {
        const float* kp = k + (size_t)(kbase + crow) * DM + hcol + cc4;
        const float* vp = v + (size_t)(kbase + crow) * DM + hcol + cc4;
        #pragma unroll
        for (int it = 0; it < 8; it++) {
            const int r = crow + it * 8;
            CP_ASYNC16(sbase + (OFF_KS(0) + r * KST + cc4) * 4, kp + (size_t)(it * 8) * DM);
            CP_ASYNC16(sbase + (OFF_VS(0) + r * VST + cc4) * 4, vp + (size_t)(it * 8) * DM);
        }
        CP_COMMIT();
    }
    if (t < 64) {
        ((float*)(smu + OFF_MADD(0)))[t] = mask[b * SEQ + t] ? 0.f : -1e9f;
    }
    int mreg = (t < 64) ? mask[b * SEQ + 64 + t] : 0;

    __syncthreads();

    // Q A-fragments for both 16-row tiles, register-resident
    uint32_t qf[2][8][4];
    #pragma unroll
    for (int mi = 0; mi < 2; mi++)
        #pragma unroll
        for (int ks = 0; ks < 8; ks++) {
            const int k0 = ks * 8 + kq;
            const int row = wr + mi * 16 + g;
            qf[mi][ks][0] = Ps[row * KST + k0];
            qf[mi][ks][1] = Ps[(row + 8) * KST + k0];
            qf[mi][ks][2] = Ps[row * KST + k0 + 4];
            qf[mi][ks][3] = Ps[(row + 8) * KST + k0 + 4];
        }

    float mx[2][2], lx[2][2];
    #pragma unroll
    for (int mi = 0; mi < 2; mi++) {
        mx[mi][0] = -1e30f; mx[mi][1] = -1e30f;
        lx[mi][0] = 0.f;    lx[mi][1] = 0.f;
    }
    float acc[2][8][4];
    #pragma unroll
    for (int mi = 0; mi < 2; mi++)
        #pragma unroll
        for (int nt = 0; nt < 8; nt++)
            #pragma unroll
            for (int j = 0; j < 4; j++) acc[mi][nt][j] = 0.f;

    #pragma unroll 1
    for (int kt = 0; kt < 32; kt++) {
        const int cur = kt & 1;
        const int nxt = cur ^ 1;

        CP_WAIT0();
        __syncthreads();

        if (kt + 1 < 32) {
            const size_t rb = (size_t)(kbase + (kt + 1) * 64 + crow) * DM + hcol + cc4;
            const float* kp = k + rb;
            const float* vp = v + rb;
            #pragma unroll
            for (int it = 0; it < 8; it++) {
                const int r = crow + it * 8;
                CP_ASYNC16(sbase + (OFF_KS(nxt) + r * KST + cc4) * 4, kp + (size_t)(it * 8) * DM);
                CP_ASYNC16(sbase + (OFF_VS(nxt) + r * VST + cc4) * 4, vp + (size_t)(it * 8) * DM);
            }
            CP_COMMIT();
            if (t < 64) {
                ((float*)(smu + OFF_MADD(nxt)))[t] = mreg ? 0.f : -1e9f;
                if (kt + 2 < 32) mreg = mask[b * SEQ + (kt + 2) * 64 + t];
            }
        }

        const uint32_t* Ks = smu + OFF_KS(cur);
        const uint32_t* Vs = smu + OFF_VS(cur);
        const float* madd  = (const float*)(smu + OFF_MADD(cur));

        // ---- S = (Q/8) K^T ----
        float s[2][8][4];
        #pragma unroll
        for (int mi = 0; mi < 2; mi++)
            #pragma unroll
            for (int nt = 0; nt < 8; nt++)
                #pragma unroll
                for (int j = 0; j < 4; j++) s[mi][nt][j] = 0.f;

        #pragma unroll
        for (int ks = 0; ks < 8; ks++) {
            const int k0 = ks * 8 + kq;
            #pragma unroll
            for (int nt = 0; nt < 8; nt++) {
                uint32_t bb0 = Ks[(nt * 8 + g) * KST + k0];
                uint32_t bb1 = Ks[(nt * 8 + g) * KST + k0 + 4];
                #pragma unroll
                for (int mi = 0; mi < 2; mi++)
                    MMA_TF32(s[mi][nt][0], s[mi][nt][1], s[mi][nt][2], s[mi][nt][3],
                             qf[mi][ks][0], qf[mi][ks][1],
                             qf[mi][ks][2], qf[mi][ks][3], bb0, bb1);
            }
        }

        // ---- Online softmax per mi (rows g, g+8; cols in-warp) ----
        #pragma unroll
        for (int mi = 0; mi < 2; mi++) {
            float rmax0 = -1e30f, rmax1 = -1e30f;
            #pragma unroll
            for (int nt = 0; nt < 8; nt++) {
                float2 md = *(float2*)&madd[nt * 8 + 2 * kq];
                s[mi][nt][0] += md.x; s[mi][nt][1] += md.y;
                s[mi][nt][2] += md.x; s[mi][nt][3] += md.y;
                rmax0 = fmaxf(rmax0, fmaxf(s[mi][nt][0], s[mi][nt][1]));
                rmax1 = fmaxf(rmax1, fmaxf(s[mi][nt][2], s[mi][nt][3]));
            }
            rmax0 = fmaxf(rmax0, __shfl_xor_sync(0xffffffffu, rmax0, 1));
            rmax0 = fmaxf(rmax0, __shfl_xor_sync(0xffffffffu, rmax0, 2));
            rmax1 = fmaxf(rmax1, __shfl_xor_sync(0xffffffffu, rmax1, 1));
            rmax1 = fmaxf(rmax1, __shfl_xor_sync(0xffffffffu, rmax1, 2));

            const float mn0 = fmaxf(mx[mi][0], rmax0);
            const float mn1 = fmaxf(mx[mi][1], rmax1);
            const float a0  = __expf(mx[mi][0] - mn0);
            const float a1  = __expf(mx[mi][1] - mn1);
            float sum0 = 0.f, sum1 = 0.f;

            const int row = wr + mi * 16 + g;
            #pragma unroll
            for (int nt = 0; nt < 8; nt++) {
                float p0 = __expf(s[mi][nt][0] - mn0);
                float p1 = __expf(s[mi][nt][1] - mn0);
                float p2 = __expf(s[mi][nt][2] - mn1);
                float p3 = __expf(s[mi][nt][3] - mn1);
                sum0 += p0 + p1;
                sum1 += p2 + p3;
                uint2 w0 = make_uint2(tf32r(p0), tf32r(p1));
                uint2 w1 = make_uint2(tf32r(p2), tf32r(p3));
                *(uint2*)&Ps[row * KST + nt * 8 + 2 * kq]       = w0;
                *(uint2*)&Ps[(row + 8) * KST + nt * 8 + 2 * kq] = w1;
            }
            sum0 += __shfl_xor_sync(0xffffffffu, sum0, 1);
            sum0 += __shfl_xor_sync(0xffffffffu, sum0, 2);
            sum1 += __shfl_xor_sync(0xffffffffu, sum1, 1);
            sum1 += __shfl_xor_sync(0xffffffffu, sum1, 2);

            lx[mi][0] = lx[mi][0] * a0 + sum0;  mx[mi][0] = mn0;
            lx[mi][1] = lx[mi][1] * a1 + sum1;  mx[mi][1] = mn1;
            #pragma unroll
            for (int nt = 0; nt < 8; nt++) {
                acc[mi][nt][0] *= a0; acc[mi][nt][1] *= a0;
                acc[mi][nt][2] *= a1; acc[mi][nt][3] *= a1;
            }
        }
        __syncwarp();   // P stores visible to own-warp LDS

        // ---- O += P V ----
        #pragma unroll
        for (int ks = 0; ks < 8; ks++) {
            const int k0 = ks * 8 + kq;
            uint32_t pa[2][4];
            #pragma unroll
            for (int mi = 0; mi < 2; mi++) {
                const int row = wr + mi * 16 + g;
                pa[mi][0] = Ps[row * KST + k0];
                pa[mi][1] = Ps[(row + 8) * KST + k0];
                pa[mi][2] = Ps[row * KST + k0 + 4];
                pa[mi][3] = Ps[(row + 8) * KST + k0 + 4];
            }
            #pragma unroll
            for (int nt = 0; nt < 8; nt++) {
                uint32_t bb0 = Vs[(k0) * VST + nt * 8 + g];
                uint32_t bb1 = Vs[(k0 + 4) * VST + nt * 8 + g];
                #pragma unroll
                for (int mi = 0; mi < 2; mi++)
                    MMA_TF32(acc[mi][nt][0], acc[mi][nt][1],
                             acc[mi][nt][2], acc[mi][nt][3],
                             pa[mi][0], pa[mi][1], pa[mi][2], pa[mi][3],
                             bb0, bb1);
            }
        }
    }

    // ---- Finalize (tf32-rounded for the output GEMM) ----
    #pragma unroll
    for (int mi = 0; mi < 2; mi++) {
        const float inv0 = (lx[mi][0] > 0.f) ? 1.f / lx[mi][0] : 0.f;
        const float inv1 = (lx[mi][1] > 0.f) ? 1.f / lx[mi][1] : 0.f;
        const int row0 = qbase + wr + mi * 16 + g;
        #pragma unroll
        for (int nt = 0; nt < 8; nt++) {
            const int col = hcol + nt * 8 + 2 * kq;
            float2 o0 = make_float2(tf32rf(acc[mi][nt][0] * inv0),
                                    tf32rf(acc[mi][nt][1] * inv0));
            float2 o1 = make_float2(tf32rf(acc[mi][nt][2] * inv1),
                                    tf32rf(acc[mi][nt][3] * inv1));
            *(float2*)(o + (size_t)row0 * DM + col)       = o0;
            *(float2*)(o + (size_t)(row0 + 8) * DM + col) = o1;
        }
    }
}

// ---------------------------------------------------------------------------
// Launch: weight transpose+round -> QKV GEMMs (fused, rounded out) ->
// attention (rounded out) -> output GEMM (raw fp32 out).
// ---------------------------------------------------------------------------
extern "C" void kernel_launch(void* const* d_in, const int* in_sizes, int n_in,
                              void* d_out, int out_size)
{
    const float* Q    = (const float*)d_in[0];
    const float* K    = (const float*)d_in[1];
    const float* V    = (const float*)d_in[2];
    const int*   mask = (const int*)  d_in[3];
    const float* Wq   = (const float*)d_in[4];
    const float* bq   = (const float*)d_in[5];
    const float* Wk   = (const float*)d_in[6];
    const float* bk   = (const float*)d_in[7];
    const float* Wv   = (const float*)d_in[8];
    const float* bv   = (const float*)d_in[9];
    const float* Wo   = (const float*)d_in[10];
    const float* bo   = (const float*)d_in[11];
    float* out = (float*)d_out;

    float *gq, *gk, *gv, *ga, *gwt;
    cudaGetSymbolAddress((void**)&gq,  g_q);
    cudaGetSymbolAddress((void**)&gk,  g_k);
    cudaGetSymbolAddress((void**)&gv,  g_v);
    cudaGetSymbolAddress((void**)&ga,  g_att);
    cudaGetSymbolAddress((void**)&gwt, g_wt);
    float* wtq = gwt + 0 * (size_t)DM * DM;
    float* wtk = gwt + 1 * (size_t)DM * DM;
    float* wtv = gwt + 2 * (size_t)DM * DM;
    float* wto = gwt + 3 * (size_t)DM * DM;

    cudaFuncSetAttribute(gemm_mma_k, cudaFuncAttributeMaxDynamicSharedMemorySize,
                         GEMM_SMEM);
    cudaFuncSetAttribute(attn_mma_k, cudaFuncAttributeMaxDynamicSharedMemorySize,
                         ATT_SMEM);

    dim3 tgrid(DM / 32, DM / 32, 4);
    dim3 tblk(32, 8);
    round_wt_k<<<tgrid, tblk>>>(Wq, Wk, Wv, Wo, gwt);

    dim3 qkv_grid(DM / 128, MROWS / 128, 3);  // (8, 64, 3)
    dim3 out_grid(DM / 128, MROWS / 128, 1);  // (8, 64, 1)
    dim3 attn_grid(NB * NH, SEQ / 128);       // (64, 16)

    gemm_mma_k<<<qkv_grid, 128, GEMM_SMEM>>>(Q, K, V, wtq, wtk, wtv,
                                             bq, bk, bv, gq, gk, gv, 1);
    attn_mma_k<<<attn_grid, 128, ATT_SMEM>>>(gq, gk, gv, mask, ga);
    gemm_mma_k<<<out_grid, 128, GEMM_SMEM>>>(ga, ga, ga, wto, wto, wto,
                                             bo, bo, bo, out, out, out, 0);
}

// round 12
// speedup vs baseline: 1.2586x; 1.2458x over previous
#include <cuda_runtime.h>
#include <cuda_fp16.h>
#include <math.h>
#include <stdint.h>

// Problem constants
#define NB   4
#define SEQ  2048
#define DM   1024
#define NH   16
#define HD   64
#define MROWS (NB*SEQ)          // 8192

// Scratch (device globals — no allocation allowed)
__device__ __half g_in16[3][MROWS*DM];   // fp16(Q,K,V inputs)
__device__ __half g_wt16[4][DM*DM];      // fp16 transposed weights [n][k]
__device__ float  g_q  [MROWS*DM];       // tf32-exact fp32 (attention operands)
__device__ float  g_k  [MROWS*DM];
__device__ float  g_v  [MROWS*DM];
__device__ __half g_att16[MROWS*DM];     // fp16 attention output

__device__ __forceinline__ uint32_t tf32r(float x) {
    uint32_t u;
    asm("cvt.rna.tf32.f32 %0, %1;" : "=r"(u) : "f"(x));
    return u;
}
__device__ __forceinline__ float tf32rf(float x) {
    return __uint_as_float(tf32r(x));
}

__device__ __forceinline__ uint32_t smem_u32(const void* p) {
    uint32_t a;
    asm("{ .reg .u64 t; cvta.to.shared.u64 t, %1; cvt.u32.u64 %0, t; }"
        : "=r"(a) : "l"(p));
    return a;
}

#define CP_ASYNC16(dst, src) \
    asm volatile("cp.async.cg.shared.global [%0], [%1], 16;" \
                 :: "r"(dst), "l"(src) : "memory")
#define CP_COMMIT() asm volatile("cp.async.commit_group;" ::: "memory")
#define CP_WAIT0()  asm volatile("cp.async.wait_group 0;" ::: "memory")

#define MMA_TF32(c0, c1, c2, c3, a0, a1, a2, a3, b0, b1) \
    asm volatile("mma.sync.aligned.m16n8k8.row.col.f32.tf32.tf32.f32 " \
        "{%0,%1,%2,%3}, {%4,%5,%6,%7}, {%8,%9}, {%0,%1,%2,%3};" \
        : "+f"(c0), "+f"(c1), "+f"(c2), "+f"(c3) \
        : "r"(a0), "r"(a1), "r"(a2), "r"(a3), "r"(b0), "r"(b1))

#define MMA_F16(c0, c1, c2, c3, a0, a1, a2, a3, b0, b1) \
    asm volatile("mma.sync.aligned.m16n8k16.row.col.f32.f16.f16.f32 " \
        "{%0,%1,%2,%3}, {%4,%5,%6,%7}, {%8,%9}, {%0,%1,%2,%3};" \
        : "+f"(c0), "+f"(c1), "+f"(c2), "+f"(c3) \
        : "r"(a0), "r"(a1), "r"(a2), "r"(a3), "r"(b0), "r"(b1))

// ---------------------------------------------------------------------------
// Input convert: g_in16[z] = fp16_rn(input_z), z in {Q,K,V}. float4-wide.
// ---------------------------------------------------------------------------
__global__ __launch_bounds__(256) void cvt_in_k(
    const float* __restrict__ Q, const float* __restrict__ K,
    const float* __restrict__ V, __half* __restrict__ D)
{
    const int n4 = MROWS * DM / 4;
    for (int i = blockIdx.x * blockDim.x + threadIdx.x; i < 3 * n4;
         i += gridDim.x * blockDim.x) {
        const int w = i / n4, j = i - w * n4;
        const float* S = (w == 0) ? Q : (w == 1) ? K : V;
        float4 v = *(const float4*)(S + 4 * (size_t)j);
        __half2* d = (__half2*)(D + (size_t)w * MROWS * DM + 4 * (size_t)j);
        d[0] = __floats2half2_rn(v.x, v.y);
        d[1] = __floats2half2_rn(v.z, v.w);
    }
}

// ---------------------------------------------------------------------------
// Weight transpose + fp16 round: D[z][n*DM+k] = fp16_rn(W_z[k*DM+n]).
// ---------------------------------------------------------------------------
__global__ __launch_bounds__(256) void round_wt16_k(
    const float* __restrict__ W0, const float* __restrict__ W1,
    const float* __restrict__ W2, const float* __restrict__ W3,
    __half* __restrict__ D)
{
    __shared__ float tile[32][33];
    const int z = blockIdx.z;
    const float* W = (z == 0) ? W0 : (z == 1) ? W1 : (z == 2) ? W2 : W3;
    __half* Dw = D + (size_t)z * DM * DM;

    const int tx = threadIdx.x, ty = threadIdx.y;
    const int x = blockIdx.x * 32 + tx;          // n
    #pragma unroll
    for (int j = ty; j < 32; j += 8)
        tile[j][tx] = W[(size_t)(blockIdx.y * 32 + j) * DM + x];
    __syncthreads();
    const int x2 = blockIdx.y * 32 + tx;         // k
    #pragma unroll
    for (int j = ty; j < 32; j += 8)
        Dw[(size_t)(blockIdx.x * 32 + j) * DM + x2] = __float2half_rn(tile[tx][j]);
}

// ---------------------------------------------------------------------------
// fp16 tensor-core GEMM (mma.m16n8k16), cp.async double-buffered.
//   C[M,1024](fp32) = A16[M,1024] @ W16 + bias, weights TRANSPOSED [n][k].
// 128 threads = 4 warps (2m x 2n), warp 64x64, CTA 128x128, BK=32 halves.
// Per chunk per warp: 64 LDS : 64 MMA (each 4096 FLOP).
//   As[2][128][40h] : A chunk [m][k]   (A-frag word bank 20g+kq, CF)
//   Bs[2][128][40h] : Wt chunk [n][k]  (B-frag word bank 20g+kq, CF)
// roundC: 1 -> store tf32-rounded fp32 (feeds attention); 0 -> raw fp32.
// ---------------------------------------------------------------------------
#define LDHW 20                       // words per row (40 halves)
#define SSTG 20480                    // bytes per stage (A 10240 + B 10240)
#define GOFF_A(s) ((s) * SSTG)
#define GOFF_B(s) ((s) * SSTG + 10240)
#define GEMM_SMEM (2 * SSTG)          // 40960 B

__global__ __launch_bounds__(128, 2) void gemm_f16_k(
    const __half* __restrict__ A0, const __half* __restrict__ A1,
    const __half* __restrict__ A2,
    const __half* __restrict__ W0, const __half* __restrict__ W1,
    const __half* __restrict__ W2,
    const float* __restrict__ b0_, const float* __restrict__ b1_,
    const float* __restrict__ b2_,
    float* __restrict__ C0, float* __restrict__ C1, float* __restrict__ C2,
    int roundC)
{
    extern __shared__ uint32_t smg[];
    const uint32_t sbase = smem_u32(smg);

    const int z = blockIdx.z;
    const __half* A    = (z == 0) ? A0 : (z == 1) ? A1 : A2;
    const __half* Wt   = (z == 0) ? W0 : (z == 1) ? W1 : W2;
    const float*  bias = (z == 0) ? b0_ : (z == 1) ? b1_ : b2_;
    float*        C    = (z == 0) ? C0 : (z == 1) ? C1 : C2;

    const int t    = threadIdx.x;
    const int lane = t & 31;
    const int wid  = t >> 5;           // 0..3
    const int m0   = blockIdx.y * 128;
    const int n0   = blockIdx.x * 128;
    const int wm   = (wid & 1) * 64;
    const int wn   = (wid >> 1) * 64;
    const int g    = lane >> 2;
    const int kq   = lane & 3;

    // cp.async mapping: rows ar + i*32 (i=0..3), 16B slice acb of the 64B row
    const int ar  = t >> 2;            // 0..31
    const int acb = (t & 3) << 4;      // byte 0,16,32,48
    const int ach = acb >> 1;          // half offset 0,8,16,24

    float acc[4][8][4];
    #pragma unroll
    for (int mi = 0; mi < 4; mi++)
        #pragma unroll
        for (int nj = 0; nj < 8; nj++)
            #pragma unroll
            for (int r = 0; r < 4; r++) acc[mi][nj][r] = 0.f;

    // ---- Prologue: chunk 0 ----
    #pragma unroll
    for (int i = 0; i < 4; i++) {
        const int row = ar + i * 32;
        CP_ASYNC16(sbase + GOFF_A(0) + row * 80 + acb,
                   A + (size_t)(m0 + row) * DM + ach);
        CP_ASYNC16(sbase + GOFF_B(0) + row * 80 + acb,
                   Wt + (size_t)(n0 + row) * DM + ach);
    }
    CP_COMMIT();

    #pragma unroll 1
    for (int kt = 0; kt < 32; kt++) {
        const int cur = kt & 1;
        const int nxt = cur ^ 1;

        CP_WAIT0();
        __syncthreads();

        if (kt + 1 < 32) {
            const int kf = (kt + 1) * 32;     // half offset
            #pragma unroll
            for (int i = 0; i < 4; i++) {
                const int row = ar + i * 32;
                CP_ASYNC16(sbase + GOFF_A(nxt) + row * 80 + acb,
                           A + (size_t)(m0 + row) * DM + kf + ach);
                CP_ASYNC16(sbase + GOFF_B(nxt) + row * 80 + acb,
                           Wt + (size_t)(n0 + row) * DM + kf + ach);
            }
            CP_COMMIT();
        }

        const uint32_t* As = smg + (GOFF_A(cur) >> 2);
        const uint32_t* Bs = smg + (GOFF_B(cur) >> 2);

        #pragma unroll
        for (int ks = 0; ks < 2; ks++) {      // two k16 steps per 32-half chunk
            const int kw = ks * 8 + kq;       // word offset within row
            uint32_t af[4][4];
            #pragma unroll
            for (int mi = 0; mi < 4; mi++) {
                const int w0 = (wm + mi * 16 + g) * LDHW + kw;
                af[mi][0] = As[w0];
                af[mi][1] = As[w0 + 8 * LDHW];
                af[mi][2] = As[w0 + 4];
                af[mi][3] = As[w0 + 8 * LDHW + 4];
            }
            #pragma unroll
            for (int nj = 0; nj < 8; nj++) {
                const int wb = (wn + nj * 8 + g) * LDHW + kw;
                uint32_t bb0 = Bs[wb];
                uint32_t bb1 = Bs[wb + 4];
                #pragma unroll
                for (int mi = 0; mi < 4; mi++)
                    MMA_F16(acc[mi][nj][0], acc[mi][nj][1],
                            acc[mi][nj][2], acc[mi][nj][3],
                            af[mi][0], af[mi][1], af[mi][2], af[mi][3],
                            bb0, bb1);
            }
        }
    }

    #pragma unroll
    for (int mi = 0; mi < 4; mi++) {
        const int row = m0 + wm + mi * 16 + g;
        #pragma unroll
        for (int nj = 0; nj < 8; nj++) {
            const int col = n0 + wn + nj * 8 + kq * 2;
            const float bx = bias[col], by = bias[col + 1];
            float2 v0 = make_float2(acc[mi][nj][0] + bx, acc[mi][nj][1] + by);
            float2 v1 = make_float2(acc[mi][nj][2] + bx, acc[mi][nj][3] + by);
            if (roundC) {
                v0.x = tf32rf(v0.x); v0.y = tf32rf(v0.y);
                v1.x = tf32rf(v1.x); v1.y = tf32rf(v1.y);
            }
            *(float2*)(C + (size_t)row * DM + col)       = v0;
            *(float2*)(C + (size_t)(row + 8) * DM + col) = v1;
        }
    }
}

// ---------------------------------------------------------------------------
// Tensor-core flash attention (tf32 mma.sync), cp.async double-buffered.
// R9 version; epilogue now writes fp16 (for the fp16 output GEMM).
// ---------------------------------------------------------------------------
#define KST 68
#define VST 72
#define OFF_KS(buf) ((buf) * 4352)
#define OFF_VS(buf) (8704 + (buf) * 4608)
#define OFF_MADD(buf) (17920 + (buf) * 64)
#define OFF_PS 18048
#define ATT_WORDS (OFF_PS + 128 * KST)        // 26752 words
#define ATT_SMEM  (ATT_WORDS * 4)             // 107008 B

__global__ __launch_bounds__(128, 2) void attn_mma_k(
    const float* __restrict__ q, const float* __restrict__ k,
    const float* __restrict__ v, const int* __restrict__ mask,
    __half* __restrict__ o16)
{
    extern __shared__ uint32_t smu[];
    uint32_t* Ps = smu + OFF_PS;
    const uint32_t sbase = smem_u32(smu);

    const int t    = threadIdx.x;
    const int lane = t & 31;
    const int wid  = t >> 5;           // 0..3
    const int g    = lane >> 2;
    const int kq   = lane & 3;
    const int bh   = blockIdx.x;
    const int b    = bh >> 4;
    const int h    = bh & 15;
    const int qt   = blockIdx.y;

    const int qbase = b * SEQ + qt * 128;
    const int kbase = b * SEQ;
    const int hcol  = h * HD;
    const int wr    = wid * 32;

    const int crow = t >> 4;
    const int cc4  = (t & 15) << 2;

    #pragma unroll
    for (int it = 0; it < 16; it++) {
        int idx = it * 128 + t;
        int r = idx >> 4, c4 = (idx & 15) << 2;
        float4 qv = *(const float4*)(q + (size_t)(qbase + r) * DM + hcol + c4);
        uint32_t* p = &Ps[r * KST + c4];
        p[0] = tf32r(qv.x * 0.125f); p[1] = tf32r(qv.y * 0.125f);
        p[2] = tf32r(qv.z * 0.125f); p[3] = tf32r(qv.w * 0.125f);
    }

    {
        const float* kp = k + (size_t)(kbase + crow) * DM + hcol + cc4;
        const float* vp = v + (size_t)(kbase + crow) * DM + hcol + cc4;
        #pragma unroll
        for (int it = 0; it < 8; it++) {
            const int r = crow + it * 8;
            CP_ASYNC16(sbase + (OFF_KS(0) + r * KST + cc4) * 4, kp + (size_t)(it * 8) * DM);
            CP_ASYNC16(sbase + (OFF_VS(0) + r * VST + cc4) * 4, vp + (size_t)(it * 8) * DM);
        }
        CP_COMMIT();
    }
    if (t < 64) {
        ((float*)(smu + OFF_MADD(0)))[t] = mask[b * SEQ + t] ? 0.f : -1e9f;
    }
    int mreg = (t < 64) ? mask[b * SEQ + 64 + t] : 0;

    __syncthreads();

    uint32_t qf[2][8][4];
    #pragma unroll
    for (int mi = 0; mi < 2; mi++)
        #pragma unroll
        for (int ks = 0; ks < 8; ks++) {
            const int k0 = ks * 8 + kq;
            const int row = wr + mi * 16 + g;
            qf[mi][ks][0] = Ps[row * KST + k0];
            qf[mi][ks][1] = Ps[(row + 8) * KST + k0];
            qf[mi][ks][2] = Ps[row * KST + k0 + 4];
            qf[mi][ks][3] = Ps[(row + 8) * KST + k0 + 4];
        }

    float mx[2][2], lx[2][2];
    #pragma unroll
    for (int mi = 0; mi < 2; mi++) {
        mx[mi][0] = -1e30f; mx[mi][1] = -1e30f;
        lx[mi][0] = 0.f;    lx[mi][1] = 0.f;
    }
    float acc[2][8][4];
    #pragma unroll
    for (int mi = 0; mi < 2; mi++)
        #pragma unroll
        for (int nt = 0; nt < 8; nt++)
            #pragma unroll
            for (int j = 0; j < 4; j++) acc[mi][nt][j] = 0.f;

    #pragma unroll 1
    for (int kt = 0; kt < 32; kt++) {
        const int cur = kt & 1;
        const int nxt = cur ^ 1;

        CP_WAIT0();
        __syncthreads();

        if (kt + 1 < 32) {
            const size_t rb = (size_t)(kbase + (kt + 1) * 64 + crow) * DM + hcol + cc4;
            const float* kp = k + rb;
            const float* vp = v + rb;
            #pragma unroll
            for (int it = 0; it < 8; it++) {
                const int r = crow + it * 8;
                CP_ASYNC16(sbase + (OFF_KS(nxt) + r * KST + cc4) * 4, kp + (size_t)(it * 8) * DM);
                CP_ASYNC16(sbase + (OFF_VS(nxt) + r * VST + cc4) * 4, vp + (size_t)(it * 8) * DM);
            }
            CP_COMMIT();
            if (t < 64) {
                ((float*)(smu + OFF_MADD(nxt)))[t] = mreg ? 0.f : -1e9f;
                if (kt + 2 < 32) mreg = mask[b * SEQ + (kt + 2) * 64 + t];
            }
        }

        const uint32_t* Ks = smu + OFF_KS(cur);
        const uint32_t* Vs = smu + OFF_VS(cur);
        const float* madd  = (const float*)(smu + OFF_MADD(cur));

        float s[2][8][4];
        #pragma unroll
        for (int mi = 0; mi < 2; mi++)
            #pragma unroll
            for (int nt = 0; nt < 8; nt++)
                #pragma unroll
                for (int j = 0; j < 4; j++) s[mi][nt][j] = 0.f;

        #pragma unroll
        for (int ks = 0; ks < 8; ks++) {
            const int k0 = ks * 8 + kq;
            #pragma unroll
            for (int nt = 0; nt < 8; nt++) {
                uint32_t bb0 = Ks[(nt * 8 + g) * KST + k0];
                uint32_t bb1 = Ks[(nt * 8 + g) * KST + k0 + 4];
                #pragma unroll
                for (int mi = 0; mi < 2; mi++)
                    MMA_TF32(s[mi][nt][0], s[mi][nt][1], s[mi][nt][2], s[mi][nt][3],
                             qf[mi][ks][0], qf[mi][ks][1],
                             qf[mi][ks][2], qf[mi][ks][3], bb0, bb1);
            }
        }

        #pragma unroll
        for (int mi = 0; mi < 2; mi++) {
            float rmax0 = -1e30f, rmax1 = -1e30f;
            #pragma unroll
            for (int nt = 0; nt < 8; nt++) {
                float2 md = *(float2*)&madd[nt * 8 + 2 * kq];
                s[mi][nt][0] += md.x; s[mi][nt][1] += md.y;
                s[mi][nt][2] += md.x; s[mi][nt][3] += md.y;
                rmax0 = fmaxf(rmax0, fmaxf(s[mi][nt][0], s[mi][nt][1]));
                rmax1 = fmaxf(rmax1, fmaxf(s[mi][nt][2], s[mi][nt][3]));
            }
            rmax0 = fmaxf(rmax0, __shfl_xor_sync(0xffffffffu, rmax0, 1));
            rmax0 = fmaxf(rmax0, __shfl_xor_sync(0xffffffffu, rmax0, 2));
            rmax1 = fmaxf(rmax1, __shfl_xor_sync(0xffffffffu, rmax1, 1));
            rmax1 = fmaxf(rmax1, __shfl_xor_sync(0xffffffffu, rmax1, 2));

            const float mn0 = fmaxf(mx[mi][0], rmax0);
            const float mn1 = fmaxf(mx[mi][1], rmax1);
            const float a0  = __expf(mx[mi][0] - mn0);
            const float a1  = __expf(mx[mi][1] - mn1);
            float sum0 = 0.f, sum1 = 0.f;

            const int row = wr + mi * 16 + g;
            #pragma unroll
            for (int nt = 0; nt < 8; nt++) {
                float p0 = __expf(s[mi][nt][0] - mn0);
                float p1 = __expf(s[mi][nt][1] - mn0);
                float p2 = __expf(s[mi][nt][2] - mn1);
                float p3 = __expf(s[mi][nt][3] - mn1);
                sum0 += p0 + p1;
                sum1 += p2 + p3;
                uint2 w0 = make_uint2(tf32r(p0), tf32r(p1));
                uint2 w1 = make_uint2(tf32r(p2), tf32r(p3));
                *(uint2*)&Ps[row * KST + nt * 8 + 2 * kq]       = w0;
                *(uint2*)&Ps[(row + 8) * KST + nt * 8 + 2 * kq] = w1;
            }
            sum0 += __shfl_xor_sync(0xffffffffu, sum0, 1);
            sum0 += __shfl_xor_sync(0xffffffffu, sum0, 2);
            sum1 += __shfl_xor_sync(0xffffffffu, sum1, 1);
            sum1 += __shfl_xor_sync(0xffffffffu, sum1, 2);

            lx[mi][0] = lx[mi][0] * a0 + sum0;  mx[mi][0] = mn0;
            lx[mi][1] = lx[mi][1] * a1 + sum1;  mx[mi][1] = mn1;
            #pragma unroll
            for (int nt = 0; nt < 8; nt++) {
                acc[mi][nt][0] *= a0; acc[mi][nt][1] *= a0;
                acc[mi][nt][2] *= a1; acc[mi][nt][3] *= a1;
            }
        }
        __syncwarp();

        #pragma unroll
        for (int ks = 0; ks < 8; ks++) {
            const int k0 = ks * 8 + kq;
            uint32_t pa[2][4];
            #pragma unroll
            for (int mi = 0; mi < 2; mi++) {
                const int row = wr + mi * 16 + g;
                pa[mi][0] = Ps[row * KST + k0];
                pa[mi][1] = Ps[(row + 8) * KST + k0];
                pa[mi][2] = Ps[row * KST + k0 + 4];
                pa[mi][3] = Ps[(row + 8) * KST + k0 + 4];
            }
            #pragma unroll
            for (int nt = 0; nt < 8; nt++) {
                uint32_t bb0 = Vs[(k0) * VST + nt * 8 + g];
                uint32_t bb1 = Vs[(k0 + 4) * VST + nt * 8 + g];
                #pragma unroll
                for (int mi = 0; mi < 2; mi++)
                    MMA_TF32(acc[mi][nt][0], acc[mi][nt][1],
                             acc[mi][nt][2], acc[mi][nt][3],
                             pa[mi][0], pa[mi][1], pa[mi][2], pa[mi][3],
                             bb0, bb1);
            }
        }
    }

    // ---- Finalize: fp16 output for the fp16 output GEMM ----
    #pragma unroll
    for (int mi = 0; mi < 2; mi++) {
        const float inv0 = (lx[mi][0] > 0.f) ? 1.f / lx[mi][0] : 0.f;
        const float inv1 = (lx[mi][1] > 0.f) ? 1.f / lx[mi][1] : 0.f;
        const int row0 = qbase + wr + mi * 16 + g;
        #pragma unroll
        for (int nt = 0; nt < 8; nt++) {
            const int col = hcol + nt * 8 + 2 * kq;
            *(__half2*)(o16 + (size_t)row0 * DM + col) =
                __floats2half2_rn(acc[mi][nt][0] * inv0, acc[mi][nt][1] * inv0);
            *(__half2*)(o16 + (size_t)(row0 + 8) * DM + col) =
                __floats2half2_rn(acc[mi][nt][2] * inv1, acc[mi][nt][3] * inv1);
        }
    }
}

// ---------------------------------------------------------------------------
// Launch: convert inputs + weights -> fp16 QKV GEMMs (tf32-rounded fp32 out)
// -> tf32 attention (fp16 out) -> fp16 output GEMM (fp32 out).
// ---------------------------------------------------------------------------
extern "C" void kernel_launch(void* const* d_in, const int* in_sizes, int n_in,
                              void* d_out, int out_size)
{
    const float* Q    = (const float*)d_in[0];
    const float* K    = (const float*)d_in[1];
    const float* V    = (const float*)d_in[2];
    const int*   mask = (const int*)  d_in[3];
    const float* Wq   = (const float*)d_in[4];
    const float* bq   = (const float*)d_in[5];
    const float* Wk   = (const float*)d_in[6];
    const float* bk   = (const float*)d_in[7];
    const float* Wv   = (const float*)d_in[8];
    const float* bv   = (const float*)d_in[9];
    const float* Wo   = (const float*)d_in[10];
    const float* bo   = (const float*)d_in[11];
    float* out = (float*)d_out;

    float *gq, *gk, *gv;
    __half *gin, *gwt, *gatt;
    cudaGetSymbolAddress((void**)&gq,   g_q);
    cudaGetSymbolAddress((void**)&gk,   g_k);
    cudaGetSymbolAddress((void**)&gv,   g_v);
    cudaGetSymbolAddress((void**)&gin,  g_in16);
    cudaGetSymbolAddress((void**)&gwt,  g_wt16);
    cudaGetSymbolAddress((void**)&gatt, g_att16);

    __half* inq = gin + 0 * (size_t)MROWS * DM;
    __half* ink = gin + 1 * (size_t)MROWS * DM;
    __half* inv = gin + 2 * (size_t)MROWS * DM;
    __half* wtq = gwt + 0 * (size_t)DM * DM;
    __half* wtk = gwt + 1 * (size_t)DM * DM;
    __half* wtv = gwt + 2 * (size_t)DM * DM;
    __half* wto = gwt + 3 * (size_t)DM * DM;

    cudaFuncSetAttribute(gemm_f16_k, cudaFuncAttributeMaxDynamicSharedMemorySize,
                         GEMM_SMEM);
    cudaFuncSetAttribute(attn_mma_k, cudaFuncAttributeMaxDynamicSharedMemorySize,
                         ATT_SMEM);

    cvt_in_k<<<1184, 256>>>(Q, K, V, gin);
    dim3 tgrid(DM / 32, DM / 32, 4);
    dim3 tblk(32, 8);
    round_wt16_k<<<tgrid, tblk>>>(Wq, Wk, Wv, Wo, gwt);

    dim3 qkv_grid(DM / 128, MROWS / 128, 3);  // (8, 64, 3)
    dim3 out_grid(DM / 128, MROWS / 128, 1);  // (8, 64, 1)
    dim3 attn_grid(NB * NH, SEQ / 128);       // (64, 16)

    gemm_f16_k<<<qkv_grid, 128, GEMM_SMEM>>>(inq, ink, inv, wtq, wtk, wtv,
                                             bq, bk, bv, gq, gk, gv, 1);
    attn_mma_k<<<attn_grid, 128, ATT_SMEM>>>(gq, gk, gv, mask, gatt);
    gemm_f16_k<<<out_grid, 128, GEMM_SMEM>>>(gatt, gatt, gatt, wto, wto, wto,
                                             bo, bo, bo, out, out, out, 0);
}

// round 13
// speedup vs baseline: 1.7498x; 1.3903x over previous
#include <cuda_runtime.h>
#include <cuda_fp16.h>
#include <math.h>
#include <stdint.h>

// Problem constants
#define NB   4
#define SEQ  2048
#define DM   1024
#define NH   16
#define HD   64
#define MROWS (NB*SEQ)          // 8192

// Scratch (device globals — no allocation allowed)
__device__ __half g_in16[3][MROWS*DM];   // fp16(Q,K,V inputs)
__device__ __half g_wt16[4][DM*DM];      // fp16 transposed weights [n][k]
__device__ __half g_q16 [MROWS*DM];      // fp16 q (pre-scaled by 1/8)
__device__ __half g_k16 [MROWS*DM];      // fp16 k, natural [token][d]
__device__ __half g_vt16[MROWS*DM];      // fp16 v TRANSPOSED [d][token]
__device__ __half g_att16[MROWS*DM];     // fp16 attention output

__device__ __forceinline__ uint32_t smem_u32(const void* p) {
    uint32_t a;
    asm("{ .reg .u64 t; cvta.to.shared.u64 t, %1; cvt.u32.u64 %0, t; }"
        : "=r"(a) : "l"(p));
    return a;
}
__device__ __forceinline__ uint32_t h2u(__half2 h) {
    return *(uint32_t*)&h;
}

#define CP_ASYNC16(dst, src) \
    asm volatile("cp.async.cg.shared.global [%0], [%1], 16;" \
                 :: "r"(dst), "l"(src) : "memory")
#define CP_COMMIT() asm volatile("cp.async.commit_group;" ::: "memory")
#define CP_WAIT0()  asm volatile("cp.async.wait_group 0;" ::: "memory")

#define MMA_F16(c0, c1, c2, c3, a0, a1, a2, a3, b0, b1) \
    asm volatile("mma.sync.aligned.m16n8k16.row.col.f32.f16.f16.f32 " \
        "{%0,%1,%2,%3}, {%4,%5,%6,%7}, {%8,%9}, {%0,%1,%2,%3};" \
        : "+f"(c0), "+f"(c1), "+f"(c2), "+f"(c3) \
        : "r"(a0), "r"(a1), "r"(a2), "r"(a3), "r"(b0), "r"(b1))

// ---------------------------------------------------------------------------
// Input convert: g_in16[z] = fp16_rn(input_z), z in {Q,K,V}.
// ---------------------------------------------------------------------------
__global__ __launch_bounds__(256) void cvt_in_k(
    const float* __restrict__ Q, const float* __restrict__ K,
    const float* __restrict__ V, __half* __restrict__ D)
{
    const int n4 = MROWS * DM / 4;
    for (int i = blockIdx.x * blockDim.x + threadIdx.x; i < 3 * n4;
         i += gridDim.x * blockDim.x) {
        const int w = i / n4, j = i - w * n4;
        const float* S = (w == 0) ? Q : (w == 1) ? K : V;
        float4 v = *(const float4*)(S + 4 * (size_t)j);
        __half2* d = (__half2*)(D + (size_t)w * MROWS * DM + 4 * (size_t)j);
        d[0] = __floats2half2_rn(v.x, v.y);
        d[1] = __floats2half2_rn(v.z, v.w);
    }
}

// ---------------------------------------------------------------------------
// Weight transpose + fp16 round: D[z][n*DM+k] = fp16_rn(W_z[k*DM+n]).
// ---------------------------------------------------------------------------
__global__ __launch_bounds__(256) void round_wt16_k(
    const float* __restrict__ W0, const float* __restrict__ W1,
    const float* __restrict__ W2, const float* __restrict__ W3,
    __half* __restrict__ D)
{
    __shared__ float tile[32][33];
    const int z = blockIdx.z;
    const float* W = (z == 0) ? W0 : (z == 1) ? W1 : (z == 2) ? W2 : W3;
    __half* Dw = D + (size_t)z * DM * DM;

    const int tx = threadIdx.x, ty = threadIdx.y;
    const int x = blockIdx.x * 32 + tx;
    #pragma unroll
    for (int j = ty; j < 32; j += 8)
        tile[j][tx] = W[(size_t)(blockIdx.y * 32 + j) * DM + x];
    __syncthreads();
    const int x2 = blockIdx.y * 32 + tx;
    #pragma unroll
    for (int j = ty; j < 32; j += 8)
        Dw[(size_t)(blockIdx.x * 32 + j) * DM + x2] = __float2half_rn(tile[tx][j]);
}

// ---------------------------------------------------------------------------
// fp16 tensor-core GEMM (mma.m16n8k16), cp.async double-buffered.
// qkv=1: z=0 -> fp16 out scaled 1/8 (Q); z=1 -> fp16 out (K);
//        z=2 -> fp16 out TRANSPOSED [d][token] (V).
// qkv=0: fp32 out (final output GEMM).
// ---------------------------------------------------------------------------
#define LDHW 20                       // words per row (40 halves)
#define SSTG 20480                    // bytes per stage (A 10240 + B 10240)
#define GOFF_A(s) ((s) * SSTG)
#define GOFF_B(s) ((s) * SSTG + 10240)
#define GEMM_SMEM (2 * SSTG)          // 40960 B

__global__ __launch_bounds__(128, 2) void gemm_f16_k(
    const __half* __restrict__ A0, const __half* __restrict__ A1,
    const __half* __restrict__ A2,
    const __half* __restrict__ W0, const __half* __restrict__ W1,
    const __half* __restrict__ W2,
    const float* __restrict__ b0_, const float* __restrict__ b1_,
    const float* __restrict__ b2_,
    float* __restrict__ C0,
    __half* __restrict__ H0, __half* __restrict__ H1, __half* __restrict__ H2,
    int qkv)
{
    extern __shared__ uint32_t smg[];
    const uint32_t sbase = smem_u32(smg);

    const int z = blockIdx.z;
    const __half* A    = (z == 0) ? A0 : (z == 1) ? A1 : A2;
    const __half* Wt   = (z == 0) ? W0 : (z == 1) ? W1 : W2;
    const float*  bias = (z == 0) ? b0_ : (z == 1) ? b1_ : b2_;
    __half*       H    = (z == 0) ? H0 : (z == 1) ? H1 : H2;

    const int t    = threadIdx.x;
    const int lane = t & 31;
    const int wid  = t >> 5;
    const int m0   = blockIdx.y * 128;
    const int n0   = blockIdx.x * 128;
    const int wm   = (wid & 1) * 64;
    const int wn   = (wid >> 1) * 64;
    const int g    = lane >> 2;
    const int kq   = lane & 3;

    const int ar  = t >> 2;            // 0..31
    const int acb = (t & 3) << 4;      // byte 0,16,32,48
    const int ach = acb >> 1;          // half offset

    float acc[4][8][4];
    #pragma unroll
    for (int mi = 0; mi < 4; mi++)
        #pragma unroll
        for (int nj = 0; nj < 8; nj++)
            #pragma unroll
            for (int r = 0; r < 4; r++) acc[mi][nj][r] = 0.f;

    #pragma unroll
    for (int i = 0; i < 4; i++) {
        const int row = ar + i * 32;
        CP_ASYNC16(sbase + GOFF_A(0) + row * 80 + acb,
                   A + (size_t)(m0 + row) * DM + ach);
        CP_ASYNC16(sbase + GOFF_B(0) + row * 80 + acb,
                   Wt + (size_t)(n0 + row) * DM + ach);
    }
    CP_COMMIT();

    #pragma unroll 1
    for (int kt = 0; kt < 32; kt++) {
        const int cur = kt & 1;
        const int nxt = cur ^ 1;

        CP_WAIT0();
        __syncthreads();

        if (kt + 1 < 32) {
            const int kf = (kt + 1) * 32;
            #pragma unroll
            for (int i = 0; i < 4; i++) {
                const int row = ar + i * 32;
                CP_ASYNC16(sbase + GOFF_A(nxt) + row * 80 + acb,
                           A + (size_t)(m0 + row) * DM + kf + ach);
                CP_ASYNC16(sbase + GOFF_B(nxt) + row * 80 + acb,
                           Wt + (size_t)(n0 + row) * DM + kf + ach);
            }
            CP_COMMIT();
        }

        const uint32_t* As = smg + (GOFF_A(cur) >> 2);
        const uint32_t* Bs = smg + (GOFF_B(cur) >> 2);

        #pragma unroll
        for (int ks = 0; ks < 2; ks++) {
            const int kw = ks * 8 + kq;
            uint32_t af[4][4];
            #pragma unroll
            for (int mi = 0; mi < 4; mi++) {
                const int w0 = (wm + mi * 16 + g) * LDHW + kw;
                af[mi][0] = As[w0];
                af[mi][1] = As[w0 + 8 * LDHW];
                af[mi][2] = As[w0 + 4];
                af[mi][3] = As[w0 + 8 * LDHW + 4];
            }
            #pragma unroll
            for (int nj = 0; nj < 8; nj++) {
                const int wb = (wn + nj * 8 + g) * LDHW + kw;
                uint32_t bb0 = Bs[wb];
                uint32_t bb1 = Bs[wb + 4];
                #pragma unroll
                for (int mi = 0; mi < 4; mi++)
                    MMA_F16(acc[mi][nj][0], acc[mi][nj][1],
                            acc[mi][nj][2], acc[mi][nj][3],
                            af[mi][0], af[mi][1], af[mi][2], af[mi][3],
                            bb0, bb1);
            }
        }
    }

    const float oscale = (qkv && z == 0) ? 0.125f : 1.0f;
    #pragma unroll
    for (int mi = 0; mi < 4; mi++) {
        const int row = m0 + wm + mi * 16 + g;
        #pragma unroll
        for (int nj = 0; nj < 8; nj++) {
            const int col = n0 + wn + nj * 8 + kq * 2;
            const float bx = bias[col], by = bias[col + 1];
            const float v0 = acc[mi][nj][0] + bx, v1 = acc[mi][nj][1] + by;
            const float v2 = acc[mi][nj][2] + bx, v3 = acc[mi][nj][3] + by;
            if (!qkv) {
                *(float2*)(C0 + (size_t)row * DM + col)       = make_float2(v0, v1);
                *(float2*)(C0 + (size_t)(row + 8) * DM + col) = make_float2(v2, v3);
            } else if (z < 2) {
                *(__half2*)(H + (size_t)row * DM + col) =
                    __floats2half2_rn(v0 * oscale, v1 * oscale);
                *(__half2*)(H + (size_t)(row + 8) * DM + col) =
                    __floats2half2_rn(v2 * oscale, v3 * oscale);
            } else {   // V: transposed [d][token]
                H[(size_t)col * MROWS + row]           = __float2half_rn(v0);
                H[(size_t)(col + 1) * MROWS + row]     = __float2half_rn(v1);
                H[(size_t)col * MROWS + row + 8]       = __float2half_rn(v2);
                H[(size_t)(col + 1) * MROWS + row + 8] = __float2half_rn(v3);
            }
        }
    }
}

// ---------------------------------------------------------------------------
// fp16 tensor-core flash attention (mma.m16n8k16), cp.async double-buffered.
// CTA: (b,h) x 128 q rows, 128 threads = 4 warps; warp = 32 q rows (mi=2).
// 32 chunks of 64 keys. Q A-frags + P A-frags register-resident (no P SMEM).
//   Kst[2][64 key][72h] : K chunk [key][d]
//   Vst[2][64 d ][72h]  : V chunk TRANSPOSED [d][key] (from g_vt16)
//   Qst [128 q ][72h]   : Q staging (prologue only)
// B-frag LDS bank = 4g+kq (+8ks const) -> conflict-free.
// ---------------------------------------------------------------------------
#define KW 36                          // words per row (72 halves)
#define ASTG (2 * 64 * KW + 64)        // stage: K + V + madd = 4672 words
#define OFF_K(s)  ((s) * ASTG)
#define OFF_V(s)  ((s) * ASTG + 64 * KW)
#define OFF_M(s)  ((s) * ASTG + 2 * 64 * KW)
#define OFF_Q     (2 * ASTG)           // 9344
#define ATT_WORDS (OFF_Q + 128 * KW)   // 13952 words
#define ATT_SMEM  (ATT_WORDS * 4)      // 55808 B

__global__ __launch_bounds__(128, 2) void attn_f16_k(
    const __half* __restrict__ q, const __half* __restrict__ k,
    const __half* __restrict__ vt, const int* __restrict__ mask,
    __half* __restrict__ o16)
{
    extern __shared__ uint32_t smu[];
    const uint32_t sbase = smem_u32(smu);

    const int t    = threadIdx.x;
    const int lane = t & 31;
    const int wid  = t >> 5;           // 0..3
    const int g    = lane >> 2;
    const int kq   = lane & 3;
    const int bh   = blockIdx.x;
    const int b    = bh >> 4;
    const int h    = bh & 15;
    const int qt   = blockIdx.y;

    const int qbase = b * SEQ + qt * 128;
    const int kbase = b * SEQ;
    const int hcol  = h * HD;
    const int wr    = wid * 32;

    // cp.async seg mapping: idx -> row = idx>>3, seg = idx&7 (16B segs)
    const int crow0 = t >> 3;          // 0..15
    const int cseg  = t & 7;

    // ---- Prologue: Q tile (8 iters => 128 rows), chunk 0 K/V ----
    #pragma unroll
    for (int it = 0; it < 8; it++) {
        const int row = crow0 + it * 16;
        CP_ASYNC16(sbase + OFF_Q * 4 + row * 144 + cseg * 16,
                   q + (size_t)(qbase + row) * DM + hcol + cseg * 8);
    }
    #pragma unroll
    for (int it = 0; it < 4; it++) {
        const int row = crow0 + it * 16;
        CP_ASYNC16(sbase + OFF_K(0) * 4 + row * 144 + cseg * 16,
                   k + (size_t)(kbase + row) * DM + hcol + cseg * 8);
        CP_ASYNC16(sbase + OFF_V(0) * 4 + row * 144 + cseg * 16,
                   vt + (size_t)(hcol + row) * MROWS + kbase + cseg * 8);
    }
    CP_COMMIT();
    if (t < 64)
        ((float*)(smu + OFF_M(0)))[t] = mask[b * SEQ + t] ? 0.f : -1e9f;
    int mreg = (t < 64) ? mask[b * SEQ + 64 + t] : 0;

    CP_WAIT0();
    __syncthreads();

    // ---- Pull Q A-fragments (2 mi x 4 ks x 4 regs) ----
    uint32_t qf[2][4][4];
    {
        const uint32_t* Qw = smu + OFF_Q;
        #pragma unroll
        for (int mi = 0; mi < 2; mi++)
            #pragma unroll
            for (int ks = 0; ks < 4; ks++) {
                const int kw = ks * 8 + kq;
                const int r0 = (wr + mi * 16 + g) * KW;
                qf[mi][ks][0] = Qw[r0 + kw];
                qf[mi][ks][1] = Qw[r0 + 8 * KW + kw];
                qf[mi][ks][2] = Qw[r0 + kw + 4];
                qf[mi][ks][3] = Qw[r0 + 8 * KW + kw + 4];
            }
    }

    float mx[2][2], lx[2][2];
    #pragma unroll
    for (int mi = 0; mi < 2; mi++) {
        mx[mi][0] = -1e30f; mx[mi][1] = -1e30f;
        lx[mi][0] = 0.f;    lx[mi][1] = 0.f;
    }
    float acc[2][8][4];
    #pragma unroll
    for (int mi = 0; mi < 2; mi++)
        #pragma unroll
        for (int nt = 0; nt < 8; nt++)
            #pragma unroll
            for (int j = 0; j < 4; j++) acc[mi][nt][j] = 0.f;

    #pragma unroll 1
    for (int kt = 0; kt < 32; kt++) {
        const int cur = kt & 1;
        const int nxt = cur ^ 1;

        if (kt > 0) {
            CP_WAIT0();
            __syncthreads();
        }

        if (kt + 1 < 32) {
            const int kb2 = kbase + (kt + 1) * 64;
            #pragma unroll
            for (int it = 0; it < 4; it++) {
                const int row = crow0 + it * 16;
                CP_ASYNC16(sbase + OFF_K(nxt) * 4 + row * 144 + cseg * 16,
                           k + (size_t)(kb2 + row) * DM + hcol + cseg * 8);
                CP_ASYNC16(sbase + OFF_V(nxt) * 4 + row * 144 + cseg * 16,
                           vt + (size_t)(hcol + row) * MROWS + kb2 + cseg * 8);
            }
            CP_COMMIT();
            if (t < 64) {
                ((float*)(smu + OFF_M(nxt)))[t] = mreg ? 0.f : -1e9f;
                if (kt + 2 < 32) mreg = mask[b * SEQ + (kt + 2) * 64 + t];
            }
        }

        const uint32_t* Ks = smu + OFF_K(cur);
        const uint32_t* Vs = smu + OFF_V(cur);
        const float* madd  = (const float*)(smu + OFF_M(cur));

        // ---- S = (Q/8) K^T : 4 k16 steps x 8 n-tiles x 2 mi = 64 MMA ----
        float s[2][8][4];
        #pragma unroll
        for (int mi = 0; mi < 2; mi++)
            #pragma unroll
            for (int nt = 0; nt < 8; nt++)
                #pragma unroll
                for (int j = 0; j < 4; j++) s[mi][nt][j] = 0.f;

        #pragma unroll
        for (int ks = 0; ks < 4; ks++) {
            const int kw = ks * 8 + kq;
            #pragma unroll
            for (int nt = 0; nt < 8; nt++) {
                const int rb = (nt * 8 + g) * KW + kw;
                uint32_t bb0 = Ks[rb];
                uint32_t bb1 = Ks[rb + 4];
                #pragma unroll
                for (int mi = 0; mi < 2; mi++)
                    MMA_F16(s[mi][nt][0], s[mi][nt][1], s[mi][nt][2], s[mi][nt][3],
                            qf[mi][ks][0], qf[mi][ks][1],
                            qf[mi][ks][2], qf[mi][ks][3], bb0, bb1);
            }
        }

        // ---- Online softmax; P packed to half2 registers ----
        uint32_t ph[2][8][2];
        #pragma unroll
        for (int mi = 0; mi < 2; mi++) {
            float rmax0 = -1e30f, rmax1 = -1e30f;
            #pragma unroll
            for (int nt = 0; nt < 8; nt++) {
                float2 md = *(float2*)&madd[nt * 8 + 2 * kq];
                s[mi][nt][0] += md.x; s[mi][nt][1] += md.y;
                s[mi][nt][2] += md.x; s[mi][nt][3] += md.y;
                rmax0 = fmaxf(rmax0, fmaxf(s[mi][nt][0], s[mi][nt][1]));
                rmax1 = fmaxf(rmax1, fmaxf(s[mi][nt][2], s[mi][nt][3]));
            }
            rmax0 = fmaxf(rmax0, __shfl_xor_sync(0xffffffffu, rmax0, 1));
            rmax0 = fmaxf(rmax0, __shfl_xor_sync(0xffffffffu, rmax0, 2));
            rmax1 = fmaxf(rmax1, __shfl_xor_sync(0xffffffffu, rmax1, 1));
            rmax1 = fmaxf(rmax1, __shfl_xor_sync(0xffffffffu, rmax1, 2));

            const float mn0 = fmaxf(mx[mi][0], rmax0);
            const float mn1 = fmaxf(mx[mi][1], rmax1);
            const float a0  = __expf(mx[mi][0] - mn0);
            const float a1  = __expf(mx[mi][1] - mn1);
            float sum0 = 0.f, sum1 = 0.f;

            #pragma unroll
            for (int nt = 0; nt < 8; nt++) {
                float p0 = __expf(s[mi][nt][0] - mn0);
                float p1 = __expf(s[mi][nt][1] - mn0);
                float p2 = __expf(s[mi][nt][2] - mn1);
                float p3 = __expf(s[mi][nt][3] - mn1);
                sum0 += p0 + p1;
                sum1 += p2 + p3;
                ph[mi][nt][0] = h2u(__floats2half2_rn(p0, p1));
                ph[mi][nt][1] = h2u(__floats2half2_rn(p2, p3));
            }
            sum0 += __shfl_xor_sync(0xffffffffu, sum0, 1);
            sum0 += __shfl_xor_sync(0xffffffffu, sum0, 2);
            sum1 += __shfl_xor_sync(0xffffffffu, sum1, 1);
            sum1 += __shfl_xor_sync(0xffffffffu, sum1, 2);

            lx[mi][0] = lx[mi][0] * a0 + sum0;  mx[mi][0] = mn0;
            lx[mi][1] = lx[mi][1] * a1 + sum1;  mx[mi][1] = mn1;
            #pragma unroll
            for (int nt = 0; nt < 8; nt++) {
                acc[mi][nt][0] *= a0; acc[mi][nt][1] *= a0;
                acc[mi][nt][2] *= a1; acc[mi][nt][3] *= a1;
            }
        }

        // ---- O += P V : P from registers, V (transposed) B-frags ----
        #pragma unroll
        for (int ks = 0; ks < 4; ks++) {
            const int kw = ks * 8 + kq;
            #pragma unroll
            for (int nt = 0; nt < 8; nt++) {
                const int rb = (nt * 8 + g) * KW + kw;
                uint32_t bb0 = Vs[rb];
                uint32_t bb1 = Vs[rb + 4];
                #pragma unroll
                for (int mi = 0; mi < 2; mi++)
                    MMA_F16(acc[mi][nt][0], acc[mi][nt][1],
                            acc[mi][nt][2], acc[mi][nt][3],
                            ph[mi][2 * ks][0],     ph[mi][2 * ks][1],
                            ph[mi][2 * ks + 1][0], ph[mi][2 * ks + 1][1],
                            bb0, bb1);
            }
        }
    }

    // ---- Finalize: fp16 output ----
    #pragma unroll
    for (int mi = 0; mi < 2; mi++) {
        const float inv0 = (lx[mi][0] > 0.f) ? 1.f / lx[mi][0] : 0.f;
        const float inv1 = (lx[mi][1] > 0.f) ? 1.f / lx[mi][1] : 0.f;
        const int row0 = qbase + wr + mi * 16 + g;
        #pragma unroll
        for (int nt = 0; nt < 8; nt++) {
            const int col = hcol + nt * 8 + 2 * kq;
            *(__half2*)(o16 + (size_t)row0 * DM + col) =
                __floats2half2_rn(acc[mi][nt][0] * inv0, acc[mi][nt][1] * inv0);
            *(__half2*)(o16 + (size_t)(row0 + 8) * DM + col) =
                __floats2half2_rn(acc[mi][nt][2] * inv1, acc[mi][nt][3] * inv1);
        }
    }
}

// ---------------------------------------------------------------------------
// Launch: convert -> fp16 QKV GEMM (Q scaled fp16 / K fp16 / V fp16^T) ->
// fp16 attention -> fp16 output GEMM (fp32 out).
// ---------------------------------------------------------------------------
extern "C" void kernel_launch(void* const* d_in, const int* in_sizes, int n_in,
                              void* d_out, int out_size)
{
    const float* Q    = (const float*)d_in[0];
    const float* K    = (const float*)d_in[1];
    const float* V    = (const float*)d_in[2];
    const int*   mask = (const int*)  d_in[3];
    const float* Wq   = (const float*)d_in[4];
    const float* bq   = (const float*)d_in[5];
    const float* Wk   = (const float*)d_in[6];
    const float* bk   = (const float*)d_in[7];
    const float* Wv   = (const float*)d_in[8];
    const float* bv   = (const float*)d_in[9];
    const float* Wo   = (const float*)d_in[10];
    const float* bo   = (const float*)d_in[11];
    float* out = (float*)d_out;

    __half *gin, *gwt, *gq16, *gk16, *gvt16, *gatt;
    cudaGetSymbolAddress((void**)&gin,   g_in16);
    cudaGetSymbolAddress((void**)&gwt,   g_wt16);
    cudaGetSymbolAddress((void**)&gq16,  g_q16);
    cudaGetSymbolAddress((void**)&gk16,  g_k16);
    cudaGetSymbolAddress((void**)&gvt16, g_vt16);
    cudaGetSymbolAddress((void**)&gatt,  g_att16);

    __half* inq = gin + 0 * (size_t)MROWS * DM;
    __half* ink = gin + 1 * (size_t)MROWS * DM;
    __half* inv = gin + 2 * (size_t)MROWS * DM;
    __half* wtq = gwt + 0 * (size_t)DM * DM;
    __half* wtk = gwt + 1 * (size_t)DM * DM;
    __half* wtv = gwt + 2 * (size_t)DM * DM;
    __half* wto = gwt + 3 * (size_t)DM * DM;

    cudaFuncSetAttribute(gemm_f16_k, cudaFuncAttributeMaxDynamicSharedMemorySize,
                         GEMM_SMEM);
    cudaFuncSetAttribute(attn_f16_k, cudaFuncAttributeMaxDynamicSharedMemorySize,
                         ATT_SMEM);

    cvt_in_k<<<1184, 256>>>(Q, K, V, gin);
    dim3 tgrid(DM / 32, DM / 32, 4);
    dim3 tblk(32, 8);
    round_wt16_k<<<tgrid, tblk>>>(Wq, Wk, Wv, Wo, gwt);

    dim3 qkv_grid(DM / 128, MROWS / 128, 3);  // (8, 64, 3)
    dim3 out_grid(DM / 128, MROWS / 128, 1);  // (8, 64, 1)
    dim3 attn_grid(NB * NH, SEQ / 128);       // (64, 16)

    gemm_f16_k<<<qkv_grid, 128, GEMM_SMEM>>>(inq, ink, inv, wtq, wtk, wtv,
                                             bq, bk, bv, nullptr,
                                             gq16, gk16, gvt16, 1);
    attn_f16_k<<<attn_grid, 128, ATT_SMEM>>>(gq16, gk16, gvt16, mask, gatt);
    gemm_f16_k<<<out_grid, 128, GEMM_SMEM>>>(gatt, gatt, gatt, wto, wto, wto,
                                             bo, bo, bo, out,
                                             nullptr, nullptr, nullptr, 0);
}

// round 14
// speedup vs baseline: 1.7628x; 1.0074x over previous
#include <cuda_runtime.h>
#include <cuda_fp16.h>
#include <math.h>
#include <stdint.h>

// Problem constants
#define NB   4
#define SEQ  2048
#define DM   1024
#define NH   16
#define HD   64
#define MROWS (NB*SEQ)          // 8192

// Q pre-scale: (1/sqrt(64)) * log2(e) so attention works in exp2 domain
#define QSCALE 0.18033688011111364f

// Scratch (device globals — no allocation allowed)
__device__ __half g_in16[3][MROWS*DM];   // fp16(Q,K,V inputs)
__device__ __half g_wt16[4][DM*DM];      // fp16 transposed weights [n][k]
__device__ __half g_q16 [MROWS*DM];      // fp16 q (pre-scaled by log2e/8)
__device__ __half g_k16 [MROWS*DM];      // fp16 k, natural [token][d]
__device__ __half g_vt16[MROWS*DM];      // fp16 v TRANSPOSED [d][token]
__device__ __half g_att16[MROWS*DM];     // fp16 attention output

__device__ __forceinline__ uint32_t smem_u32(const void* p) {
    uint32_t a;
    asm("{ .reg .u64 t; cvta.to.shared.u64 t, %1; cvt.u32.u64 %0, t; }"
        : "=r"(a) : "l"(p));
    return a;
}
__device__ __forceinline__ uint32_t h2u(__half2 h) {
    return *(uint32_t*)&h;
}
__device__ __forceinline__ float ex2f(float x) {
    float y;
    asm("ex2.approx.f32 %0, %1;" : "=f"(y) : "f"(x));
    return y;
}

#define CP_ASYNC16(dst, src) \
    asm volatile("cp.async.cg.shared.global [%0], [%1], 16;" \
                 :: "r"(dst), "l"(src) : "memory")
#define CP_COMMIT() asm volatile("cp.async.commit_group;" ::: "memory")
#define CP_WAIT0()  asm volatile("cp.async.wait_group 0;" ::: "memory")

#define MMA_F16(c0, c1, c2, c3, a0, a1, a2, a3, b0, b1) \
    asm volatile("mma.sync.aligned.m16n8k16.row.col.f32.f16.f16.f32 " \
        "{%0,%1,%2,%3}, {%4,%5,%6,%7}, {%8,%9}, {%0,%1,%2,%3};" \
        : "+f"(c0), "+f"(c1), "+f"(c2), "+f"(c3) \
        : "r"(a0), "r"(a1), "r"(a2), "r"(a3), "r"(b0), "r"(b1))

// ---------------------------------------------------------------------------
// Input convert: g_in16[z] = fp16_rn(input_z), z in {Q,K,V}.
// ---------------------------------------------------------------------------
__global__ __launch_bounds__(256) void cvt_in_k(
    const float* __restrict__ Q, const float* __restrict__ K,
    const float* __restrict__ V, __half* __restrict__ D)
{
    const int n4 = MROWS * DM / 4;
    for (int i = blockIdx.x * blockDim.x + threadIdx.x; i < 3 * n4;
         i += gridDim.x * blockDim.x) {
        const int w = i / n4, j = i - w * n4;
        const float* S = (w == 0) ? Q : (w == 1) ? K : V;
        float4 v = *(const float4*)(S + 4 * (size_t)j);
        __half2* d = (__half2*)(D + (size_t)w * MROWS * DM + 4 * (size_t)j);
        d[0] = __floats2half2_rn(v.x, v.y);
        d[1] = __floats2half2_rn(v.z, v.w);
    }
}

// ---------------------------------------------------------------------------
// Weight transpose + fp16 round: D[z][n*DM+k] = fp16_rn(W_z[k*DM+n]).
// ---------------------------------------------------------------------------
__global__ __launch_bounds__(256) void round_wt16_k(
    const float* __restrict__ W0, const float* __restrict__ W1,
    const float* __restrict__ W2, const float* __restrict__ W3,
    __half* __restrict__ D)
{
    __shared__ float tile[32][33];
    const int z = blockIdx.z;
    const float* W = (z == 0) ? W0 : (z == 1) ? W1 : (z == 2) ? W2 : W3;
    __half* Dw = D + (size_t)z * DM * DM;

    const int tx = threadIdx.x, ty = threadIdx.y;
    const int x = blockIdx.x * 32 + tx;
    #pragma unroll
    for (int j = ty; j < 32; j += 8)
        tile[j][tx] = W[(size_t)(blockIdx.y * 32 + j) * DM + x];
    __syncthreads();
    const int x2 = blockIdx.y * 32 + tx;
    #pragma unroll
    for (int j = ty; j < 32; j += 8)
        Dw[(size_t)(blockIdx.x * 32 + j) * DM + x2] = __float2half_rn(tile[tx][j]);
}

// ---------------------------------------------------------------------------
// fp16 tensor-core GEMM (mma.m16n8k16), cp.async double-buffered.
// qkv=1: z=0 -> fp16 out scaled QSCALE (Q); z=1 -> fp16 out (K);
//        z=2 -> fp16 out TRANSPOSED [d][token] (V).
// qkv=0: fp32 out (final output GEMM).
// ---------------------------------------------------------------------------
#define LDHW 20                       // words per row (40 halves)
#define SSTG 20480                    // bytes per stage (A 10240 + B 10240)
#define GOFF_A(s) ((s) * SSTG)
#define GOFF_B(s) ((s) * SSTG + 10240)
#define GEMM_SMEM (2 * SSTG)          // 40960 B

__global__ __launch_bounds__(128, 2) void gemm_f16_k(
    const __half* __restrict__ A0, const __half* __restrict__ A1,
    const __half* __restrict__ A2,
    const __half* __restrict__ W0, const __half* __restrict__ W1,
    const __half* __restrict__ W2,
    const float* __restrict__ b0_, const float* __restrict__ b1_,
    const float* __restrict__ b2_,
    float* __restrict__ C0,
    __half* __restrict__ H0, __half* __restrict__ H1, __half* __restrict__ H2,
    int qkv)
{
    extern __shared__ uint32_t smg[];
    const uint32_t sbase = smem_u32(smg);

    const int z = blockIdx.z;
    const __half* A    = (z == 0) ? A0 : (z == 1) ? A1 : A2;
    const __half* Wt   = (z == 0) ? W0 : (z == 1) ? W1 : W2;
    const float*  bias = (z == 0) ? b0_ : (z == 1) ? b1_ : b2_;
    __half*       H    = (z == 0) ? H0 : (z == 1) ? H1 : H2;

    const int t    = threadIdx.x;
    const int lane = t & 31;
    const int wid  = t >> 5;
    const int m0   = blockIdx.y * 128;
    const int n0   = blockIdx.x * 128;
    const int wm   = (wid & 1) * 64;
    const int wn   = (wid >> 1) * 64;
    const int g    = lane >> 2;
    const int kq   = lane & 3;

    const int ar  = t >> 2;            // 0..31
    const int acb = (t & 3) << 4;      // byte 0,16,32,48
    const int ach = acb >> 1;          // half offset

    float acc[4][8][4];
    #pragma unroll
    for (int mi = 0; mi < 4; mi++)
        #pragma unroll
        for (int nj = 0; nj < 8; nj++)
            #pragma unroll
            for (int r = 0; r < 4; r++) acc[mi][nj][r] = 0.f;

    #pragma unroll
    for (int i = 0; i < 4; i++) {
        const int row = ar + i * 32;
        CP_ASYNC16(sbase + GOFF_A(0) + row * 80 + acb,
                   A + (size_t)(m0 + row) * DM + ach);
        CP_ASYNC16(sbase + GOFF_B(0) + row * 80 + acb,
                   Wt + (size_t)(n0 + row) * DM + ach);
    }
    CP_COMMIT();

    #pragma unroll 1
    for (int kt = 0; kt < 32; kt++) {
        const int cur = kt & 1;
        const int nxt = cur ^ 1;

        CP_WAIT0();
        __syncthreads();

        if (kt + 1 < 32) {
            const int kf = (kt + 1) * 32;
            #pragma unroll
            for (int i = 0; i < 4; i++) {
                const int row = ar + i * 32;
                CP_ASYNC16(sbase + GOFF_A(nxt) + row * 80 + acb,
                           A + (size_t)(m0 + row) * DM + kf + ach);
                CP_ASYNC16(sbase + GOFF_B(nxt) + row * 80 + acb,
                           Wt + (size_t)(n0 + row) * DM + kf + ach);
            }
            CP_COMMIT();
        }

        const uint32_t* As = smg + (GOFF_A(cur) >> 2);
        const uint32_t* Bs = smg + (GOFF_B(cur) >> 2);

        #pragma unroll
        for (int ks = 0; ks < 2; ks++) {
            const int kw = ks * 8 + kq;
            uint32_t af[4][4];
            #pragma unroll
            for (int mi = 0; mi < 4; mi++) {
                const int w0 = (wm + mi * 16 + g) * LDHW + kw;
                af[mi][0] = As[w0];
                af[mi][1] = As[w0 + 8 * LDHW];
                af[mi][2] = As[w0 + 4];
                af[mi][3] = As[w0 + 8 * LDHW + 4];
            }
            #pragma unroll
            for (int nj = 0; nj < 8; nj++) {
                const int wb = (wn + nj * 8 + g) * LDHW + kw;
                uint32_t bb0 = Bs[wb];
                uint32_t bb1 = Bs[wb + 4];
                #pragma unroll
                for (int mi = 0; mi < 4; mi++)
                    MMA_F16(acc[mi][nj][0], acc[mi][nj][1],
                            acc[mi][nj][2], acc[mi][nj][3],
                            af[mi][0], af[mi][1], af[mi][2], af[mi][3],
                            bb0, bb1);
            }
        }
    }

    const float oscale = (qkv && z == 0) ? QSCALE : 1.0f;
    #pragma unroll
    for (int mi = 0; mi < 4; mi++) {
        const int row = m0 + wm + mi * 16 + g;
        #pragma unroll
        for (int nj = 0; nj < 8; nj++) {
            const int col = n0 + wn + nj * 8 + kq * 2;
            const float bx = bias[col], by = bias[col + 1];
            const float v0 = acc[mi][nj][0] + bx, v1 = acc[mi][nj][1] + by;
            const float v2 = acc[mi][nj][2] + bx, v3 = acc[mi][nj][3] + by;
            if (!qkv) {
                *(float2*)(C0 + (size_t)row * DM + col)       = make_float2(v0, v1);
                *(float2*)(C0 + (size_t)(row + 8) * DM + col) = make_float2(v2, v3);
            } else if (z < 2) {
                *(__half2*)(H + (size_t)row * DM + col) =
                    __floats2half2_rn(v0 * oscale, v1 * oscale);
                *(__half2*)(H + (size_t)(row + 8) * DM + col) =
                    __floats2half2_rn(v2 * oscale, v3 * oscale);
            } else {   // V: transposed [d][token]
                H[(size_t)col * MROWS + row]           = __float2half_rn(v0);
                H[(size_t)(col + 1) * MROWS + row]     = __float2half_rn(v1);
                H[(size_t)col * MROWS + row + 8]       = __float2half_rn(v2);
                H[(size_t)(col + 1) * MROWS + row + 8] = __float2half_rn(v3);
            }
        }
    }
}

// ---------------------------------------------------------------------------
// fp16 tensor-core flash attention (mma.m16n8k16), cp.async double-buffered.
// exp2-domain softmax (Q pre-scaled by log2e/8). Row sums via MMA against a
// constant all-ones B operand (no LDS, no FADD reduction). Rescale skipped by
// warp vote when no row saw a new max.
// ---------------------------------------------------------------------------
#define KW 36                          // words per row (72 halves)
#define ASTG (2 * 64 * KW + 64)        // stage: K + V + madd = 4672 words
#define OFF_K(s)  ((s) * ASTG)
#define OFF_V(s)  ((s) * ASTG + 64 * KW)
#define OFF_M(s)  ((s) * ASTG + 2 * 64 * KW)
#define OFF_Q     (2 * ASTG)           // 9344
#define ATT_WORDS (OFF_Q + 128 * KW)   // 13952 words
#define ATT_SMEM  (ATT_WORDS * 4)      // 55808 B
#define ONES2 0x3C003C00u              // half2 {1.0, 1.0}

__global__ __launch_bounds__(128, 2) void attn_f16_k(
    const __half* __restrict__ q, const __half* __restrict__ k,
    const __half* __restrict__ vt, const int* __restrict__ mask,
    __half* __restrict__ o16)
{
    extern __shared__ uint32_t smu[];
    const uint32_t sbase = smem_u32(smu);

    const int t    = threadIdx.x;
    const int lane = t & 31;
    const int wid  = t >> 5;           // 0..3
    const int g    = lane >> 2;
    const int kq   = lane & 3;
    const int bh   = blockIdx.x;
    const int b    = bh >> 4;
    const int h    = bh & 15;
    const int qt   = blockIdx.y;

    const int qbase = b * SEQ + qt * 128;
    const int kbase = b * SEQ;
    const int hcol  = h * HD;
    const int wr    = wid * 32;

    const int crow0 = t >> 3;          // 0..15
    const int cseg  = t & 7;

    // ---- Prologue: Q tile, chunk 0 K/V ----
    #pragma unroll
    for (int it = 0; it < 8; it++) {
        const int row = crow0 + it * 16;
        CP_ASYNC16(sbase + OFF_Q * 4 + row * 144 + cseg * 16,
                   q + (size_t)(qbase + row) * DM + hcol + cseg * 8);
    }
    #pragma unroll
    for (int it = 0; it < 4; it++) {
        const int row = crow0 + it * 16;
        CP_ASYNC16(sbase + OFF_K(0) * 4 + row * 144 + cseg * 16,
                   k + (size_t)(kbase + row) * DM + hcol + cseg * 8);
        CP_ASYNC16(sbase + OFF_V(0) * 4 + row * 144 + cseg * 16,
                   vt + (size_t)(hcol + row) * MROWS + kbase + cseg * 8);
    }
    CP_COMMIT();
    if (t < 64)
        ((float*)(smu + OFF_M(0)))[t] = mask[b * SEQ + t] ? 0.f : -1e9f;
    int mreg = (t < 64) ? mask[b * SEQ + 64 + t] : 0;

    CP_WAIT0();
    __syncthreads();

    // ---- Pull Q A-fragments ----
    uint32_t qf[2][4][4];
    {
        const uint32_t* Qw = smu + OFF_Q;
        #pragma unroll
        for (int mi = 0; mi < 2; mi++)
            #pragma unroll
            for (int ks = 0; ks < 4; ks++) {
                const int kw = ks * 8 + kq;
                const int r0 = (wr + mi * 16 + g) * KW;
                qf[mi][ks][0] = Qw[r0 + kw];
                qf[mi][ks][1] = Qw[r0 + 8 * KW + kw];
                qf[mi][ks][2] = Qw[r0 + kw + 4];
                qf[mi][ks][3] = Qw[r0 + 8 * KW + kw + 4];
            }
    }

    float mx[2][2];
    #pragma unroll
    for (int mi = 0; mi < 2; mi++) { mx[mi][0] = -1e30f; mx[mi][1] = -1e30f; }
    float acc[2][8][4];
    float accS[2][4];                   // row-sum tile (ones-column MMA)
    #pragma unroll
    for (int mi = 0; mi < 2; mi++) {
        #pragma unroll
        for (int nt = 0; nt < 8; nt++)
            #pragma unroll
            for (int j = 0; j < 4; j++) acc[mi][nt][j] = 0.f;
        #pragma unroll
        for (int j = 0; j < 4; j++) accS[mi][j] = 0.f;
    }

    #pragma unroll 1
    for (int kt = 0; kt < 32; kt++) {
        const int cur = kt & 1;
        const int nxt = cur ^ 1;

        if (kt > 0) {
            CP_WAIT0();
            __syncthreads();
        }

        if (kt + 1 < 32) {
            const int kb2 = kbase + (kt + 1) * 64;
            #pragma unroll
            for (int it = 0; it < 4; it++) {
                const int row = crow0 + it * 16;
                CP_ASYNC16(sbase + OFF_K(nxt) * 4 + row * 144 + cseg * 16,
                           k + (size_t)(kb2 + row) * DM + hcol + cseg * 8);
                CP_ASYNC16(sbase + OFF_V(nxt) * 4 + row * 144 + cseg * 16,
                           vt + (size_t)(hcol + row) * MROWS + kb2 + cseg * 8);
            }
            CP_COMMIT();
            if (t < 64) {
                ((float*)(smu + OFF_M(nxt)))[t] = mreg ? 0.f : -1e9f;
                if (kt + 2 < 32) mreg = mask[b * SEQ + (kt + 2) * 64 + t];
            }
        }

        const uint32_t* Ks = smu + OFF_K(cur);
        const uint32_t* Vs = smu + OFF_V(cur);
        const float* madd  = (const float*)(smu + OFF_M(cur));

        // ---- S = (Q*log2e/8) K^T ----
        float s[2][8][4];
        #pragma unroll
        for (int mi = 0; mi < 2; mi++)
            #pragma unroll
            for (int nt = 0; nt < 8; nt++)
                #pragma unroll
                for (int j = 0; j < 4; j++) s[mi][nt][j] = 0.f;

        #pragma unroll
        for (int ks = 0; ks < 4; ks++) {
            const int kw = ks * 8 + kq;
            #pragma unroll
            for (int nt = 0; nt < 8; nt++) {
                const int rb = (nt * 8 + g) * KW + kw;
                uint32_t bb0 = Ks[rb];
                uint32_t bb1 = Ks[rb + 4];
                #pragma unroll
                for (int mi = 0; mi < 2; mi++)
                    MMA_F16(s[mi][nt][0], s[mi][nt][1], s[mi][nt][2], s[mi][nt][3],
                            qf[mi][ks][0], qf[mi][ks][1],
                            qf[mi][ks][2], qf[mi][ks][3], bb0, bb1);
            }
        }

        // ---- Online softmax (exp2 domain); P packed to half2 registers ----
        uint32_t ph[2][8][2];
        #pragma unroll
        for (int mi = 0; mi < 2; mi++) {
            float rmax0 = -1e30f, rmax1 = -1e30f;
            #pragma unroll
            for (int nt = 0; nt < 8; nt++) {
                float2 md = *(float2*)&madd[nt * 8 + 2 * kq];
                s[mi][nt][0] += md.x; s[mi][nt][1] += md.y;
                s[mi][nt][2] += md.x; s[mi][nt][3] += md.y;
                rmax0 = fmaxf(rmax0, fmaxf(s[mi][nt][0], s[mi][nt][1]));
                rmax1 = fmaxf(rmax1, fmaxf(s[mi][nt][2], s[mi][nt][3]));
            }
            rmax0 = fmaxf(rmax0, __shfl_xor_sync(0xffffffffu, rmax0, 1));
            rmax0 = fmaxf(rmax0, __shfl_xor_sync(0xffffffffu, rmax0, 2));
            rmax1 = fmaxf(rmax1, __shfl_xor_sync(0xffffffffu, rmax1, 1));
            rmax1 = fmaxf(rmax1, __shfl_xor_sync(0xffffffffu, rmax1, 2));

            const float mn0 = fmaxf(mx[mi][0], rmax0);
            const float mn1 = fmaxf(mx[mi][1], rmax1);
            const float a0  = ex2f(mx[mi][0] - mn0);
            const float a1  = ex2f(mx[mi][1] - mn1);
            mx[mi][0] = mn0;
            mx[mi][1] = mn1;

            #pragma unroll
            for (int nt = 0; nt < 8; nt++) {
                float p0 = ex2f(s[mi][nt][0] - mn0);
                float p1 = ex2f(s[mi][nt][1] - mn0);
                float p2 = ex2f(s[mi][nt][2] - mn1);
                float p3 = ex2f(s[mi][nt][3] - mn1);
                ph[mi][nt][0] = h2u(__floats2half2_rn(p0, p1));
                ph[mi][nt][1] = h2u(__floats2half2_rn(p2, p3));
            }

            // Rescale (skipped by warp vote when alpha == 1 everywhere)
            if (!__all_sync(0xffffffffu, (a0 == 1.f) & (a1 == 1.f))) {
                #pragma unroll
                for (int nt = 0; nt < 8; nt++) {
                    acc[mi][nt][0] *= a0; acc[mi][nt][1] *= a0;
                    acc[mi][nt][2] *= a1; acc[mi][nt][3] *= a1;
                }
                accS[mi][0] *= a0; accS[mi][1] *= a0;
                accS[mi][2] *= a1; accS[mi][3] *= a1;
            }
        }

        // ---- O += P V (+ row sums via constant-ones B) ----
        #pragma unroll
        for (int ks = 0; ks < 4; ks++) {
            const int kw = ks * 8 + kq;
            #pragma unroll
            for (int nt = 0; nt < 8; nt++) {
                const int rb = (nt * 8 + g) * KW + kw;
                uint32_t bb0 = Vs[rb];
                uint32_t bb1 = Vs[rb + 4];
                #pragma unroll
                for (int mi = 0; mi < 2; mi++)
                    MMA_F16(acc[mi][nt][0], acc[mi][nt][1],
                            acc[mi][nt][2], acc[mi][nt][3],
                            ph[mi][2 * ks][0],     ph[mi][2 * ks][1],
                            ph[mi][2 * ks + 1][0], ph[mi][2 * ks + 1][1],
                            bb0, bb1);
            }
            #pragma unroll
            for (int mi = 0; mi < 2; mi++)
                MMA_F16(accS[mi][0], accS[mi][1], accS[mi][2], accS[mi][3],
                        ph[mi][2 * ks][0],     ph[mi][2 * ks][1],
                        ph[mi][2 * ks + 1][0], ph[mi][2 * ks + 1][1],
                        ONES2, ONES2);
        }
    }

    // ---- Finalize: fp16 output (denominator from the ones-MMA tile) ----
    #pragma unroll
    for (int mi = 0; mi < 2; mi++) {
        const float inv0 = (accS[mi][0] > 0.f) ? 1.f / accS[mi][0] : 0.f;
        const float inv1 = (accS[mi][2] > 0.f) ? 1.f / accS[mi][2] : 0.f;
        const int row0 = qbase + wr + mi * 16 + g;
        #pragma unroll
        for (int nt = 0; nt < 8; nt++) {
            const int col = hcol + nt * 8 + 2 * kq;
            *(__half2*)(o16 + (size_t)row0 * DM + col) =
                __floats2half2_rn(acc[mi][nt][0] * inv0, acc[mi][nt][1] * inv0);
            *(__half2*)(o16 + (size_t)(row0 + 8) * DM + col) =
                __floats2half2_rn(acc[mi][nt][2] * inv1, acc[mi][nt][3] * inv1);
        }
    }
}

// ---------------------------------------------------------------------------
// Launch
// ---------------------------------------------------------------------------
extern "C" void kernel_launch(void* const* d_in, const int* in_sizes, int n_in,
                              void* d_out, int out_size)
{
    const float* Q    = (const float*)d_in[0];
    const float* K    = (const float*)d_in[1];
    const float* V    = (const float*)d_in[2];
    const int*   mask = (const int*)  d_in[3];
    const float* Wq   = (const float*)d_in[4];
    const float* bq   = (const float*)d_in[5];
    const float* Wk   = (const float*)d_in[6];
    const float* bk   = (const float*)d_in[7];
    const float* Wv   = (const float*)d_in[8];
    const float* bv   = (const float*)d_in[9];
    const float* Wo   = (const float*)d_in[10];
    const float* bo   = (const float*)d_in[11];
    float* out = (float*)d_out;

    __half *gin, *gwt, *gq16, *gk16, *gvt16, *gatt;
    cudaGetSymbolAddress((void**)&gin,   g_in16);
    cudaGetSymbolAddress((void**)&gwt,   g_wt16);
    cudaGetSymbolAddress((void**)&gq16,  g_q16);
    cudaGetSymbolAddress((void**)&gk16,  g_k16);
    cudaGetSymbolAddress((void**)&gvt16, g_vt16);
    cudaGetSymbolAddress((void**)&gatt,  g_att16);

    __half* inq = gin + 0 * (size_t)MROWS * DM;
    __half* ink = gin + 1 * (size_t)MROWS * DM;
    __half* inv = gin + 2 * (size_t)MROWS * DM;
    __half* wtq = gwt + 0 * (size_t)DM * DM;
    __half* wtk = gwt + 1 * (size_t)DM * DM;
    __half* wtv = gwt + 2 * (size_t)DM * DM;
    __half* wto = gwt + 3 * (size_t)DM * DM;

    cudaFuncSetAttribute(gemm_f16_k, cudaFuncAttributeMaxDynamicSharedMemorySize,
                         GEMM_SMEM);
    cudaFuncSetAttribute(attn_f16_k, cudaFuncAttributeMaxDynamicSharedMemorySize,
                         ATT_SMEM);

    cvt_in_k<<<1184, 256>>>(Q, K, V, gin);
    dim3 tgrid(DM / 32, DM / 32, 4);
    dim3 tblk(32, 8);
    round_wt16_k<<<tgrid, tblk>>>(Wq, Wk, Wv, Wo, gwt);

    dim3 qkv_grid(DM / 128, MROWS / 128, 3);  // (8, 64, 3)
    dim3 out_grid(DM / 128, MROWS / 128, 1);  // (8, 64, 1)
    dim3 attn_grid(NB * NH, SEQ / 128);       // (64, 16)

    gemm_f16_k<<<qkv_grid, 128, GEMM_SMEM>>>(inq, ink, inv, wtq, wtk, wtv,
                                             bq, bk, bv, nullptr,
                                             gq16, gk16, gvt16, 1);
    attn_f16_k<<<attn_grid, 128, ATT_SMEM>>>(gq16, gk16, gvt16, mask, gatt);
    gemm_f16_k<<<out_grid, 128, GEMM_SMEM>>>(gatt, gatt, gatt, wto, wto, wto,
                                             bo, bo, bo, out,
                                             nullptr, nullptr, nullptr, 0);
}

// round 15
// speedup vs baseline: 1.7794x; 1.0094x over previous
#include <cuda_runtime.h>
#include <cuda_fp16.h>
#include <math.h>
#include <stdint.h>

// Problem constants
#define NB   4
#define SEQ  2048
#define DM   1024
#define NH   16
#define HD   64
#define MROWS (NB*SEQ)          // 8192

// Q pre-scale: (1/sqrt(64)) * log2(e) so attention works in exp2 domain
#define QSCALE 0.18033688011111364f

// Scratch (device globals — no allocation allowed)
__device__ __half g_in16[3][MROWS*DM];   // fp16(Q,K,V inputs)
__device__ __half g_wt16[4][DM*DM];      // fp16 transposed weights [n][k]
__device__ __half g_q16 [MROWS*DM];      // fp16 q (pre-scaled by log2e/8)
__device__ __half g_k16 [MROWS*DM];      // fp16 k, natural [token][d]
__device__ __half g_vt16[MROWS*DM];      // fp16 v TRANSPOSED [d][token]
__device__ __half g_att16[MROWS*DM];     // fp16 attention output

__device__ __forceinline__ uint32_t smem_u32(const void* p) {
    uint32_t a;
    asm("{ .reg .u64 t; cvta.to.shared.u64 t, %1; cvt.u32.u64 %0, t; }"
        : "=r"(a) : "l"(p));
    return a;
}
__device__ __forceinline__ uint32_t h2u(__half2 h) {
    return *(uint32_t*)&h;
}
__device__ __forceinline__ float ex2f(float x) {
    float y;
    asm("ex2.approx.f32 %0, %1;" : "=f"(y) : "f"(x));
    return y;
}

#define CP_ASYNC16(dst, src) \
    asm volatile("cp.async.cg.shared.global [%0], [%1], 16;" \
                 :: "r"(dst), "l"(src) : "memory")
#define CP_COMMIT() asm volatile("cp.async.commit_group;" ::: "memory")
#define CP_WAIT0()  asm volatile("cp.async.wait_group 0;" ::: "memory")
#define CP_WAIT1()  asm volatile("cp.async.wait_group 1;" ::: "memory")

#define MMA_F16(c0, c1, c2, c3, a0, a1, a2, a3, b0, b1) \
    asm volatile("mma.sync.aligned.m16n8k16.row.col.f32.f16.f16.f32 " \
        "{%0,%1,%2,%3}, {%4,%5,%6,%7}, {%8,%9}, {%0,%1,%2,%3};" \
        : "+f"(c0), "+f"(c1), "+f"(c2), "+f"(c3) \
        : "r"(a0), "r"(a1), "r"(a2), "r"(a3), "r"(b0), "r"(b1))

// ---------------------------------------------------------------------------
// Input convert: g_in16[z] = fp16_rn(input_z), z in {Q,K,V}.
// ---------------------------------------------------------------------------
__global__ __launch_bounds__(256) void cvt_in_k(
    const float* __restrict__ Q, const float* __restrict__ K,
    const float* __restrict__ V, __half* __restrict__ D)
{
    const int n4 = MROWS * DM / 4;
    for (int i = blockIdx.x * blockDim.x + threadIdx.x; i < 3 * n4;
         i += gridDim.x * blockDim.x) {
        const int w = i / n4, j = i - w * n4;
        const float* S = (w == 0) ? Q : (w == 1) ? K : V;
        float4 v = *(const float4*)(S + 4 * (size_t)j);
        __half2* d = (__half2*)(D + (size_t)w * MROWS * DM + 4 * (size_t)j);
        d[0] = __floats2half2_rn(v.x, v.y);
        d[1] = __floats2half2_rn(v.z, v.w);
    }
}

// ---------------------------------------------------------------------------
// Weight transpose + fp16 round: D[z][n*DM+k] = fp16_rn(W_z[k*DM+n]).
// ---------------------------------------------------------------------------
__global__ __launch_bounds__(256) void round_wt16_k(
    const float* __restrict__ W0, const float* __restrict__ W1,
    const float* __restrict__ W2, const float* __restrict__ W3,
    __half* __restrict__ D)
{
    __shared__ float tile[32][33];
    const int z = blockIdx.z;
    const float* W = (z == 0) ? W0 : (z == 1) ? W1 : (z == 2) ? W2 : W3;
    __half* Dw = D + (size_t)z * DM * DM;

    const int tx = threadIdx.x, ty = threadIdx.y;
    const int x = blockIdx.x * 32 + tx;
    #pragma unroll
    for (int j = ty; j < 32; j += 8)
        tile[j][tx] = W[(size_t)(blockIdx.y * 32 + j) * DM + x];
    __syncthreads();
    const int x2 = blockIdx.y * 32 + tx;
    #pragma unroll
    for (int j = ty; j < 32; j += 8)
        Dw[(size_t)(blockIdx.x * 32 + j) * DM + x2] = __float2half_rn(tile[tx][j]);
}

// ---------------------------------------------------------------------------
// fp16 tensor-core GEMM (mma.m16n8k16), cp.async double-buffered. (R13 form.)
// qkv=1: z=0 -> fp16 out scaled QSCALE (Q); z=1 -> fp16 out (K);
//        z=2 -> fp16 out TRANSPOSED [d][token] (V).
// qkv=0: fp32 out (final output GEMM).
// ---------------------------------------------------------------------------
#define LDHW 20                       // words per row (40 halves)
#define SSTG 20480                    // bytes per stage (A 10240 + B 10240)
#define GOFF_A(s) ((s) * SSTG)
#define GOFF_B(s) ((s) * SSTG + 10240)
#define GEMM_SMEM (2 * SSTG)          // 40960 B

__global__ __launch_bounds__(128, 2) void gemm_f16_k(
    const __half* __restrict__ A0, const __half* __restrict__ A1,
    const __half* __restrict__ A2,
    const __half* __restrict__ W0, const __half* __restrict__ W1,
    const __half* __restrict__ W2,
    const float* __restrict__ b0_, const float* __restrict__ b1_,
    const float* __restrict__ b2_,
    float* __restrict__ C0,
    __half* __restrict__ H0, __half* __restrict__ H1, __half* __restrict__ H2,
    int qkv)
{
    extern __shared__ uint32_t smg[];
    const uint32_t sbase = smem_u32(smg);

    const int z = blockIdx.z;
    const __half* A    = (z == 0) ? A0 : (z == 1) ? A1 : A2;
    const __half* Wt   = (z == 0) ? W0 : (z == 1) ? W1 : W2;
    const float*  bias = (z == 0) ? b0_ : (z == 1) ? b1_ : b2_;
    __half*       H    = (z == 0) ? H0 : (z == 1) ? H1 : H2;

    const int t    = threadIdx.x;
    const int lane = t & 31;
    const int wid  = t >> 5;
    const int m0   = blockIdx.y * 128;
    const int n0   = blockIdx.x * 128;
    const int wm   = (wid & 1) * 64;
    const int wn   = (wid >> 1) * 64;
    const int g    = lane >> 2;
    const int kq   = lane & 3;

    const int ar  = t >> 2;            // 0..31
    const int acb = (t & 3) << 4;      // byte 0,16,32,48
    const int ach = acb >> 1;          // half offset

    float acc[4][8][4];
    #pragma unroll
    for (int mi = 0; mi < 4; mi++)
        #pragma unroll
        for (int nj = 0; nj < 8; nj++)
            #pragma unroll
            for (int r = 0; r < 4; r++) acc[mi][nj][r] = 0.f;

    #pragma unroll
    for (int i = 0; i < 4; i++) {
        const int row = ar + i * 32;
        CP_ASYNC16(sbase + GOFF_A(0) + row * 80 + acb,
                   A + (size_t)(m0 + row) * DM + ach);
        CP_ASYNC16(sbase + GOFF_B(0) + row * 80 + acb,
                   Wt + (size_t)(n0 + row) * DM + ach);
    }
    CP_COMMIT();

    #pragma unroll 1
    for (int kt = 0; kt < 32; kt++) {
        const int cur = kt & 1;
        const int nxt = cur ^ 1;

        CP_WAIT0();
        __syncthreads();

        if (kt + 1 < 32) {
            const int kf = (kt + 1) * 32;
            #pragma unroll
            for (int i = 0; i < 4; i++) {
                const int row = ar + i * 32;
                CP_ASYNC16(sbase + GOFF_A(nxt) + row * 80 + acb,
                           A + (size_t)(m0 + row) * DM + kf + ach);
                CP_ASYNC16(sbase + GOFF_B(nxt) + row * 80 + acb,
                           Wt + (size_t)(n0 + row) * DM + kf + ach);
            }
            CP_COMMIT();
        }

        const uint32_t* As = smg + (GOFF_A(cur) >> 2);
        const uint32_t* Bs = smg + (GOFF_B(cur) >> 2);

        #pragma unroll
        for (int ks = 0; ks < 2; ks++) {
            const int kw = ks * 8 + kq;
            uint32_t af[4][4];
            #pragma unroll
            for (int mi = 0; mi < 4; mi++) {
                const int w0 = (wm + mi * 16 + g) * LDHW + kw;
                af[mi][0] = As[w0];
                af[mi][1] = As[w0 + 8 * LDHW];
                af[mi][2] = As[w0 + 4];
                af[mi][3] = As[w0 + 8 * LDHW + 4];
            }
            #pragma unroll
            for (int nj = 0; nj < 8; nj++) {
                const int wb = (wn + nj * 8 + g) * LDHW + kw;
                uint32_t bb0 = Bs[wb];
                uint32_t bb1 = Bs[wb + 4];
                #pragma unroll
                for (int mi = 0; mi < 4; mi++)
                    MMA_F16(acc[mi][nj][0], acc[mi][nj][1],
                            acc[mi][nj][2], acc[mi][nj][3],
                            af[mi][0], af[mi][1], af[mi][2], af[mi][3],
                            bb0, bb1);
            }
        }
    }

    const float oscale = (qkv && z == 0) ? QSCALE : 1.0f;
    #pragma unroll
    for (int mi = 0; mi < 4; mi++) {
        const int row = m0 + wm + mi * 16 + g;
        #pragma unroll
        for (int nj = 0; nj < 8; nj++) {
            const int col = n0 + wn + nj * 8 + kq * 2;
            const float bx = bias[col], by = bias[col + 1];
            const float v0 = acc[mi][nj][0] + bx, v1 = acc[mi][nj][1] + by;
            const float v2 = acc[mi][nj][2] + bx, v3 = acc[mi][nj][3] + by;
            if (!qkv) {
                *(float2*)(C0 + (size_t)row * DM + col)       = make_float2(v0, v1);
                *(float2*)(C0 + (size_t)(row + 8) * DM + col) = make_float2(v2, v3);
            } else if (z < 2) {
                *(__half2*)(H + (size_t)row * DM + col) =
                    __floats2half2_rn(v0 * oscale, v1 * oscale);
                *(__half2*)(H + (size_t)(row + 8) * DM + col) =
                    __floats2half2_rn(v2 * oscale, v3 * oscale);
            } else {   // V: transposed [d][token]
                H[(size_t)col * MROWS + row]           = __float2half_rn(v0);
                H[(size_t)(col + 1) * MROWS + row]     = __float2half_rn(v1);
                H[(size_t)col * MROWS + row + 8]       = __float2half_rn(v2);
                H[(size_t)(col + 1) * MROWS + row + 8] = __float2half_rn(v3);
            }
        }
    }
}

// ---------------------------------------------------------------------------
// fp16 tensor-core flash attention (mma.m16n8k16), 3-stage cp.async pipeline.
// exp2-domain softmax with half2 ex2 (P produced directly as half2 pairs).
// Row sums via constant-ones MMA; rescale skipped by warp vote.
// ---------------------------------------------------------------------------
#define KW 36                          // words per row (72 halves)
#define ASTG (2 * 64 * KW + 64)        // stage: K + V + madd = 4672 words
#define OFF_K(s)  ((s) * ASTG)
#define OFF_V(s)  ((s) * ASTG + 64 * KW)
#define OFF_M(s)  ((s) * ASTG + 2 * 64 * KW)
#define OFF_Q     (3 * ASTG)           // 14016
#define ATT_WORDS (OFF_Q + 128 * KW)   // 18624 words
#define ATT_SMEM  (ATT_WORDS * 4)      // 74496 B
#define ONES2 0x3C003C00u              // half2 {1.0, 1.0}

__global__ __launch_bounds__(128, 2) void attn_f16_k(
    const __half* __restrict__ q, const __half* __restrict__ k,
    const __half* __restrict__ vt, const int* __restrict__ mask,
    __half* __restrict__ o16)
{
    extern __shared__ uint32_t smu[];
    const uint32_t sbase = smem_u32(smu);

    const int t    = threadIdx.x;
    const int lane = t & 31;
    const int wid  = t >> 5;           // 0..3
    const int g    = lane >> 2;
    const int kq   = lane & 3;
    const int bh   = blockIdx.x;
    const int b    = bh >> 4;
    const int h    = bh & 15;
    const int qt   = blockIdx.y;

    const int qbase = b * SEQ + qt * 128;
    const int kbase = b * SEQ;
    const int hcol  = h * HD;
    const int wr    = wid * 32;

    const int crow0 = t >> 3;          // 0..15
    const int cseg  = t & 7;

    // ---- Prologue: G0 = Q + chunk0 K/V; G1 = chunk1 K/V ----
    #pragma unroll
    for (int it = 0; it < 8; it++) {
        const int row = crow0 + it * 16;
        CP_ASYNC16(sbase + OFF_Q * 4 + row * 144 + cseg * 16,
                   q + (size_t)(qbase + row) * DM + hcol + cseg * 8);
    }
    #pragma unroll
    for (int it = 0; it < 4; it++) {
        const int row = crow0 + it * 16;
        CP_ASYNC16(sbase + OFF_K(0) * 4 + row * 144 + cseg * 16,
                   k + (size_t)(kbase + row) * DM + hcol + cseg * 8);
        CP_ASYNC16(sbase + OFF_V(0) * 4 + row * 144 + cseg * 16,
                   vt + (size_t)(hcol + row) * MROWS + kbase + cseg * 8);
    }
    CP_COMMIT();
    #pragma unroll
    for (int it = 0; it < 4; it++) {
        const int row = crow0 + it * 16;
        CP_ASYNC16(sbase + OFF_K(1) * 4 + row * 144 + cseg * 16,
                   k + (size_t)(kbase + 64 + row) * DM + hcol + cseg * 8);
        CP_ASYNC16(sbase + OFF_V(1) * 4 + row * 144 + cseg * 16,
                   vt + (size_t)(hcol + row) * MROWS + kbase + 64 + cseg * 8);
    }
    CP_COMMIT();
    if (t < 64) {
        ((float*)(smu + OFF_M(0)))[t] = mask[b * SEQ + t] ? 0.f : -1e9f;
        ((float*)(smu + OFF_M(1)))[t] = mask[b * SEQ + 64 + t] ? 0.f : -1e9f;
    }
    int mreg = (t < 64) ? mask[b * SEQ + 128 + t] : 0;

    CP_WAIT1();        // G0 (Q + chunk0) landed; G1 may be in flight
    __syncthreads();

    // ---- Pull Q A-fragments ----
    uint32_t qf[2][4][4];
    {
        const uint32_t* Qw = smu + OFF_Q;
        #pragma unroll
        for (int mi = 0; mi < 2; mi++)
            #pragma unroll
            for (int ks = 0; ks < 4; ks++) {
                const int kw = ks * 8 + kq;
                const int r0 = (wr + mi * 16 + g) * KW;
                qf[mi][ks][0] = Qw[r0 + kw];
                qf[mi][ks][1] = Qw[r0 + 8 * KW + kw];
                qf[mi][ks][2] = Qw[r0 + kw + 4];
                qf[mi][ks][3] = Qw[r0 + 8 * KW + kw + 4];
            }
    }

    float mx[2][2];
    #pragma unroll
    for (int mi = 0; mi < 2; mi++) { mx[mi][0] = -1e30f; mx[mi][1] = -1e30f; }
    float acc[2][8][4];
    float accS[2][4];
    #pragma unroll
    for (int mi = 0; mi < 2; mi++) {
        #pragma unroll
        for (int nt = 0; nt < 8; nt++)
            #pragma unroll
            for (int j = 0; j < 4; j++) acc[mi][nt][j] = 0.f;
        #pragma unroll
        for (int j = 0; j < 4; j++) accS[mi][j] = 0.f;
    }

    #pragma unroll 1
    for (int kt = 0; kt < 32; kt++) {
        const int cur = kt % 3;

        if (kt > 0) {
            if (kt + 1 < 32) CP_WAIT1(); else CP_WAIT0();
            __syncthreads();
        }

        if (kt + 2 < 32) {
            const int stg = (kt + 2) % 3;
            const int kb2 = kbase + (kt + 2) * 64;
            #pragma unroll
            for (int it = 0; it < 4; it++) {
                const int row = crow0 + it * 16;
                CP_ASYNC16(sbase + OFF_K(stg) * 4 + row * 144 + cseg * 16,
                           k + (size_t)(kb2 + row) * DM + hcol + cseg * 8);
                CP_ASYNC16(sbase + OFF_V(stg) * 4 + row * 144 + cseg * 16,
                           vt + (size_t)(hcol + row) * MROWS + kb2 + cseg * 8);
            }
            CP_COMMIT();
            if (t < 64) {
                ((float*)(smu + OFF_M(stg)))[t] = mreg ? 0.f : -1e9f;
                if (kt + 3 < 32) mreg = mask[b * SEQ + (kt + 3) * 64 + t];
            }
        }

        const uint32_t* Ks = smu + OFF_K(cur);
        const uint32_t* Vs = smu + OFF_V(cur);
        const float* madd  = (const float*)(smu + OFF_M(cur));

        // ---- S = (Q*log2e/8) K^T ----
        float s[2][8][4];
        #pragma unroll
        for (int mi = 0; mi < 2; mi++)
            #pragma unroll
            for (int nt = 0; nt < 8; nt++)
                #pragma unroll
                for (int j = 0; j < 4; j++) s[mi][nt][j] = 0.f;

        #pragma unroll
        for (int ks = 0; ks < 4; ks++) {
            const int kw = ks * 8 + kq;
            #pragma unroll
            for (int nt = 0; nt < 8; nt++) {
                const int rb = (nt * 8 + g) * KW + kw;
                uint32_t bb0 = Ks[rb];
                uint32_t bb1 = Ks[rb + 4];
                #pragma unroll
                for (int mi = 0; mi < 2; mi++)
                    MMA_F16(s[mi][nt][0], s[mi][nt][1], s[mi][nt][2], s[mi][nt][3],
                            qf[mi][ks][0], qf[mi][ks][1],
                            qf[mi][ks][2], qf[mi][ks][3], bb0, bb1);
            }
        }

        // ---- Online softmax (exp2 domain, half2 ex2) ----
        uint32_t ph[2][8][2];
        #pragma unroll
        for (int mi = 0; mi < 2; mi++) {
            float rmax0 = -1e30f, rmax1 = -1e30f;
            #pragma unroll
            for (int nt = 0; nt < 8; nt++) {
                float2 md = *(float2*)&madd[nt * 8 + 2 * kq];
                s[mi][nt][0] += md.x; s[mi][nt][1] += md.y;
                s[mi][nt][2] += md.x; s[mi][nt][3] += md.y;
                rmax0 = fmaxf(rmax0, fmaxf(s[mi][nt][0], s[mi][nt][1]));
                rmax1 = fmaxf(rmax1, fmaxf(s[mi][nt][2], s[mi][nt][3]));
            }
            rmax0 = fmaxf(rmax0, __shfl_xor_sync(0xffffffffu, rmax0, 1));
            rmax0 = fmaxf(rmax0, __shfl_xor_sync(0xffffffffu, rmax0, 2));
            rmax1 = fmaxf(rmax1, __shfl_xor_sync(0xffffffffu, rmax1, 1));
            rmax1 = fmaxf(rmax1, __shfl_xor_sync(0xffffffffu, rmax1, 2));

            const float mn0 = fmaxf(mx[mi][0], rmax0);
            const float mn1 = fmaxf(mx[mi][1], rmax1);
            const float a0  = ex2f(mx[mi][0] - mn0);
            const float a1  = ex2f(mx[mi][1] - mn1);
            mx[mi][0] = mn0;
            mx[mi][1] = mn1;

            #pragma unroll
            for (int nt = 0; nt < 8; nt++) {
                __half2 e0 = h2exp2(__floats2half2_rn(s[mi][nt][0] - mn0,
                                                      s[mi][nt][1] - mn0));
                __half2 e1 = h2exp2(__floats2half2_rn(s[mi][nt][2] - mn1,
                                                      s[mi][nt][3] - mn1));
                ph[mi][nt][0] = h2u(e0);
                ph[mi][nt][1] = h2u(e1);
            }

            if (!__all_sync(0xffffffffu, (a0 == 1.f) & (a1 == 1.f))) {
                #pragma unroll
                for (int nt = 0; nt < 8; nt++) {
                    acc[mi][nt][0] *= a0; acc[mi][nt][1] *= a0;
                    acc[mi][nt][2] *= a1; acc[mi][nt][3] *= a1;
                }
                accS[mi][0] *= a0; accS[mi][1] *= a0;
                accS[mi][2] *= a1; accS[mi][3] *= a1;
            }
        }

        // ---- O += P V (+ row sums via constant-ones B) ----
        #pragma unroll
        for (int ks = 0; ks < 4; ks++) {
            const int kw = ks * 8 + kq;
            #pragma unroll
            for (int nt = 0; nt < 8; nt++) {
                const int rb = (nt * 8 + g) * KW + kw;
                uint32_t bb0 = Vs[rb];
                uint32_t bb1 = Vs[rb + 4];
                #pragma unroll
                for (int mi = 0; mi < 2; mi++)
                    MMA_F16(acc[mi][nt][0], acc[mi][nt][1],
                            acc[mi][nt][2], acc[mi][nt][3],
                            ph[mi][2 * ks][0],     ph[mi][2 * ks][1],
                            ph[mi][2 * ks + 1][0], ph[mi][2 * ks + 1][1],
                            bb0, bb1);
            }
            #pragma unroll
            for (int mi = 0; mi < 2; mi++)
                MMA_F16(accS[mi][0], accS[mi][1], accS[mi][2], accS[mi][3],
                        ph[mi][2 * ks][0],     ph[mi][2 * ks][1],
                        ph[mi][2 * ks + 1][0], ph[mi][2 * ks + 1][1],
                        ONES2, ONES2);
        }
    }

    // ---- Finalize: fp16 output (denominator from the ones-MMA tile) ----
    #pragma unroll
    for (int mi = 0; mi < 2; mi++) {
        const float inv0 = (accS[mi][0] > 0.f) ? 1.f / accS[mi][0] : 0.f;
        const float inv1 = (accS[mi][2] > 0.f) ? 1.f / accS[mi][2] : 0.f;
        const int row0 = qbase + wr + mi * 16 + g;
        #pragma unroll
        for (int nt = 0; nt < 8; nt++) {
            const int col = hcol + nt * 8 + 2 * kq;
            *(__half2*)(o16 + (size_t)row0 * DM + col) =
                __floats2half2_rn(acc[mi][nt][0] * inv0, acc[mi][nt][1] * inv0);
            *(__half2*)(o16 + (size_t)(row0 + 8) * DM + col) =
                __floats2half2_rn(acc[mi][nt][2] * inv1, acc[mi][nt][3] * inv1);
        }
    }
}

// ---------------------------------------------------------------------------
// Launch
// ---------------------------------------------------------------------------
extern "C" void kernel_launch(void* const* d_in, const int* in_sizes, int n_in,
                              void* d_out, int out_size)
{
    const float* Q    = (const float*)d_in[0];
    const float* K    = (const float*)d_in[1];
    const float* V    = (const float*)d_in[2];
    const int*   mask = (const int*)  d_in[3];
    const float* Wq   = (const float*)d_in[4];
    const float* bq   = (const float*)d_in[5];
    const float* Wk   = (const float*)d_in[6];
    const float* bk   = (const float*)d_in[7];
    const float* Wv   = (const float*)d_in[8];
    const float* bv   = (const float*)d_in[9];
    const float* Wo   = (const float*)d_in[10];
    const float* bo   = (const float*)d_in[11];
    float* out = (float*)d_out;

    __half *gin, *gwt, *gq16, *gk16, *gvt16, *gatt;
    cudaGetSymbolAddress((void**)&gin,   g_in16);
    cudaGetSymbolAddress((void**)&gwt,   g_wt16);
    cudaGetSymbolAddress((void**)&gq16,  g_q16);
    cudaGetSymbolAddress((void**)&gk16,  g_k16);
    cudaGetSymbolAddress((void**)&gvt16, g_vt16);
    cudaGetSymbolAddress((void**)&gatt,  g_att16);

    __half* inq = gin + 0 * (size_t)MROWS * DM;
    __half* ink = gin + 1 * (size_t)MROWS * DM;
    __half* inv = gin + 2 * (size_t)MROWS * DM;
    __half* wtq = gwt + 0 * (size_t)DM * DM;
    __half* wtk = gwt + 1 * (size_t)DM * DM;
    __half* wtv = gwt + 2 * (size_t)DM * DM;
    __half* wto = gwt + 3 * (size_t)DM * DM;

    cudaFuncSetAttribute(gemm_f16_k, cudaFuncAttributeMaxDynamicSharedMemorySize,
                         GEMM_SMEM);
    cudaFuncSetAttribute(attn_f16_k, cudaFuncAttributeMaxDynamicSharedMemorySize,
                         ATT_SMEM);

    cvt_in_k<<<1184, 256>>>(Q, K, V, gin);
    dim3 tgrid(DM / 32, DM / 32, 4);
    dim3 tblk(32, 8);
    round_wt16_k<<<tgrid, tblk>>>(Wq, Wk, Wv, Wo, gwt);

    dim3 qkv_grid(DM / 128, MROWS / 128, 3);  // (8, 64, 3)
    dim3 out_grid(DM / 128, MROWS / 128, 1);  // (8, 64, 1)
    dim3 attn_grid(NB * NH, SEQ / 128);       // (64, 16)

    gemm_f16_k<<<qkv_grid, 128, GEMM_SMEM>>>(inq, ink, inv, wtq, wtk, wtv,
                                             bq, bk, bv, nullptr,
                                             gq16, gk16, gvt16, 1);
    attn_f16_k<<<attn_grid, 128, ATT_SMEM>>>(gq16, gk16, gvt16, mask, gatt);
    gemm_f16_k<<<out_grid, 128, GEMM_SMEM>>>(gatt, gatt, gatt, wto, wto, wto,
                                             bo, bo, bo, out,
                                             nullptr, nullptr, nullptr, 0);
}

// round 16
// speedup vs baseline: 1.8274x; 1.0270x over previous
#include <cuda_runtime.h>
#include <cuda_fp16.h>
#include <math.h>
#include <stdint.h>

// Problem constants
#define NB   4
#define SEQ  2048
#define DM   1024
#define NH   16
#define HD   64
#define MROWS (NB*SEQ)          // 8192

// Q pre-scale: (1/sqrt(64)) * log2(e) so attention works in exp2 domain
#define QSCALE 0.18033688011111364f

// Scratch (device globals — no allocation allowed)
__device__ __half g_in16[3][MROWS*DM];   // fp16(Q,K,V inputs)
__device__ __half g_wt16[4][DM*DM];      // fp16 transposed weights [n][k]
__device__ __half g_q16 [MROWS*DM];      // fp16 q (pre-scaled by log2e/8)
__device__ __half g_k16 [MROWS*DM];      // fp16 k, natural [token][d]
__device__ __half g_vt16[MROWS*DM];      // fp16 v TRANSPOSED [d][token]
__device__ __half g_att16[MROWS*DM];     // fp16 attention output

__device__ __forceinline__ uint32_t smem_u32(const void* p) {
    uint32_t a;
    asm("{ .reg .u64 t; cvta.to.shared.u64 t, %1; cvt.u32.u64 %0, t; }"
        : "=r"(a) : "l"(p));
    return a;
}
__device__ __forceinline__ uint32_t h2u(__half2 h) {
    return *(uint32_t*)&h;
}
__device__ __forceinline__ float ex2f(float x) {
    float y;
    asm("ex2.approx.f32 %0, %1;" : "=f"(y) : "f"(x));
    return y;
}

#define CP_ASYNC16(dst, src) \
    asm volatile("cp.async.cg.shared.global [%0], [%1], 16;" \
                 :: "r"(dst), "l"(src) : "memory")
#define CP_COMMIT() asm volatile("cp.async.commit_group;" ::: "memory")
#define CP_WAIT0()  asm volatile("cp.async.wait_group 0;" ::: "memory")
#define CP_WAIT1()  asm volatile("cp.async.wait_group 1;" ::: "memory")

#define MMA_F16(c0, c1, c2, c3, a0, a1, a2, a3, b0, b1) \
    asm volatile("mma.sync.aligned.m16n8k16.row.col.f32.f16.f16.f32 " \
        "{%0,%1,%2,%3}, {%4,%5,%6,%7}, {%8,%9}, {%0,%1,%2,%3};" \
        : "+f"(c0), "+f"(c1), "+f"(c2), "+f"(c3) \
        : "r"(a0), "r"(a1), "r"(a2), "r"(a3), "r"(b0), "r"(b1))

// ---------------------------------------------------------------------------
// Input convert: g_in16[z] = fp16_rn(input_z), z in {Q,K,V}.
// ---------------------------------------------------------------------------
__global__ __launch_bounds__(256) void cvt_in_k(
    const float* __restrict__ Q, const float* __restrict__ K,
    const float* __restrict__ V, __half* __restrict__ D)
{
    const int n4 = MROWS * DM / 4;
    for (int i = blockIdx.x * blockDim.x + threadIdx.x; i < 3 * n4;
         i += gridDim.x * blockDim.x) {
        const int w = i / n4, j = i - w * n4;
        const float* S = (w == 0) ? Q : (w == 1) ? K : V;
        float4 v = *(const float4*)(S + 4 * (size_t)j);
        __half2* d = (__half2*)(D + (size_t)w * MROWS * DM + 4 * (size_t)j);
        d[0] = __floats2half2_rn(v.x, v.y);
        d[1] = __floats2half2_rn(v.z, v.w);
    }
}

// ---------------------------------------------------------------------------
// Weight transpose + fp16 round: D[z][n*DM+k] = fp16_rn(W_z[k*DM+n]).
// ---------------------------------------------------------------------------
__global__ __launch_bounds__(256) void round_wt16_k(
    const float* __restrict__ W0, const float* __restrict__ W1,
    const float* __restrict__ W2, const float* __restrict__ W3,
    __half* __restrict__ D)
{
    __shared__ float tile[32][33];
    const int z = blockIdx.z;
    const float* W = (z == 0) ? W0 : (z == 1) ? W1 : (z == 2) ? W2 : W3;
    __half* Dw = D + (size_t)z * DM * DM;

    const int tx = threadIdx.x, ty = threadIdx.y;
    const int x = blockIdx.x * 32 + tx;
    #pragma unroll
    for (int j = ty; j < 32; j += 8)
        tile[j][tx] = W[(size_t)(blockIdx.y * 32 + j) * DM + x];
    __syncthreads();
    const int x2 = blockIdx.y * 32 + tx;
    #pragma unroll
    for (int j = ty; j < 32; j += 8)
        Dw[(size_t)(blockIdx.x * 32 + j) * DM + x2] = __float2half_rn(tile[tx][j]);
}

// ---------------------------------------------------------------------------
// fp16 tensor-core GEMM (mma.m16n8k16), cp.async double-buffered. (R13 form.)
// qkv=1: z=0 -> fp16 out scaled QSCALE (Q); z=1 -> fp16 out (K);
//        z=2 -> fp16 out TRANSPOSED [d][token] (V).
// qkv=0: fp32 out (final output GEMM).
// ---------------------------------------------------------------------------
#define LDHW 20                       // words per row (40 halves)
#define SSTG 20480                    // bytes per stage (A 10240 + B 10240)
#define GOFF_A(s) ((s) * SSTG)
#define GOFF_B(s) ((s) * SSTG + 10240)
#define GEMM_SMEM (2 * SSTG)          // 40960 B

__global__ __launch_bounds__(128, 2) void gemm_f16_k(
    const __half* __restrict__ A0, const __half* __restrict__ A1,
    const __half* __restrict__ A2,
    const __half* __restrict__ W0, const __half* __restrict__ W1,
    const __half* __restrict__ W2,
    const float* __restrict__ b0_, const float* __restrict__ b1_,
    const float* __restrict__ b2_,
    float* __restrict__ C0,
    __half* __restrict__ H0, __half* __restrict__ H1, __half* __restrict__ H2,
    int qkv)
{
    extern __shared__ uint32_t smg[];
    const uint32_t sbase = smem_u32(smg);

    const int z = blockIdx.z;
    const __half* A    = (z == 0) ? A0 : (z == 1) ? A1 : A2;
    const __half* Wt   = (z == 0) ? W0 : (z == 1) ? W1 : W2;
    const float*  bias = (z == 0) ? b0_ : (z == 1) ? b1_ : b2_;
    __half*       H    = (z == 0) ? H0 : (z == 1) ? H1 : H2;

    const int t    = threadIdx.x;
    const int lane = t & 31;
    const int wid  = t >> 5;
    const int m0   = blockIdx.y * 128;
    const int n0   = blockIdx.x * 128;
    const int wm   = (wid & 1) * 64;
    const int wn   = (wid >> 1) * 64;
    const int g    = lane >> 2;
    const int kq   = lane & 3;

    const int ar  = t >> 2;            // 0..31
    const int acb = (t & 3) << 4;      // byte 0,16,32,48
    const int ach = acb >> 1;          // half offset

    float acc[4][8][4];
    #pragma unroll
    for (int mi = 0; mi < 4; mi++)
        #pragma unroll
        for (int nj = 0; nj < 8; nj++)
            #pragma unroll
            for (int r = 0; r < 4; r++) acc[mi][nj][r] = 0.f;

    #pragma unroll
    for (int i = 0; i < 4; i++) {
        const int row = ar + i * 32;
        CP_ASYNC16(sbase + GOFF_A(0) + row * 80 + acb,
                   A + (size_t)(m0 + row) * DM + ach);
        CP_ASYNC16(sbase + GOFF_B(0) + row * 80 + acb,
                   Wt + (size_t)(n0 + row) * DM + ach);
    }
    CP_COMMIT();

    #pragma unroll 1
    for (int kt = 0; kt < 32; kt++) {
        const int cur = kt & 1;
        const int nxt = cur ^ 1;

        CP_WAIT0();
        __syncthreads();

        if (kt + 1 < 32) {
            const int kf = (kt + 1) * 32;
            #pragma unroll
            for (int i = 0; i < 4; i++) {
                const int row = ar + i * 32;
                CP_ASYNC16(sbase + GOFF_A(nxt) + row * 80 + acb,
                           A + (size_t)(m0 + row) * DM + kf + ach);
                CP_ASYNC16(sbase + GOFF_B(nxt) + row * 80 + acb,
                           Wt + (size_t)(n0 + row) * DM + kf + ach);
            }
            CP_COMMIT();
        }

        const uint32_t* As = smg + (GOFF_A(cur) >> 2);
        const uint32_t* Bs = smg + (GOFF_B(cur) >> 2);

        #pragma unroll
        for (int ks = 0; ks < 2; ks++) {
            const int kw = ks * 8 + kq;
            uint32_t af[4][4];
            #pragma unroll
            for (int mi = 0; mi < 4; mi++) {
                const int w0 = (wm + mi * 16 + g) * LDHW + kw;
                af[mi][0] = As[w0];
                af[mi][1] = As[w0 + 8 * LDHW];
                af[mi][2] = As[w0 + 4];
                af[mi][3] = As[w0 + 8 * LDHW + 4];
            }
            #pragma unroll
            for (int nj = 0; nj < 8; nj++) {
                const int wb = (wn + nj * 8 + g) * LDHW + kw;
                uint32_t bb0 = Bs[wb];
                uint32_t bb1 = Bs[wb + 4];
                #pragma unroll
                for (int mi = 0; mi < 4; mi++)
                    MMA_F16(acc[mi][nj][0], acc[mi][nj][1],
                            acc[mi][nj][2], acc[mi][nj][3],
                            af[mi][0], af[mi][1], af[mi][2], af[mi][3],
                            bb0, bb1);
            }
        }
    }

    const float oscale = (qkv && z == 0) ? QSCALE : 1.0f;
    #pragma unroll
    for (int mi = 0; mi < 4; mi++) {
        const int row = m0 + wm + mi * 16 + g;
        #pragma unroll
        for (int nj = 0; nj < 8; nj++) {
            const int col = n0 + wn + nj * 8 + kq * 2;
            const float bx = bias[col], by = bias[col + 1];
            const float v0 = acc[mi][nj][0] + bx, v1 = acc[mi][nj][1] + by;
            const float v2 = acc[mi][nj][2] + bx, v3 = acc[mi][nj][3] + by;
            if (!qkv) {
                *(float2*)(C0 + (size_t)row * DM + col)       = make_float2(v0, v1);
                *(float2*)(C0 + (size_t)(row + 8) * DM + col) = make_float2(v2, v3);
            } else if (z < 2) {
                *(__half2*)(H + (size_t)row * DM + col) =
                    __floats2half2_rn(v0 * oscale, v1 * oscale);
                *(__half2*)(H + (size_t)(row + 8) * DM + col) =
                    __floats2half2_rn(v2 * oscale, v3 * oscale);
            } else {   // V: transposed [d][token]
                H[(size_t)col * MROWS + row]           = __float2half_rn(v0);
                H[(size_t)(col + 1) * MROWS + row]     = __float2half_rn(v1);
                H[(size_t)col * MROWS + row + 8]       = __float2half_rn(v2);
                H[(size_t)(col + 1) * MROWS + row + 8] = __float2half_rn(v3);
            }
        }
    }
}

// ---------------------------------------------------------------------------
// fp16 tensor-core flash attention (mma.m16n8k16), 3-stage cp.async pipeline.
// exp2-domain softmax fully in half2 SIMD: pack S, HADD2 mask, HMAX2 tree,
// HSUB2, h2exp2. Mask staged as half2 with -30000 sentinel (finite in fp16,
// exp2 -> 0). Row sums via constant-ones MMA; rescale skipped by warp vote.
// ---------------------------------------------------------------------------
#define KW 36                          // words per row (72 halves)
#define ASTG (2 * 64 * KW + 64)        // stage: K + V + madd = 4672 words
#define OFF_K(s)  ((s) * ASTG)
#define OFF_V(s)  ((s) * ASTG + 64 * KW)
#define OFF_M(s)  ((s) * ASTG + 2 * 64 * KW)
#define OFF_Q     (3 * ASTG)           // 14016
#define ATT_WORDS (OFF_Q + 128 * KW)   // 18624 words
#define ATT_SMEM  (ATT_WORDS * 4)      // 74496 B
#define ONES2 0x3C003C00u              // half2 {1.0, 1.0}
#define MSENT -30000.f                 // mask sentinel (finite in fp16)

__global__ __launch_bounds__(128, 2) void attn_f16_k(
    const __half* __restrict__ q, const __half* __restrict__ k,
    const __half* __restrict__ vt, const int* __restrict__ mask,
    __half* __restrict__ o16)
{
    extern __shared__ uint32_t smu[];
    const uint32_t sbase = smem_u32(smu);

    const int t    = threadIdx.x;
    const int lane = t & 31;
    const int wid  = t >> 5;           // 0..3
    const int g    = lane >> 2;
    const int kq   = lane & 3;
    const int bh   = blockIdx.x;
    const int b    = bh >> 4;
    const int h    = bh & 15;
    const int qt   = blockIdx.y;

    const int qbase = b * SEQ + qt * 128;
    const int kbase = b * SEQ;
    const int hcol  = h * HD;
    const int wr    = wid * 32;

    const int crow0 = t >> 3;          // 0..15
    const int cseg  = t & 7;

    // ---- Prologue: G0 = Q + chunk0 K/V; G1 = chunk1 K/V ----
    #pragma unroll
    for (int it = 0; it < 8; it++) {
        const int row = crow0 + it * 16;
        CP_ASYNC16(sbase + OFF_Q * 4 + row * 144 + cseg * 16,
                   q + (size_t)(qbase + row) * DM + hcol + cseg * 8);
    }
    #pragma unroll
    for (int it = 0; it < 4; it++) {
        const int row = crow0 + it * 16;
        CP_ASYNC16(sbase + OFF_K(0) * 4 + row * 144 + cseg * 16,
                   k + (size_t)(kbase + row) * DM + hcol + cseg * 8);
        CP_ASYNC16(sbase + OFF_V(0) * 4 + row * 144 + cseg * 16,
                   vt + (size_t)(hcol + row) * MROWS + kbase + cseg * 8);
    }
    CP_COMMIT();
    #pragma unroll
    for (int it = 0; it < 4; it++) {
        const int row = crow0 + it * 16;
        CP_ASYNC16(sbase + OFF_K(1) * 4 + row * 144 + cseg * 16,
                   k + (size_t)(kbase + 64 + row) * DM + hcol + cseg * 8);
        CP_ASYNC16(sbase + OFF_V(1) * 4 + row * 144 + cseg * 16,
                   vt + (size_t)(hcol + row) * MROWS + kbase + 64 + cseg * 8);
    }
    CP_COMMIT();
    if (t < 32) {
        #pragma unroll
        for (int pc = 0; pc < 2; pc++) {
            const int m0 = mask[b * SEQ + pc * 64 + 2 * t];
            const int m1 = mask[b * SEQ + pc * 64 + 2 * t + 1];
            ((__half2*)(smu + OFF_M(pc)))[t] =
                __floats2half2_rn(m0 ? 0.f : MSENT, m1 ? 0.f : MSENT);
        }
    }
    int mr0 = 0, mr1 = 0;
    if (t < 32) {
        mr0 = mask[b * SEQ + 128 + 2 * t];
        mr1 = mask[b * SEQ + 128 + 2 * t + 1];
    }

    CP_WAIT1();        // G0 (Q + chunk0) landed; G1 may be in flight
    __syncthreads();

    // ---- Pull Q A-fragments ----
    uint32_t qf[2][4][4];
    {
        const uint32_t* Qw = smu + OFF_Q;
        #pragma unroll
        for (int mi = 0; mi < 2; mi++)
            #pragma unroll
            for (int ks = 0; ks < 4; ks++) {
                const int kw = ks * 8 + kq;
                const int r0 = (wr + mi * 16 + g) * KW;
                qf[mi][ks][0] = Qw[r0 + kw];
                qf[mi][ks][1] = Qw[r0 + 8 * KW + kw];
                qf[mi][ks][2] = Qw[r0 + kw + 4];
                qf[mi][ks][3] = Qw[r0 + 8 * KW + kw + 4];
            }
    }

    float mx[2][2];
    #pragma unroll
    for (int mi = 0; mi < 2; mi++) { mx[mi][0] = -1e30f; mx[mi][1] = -1e30f; }
    float acc[2][8][4];
    float accS[2][4];
    #pragma unroll
    for (int mi = 0; mi < 2; mi++) {
        #pragma unroll
        for (int nt = 0; nt < 8; nt++)
            #pragma unroll
            for (int j = 0; j < 4; j++) acc[mi][nt][j] = 0.f;
        #pragma unroll
        for (int j = 0; j < 4; j++) accS[mi][j] = 0.f;
    }

    #pragma unroll 1
    for (int kt = 0; kt < 32; kt++) {
        const int cur = kt % 3;

        if (kt > 0) {
            if (kt + 1 < 32) CP_WAIT1(); else CP_WAIT0();
            __syncthreads();
        }

        if (kt + 2 < 32) {
            const int stg = (kt + 2) % 3;
            const int kb2 = kbase + (kt + 2) * 64;
            #pragma unroll
            for (int it = 0; it < 4; it++) {
                const int row = crow0 + it * 16;
                CP_ASYNC16(sbase + OFF_K(stg) * 4 + row * 144 + cseg * 16,
                           k + (size_t)(kb2 + row) * DM + hcol + cseg * 8);
                CP_ASYNC16(sbase + OFF_V(stg) * 4 + row * 144 + cseg * 16,
                           vt + (size_t)(hcol + row) * MROWS + kb2 + cseg * 8);
            }
            CP_COMMIT();
            if (t < 32) {
                ((__half2*)(smu + OFF_M(stg)))[t] =
                    __floats2half2_rn(mr0 ? 0.f : MSENT, mr1 ? 0.f : MSENT);
                if (kt + 3 < 32) {
                    mr0 = mask[b * SEQ + (kt + 3) * 64 + 2 * t];
                    mr1 = mask[b * SEQ + (kt + 3) * 64 + 2 * t + 1];
                }
            }
        }

        const uint32_t* Ks = smu + OFF_K(cur);
        const uint32_t* Vs = smu + OFF_V(cur);
        const __half2* madd2 = (const __half2*)(smu + OFF_M(cur));

        // ---- S = (Q*log2e/8) K^T ----
        float s[2][8][4];
        #pragma unroll
        for (int mi = 0; mi < 2; mi++)
            #pragma unroll
            for (int nt = 0; nt < 8; nt++)
                #pragma unroll
                for (int j = 0; j < 4; j++) s[mi][nt][j] = 0.f;

        #pragma unroll
        for (int ks = 0; ks < 4; ks++) {
            const int kw = ks * 8 + kq;
            #pragma unroll
            for (int nt = 0; nt < 8; nt++) {
                const int rb = (nt * 8 + g) * KW + kw;
                uint32_t bb0 = Ks[rb];
                uint32_t bb1 = Ks[rb + 4];
                #pragma unroll
                for (int mi = 0; mi < 2; mi++)
                    MMA_F16(s[mi][nt][0], s[mi][nt][1], s[mi][nt][2], s[mi][nt][3],
                            qf[mi][ks][0], qf[mi][ks][1],
                            qf[mi][ks][2], qf[mi][ks][3], bb0, bb1);
            }
        }

        // ---- Online softmax: half2 SIMD datapath ----
        uint32_t ph[2][8][2];
        #pragma unroll
        for (int mi = 0; mi < 2; mi++) {
            __half2 sh[8][2];
            __half2 hm0 = __half2half2(__float2half_rn(-60000.f));
            __half2 hm1 = hm0;
            #pragma unroll
            for (int nt = 0; nt < 8; nt++) {
                const __half2 m2 = madd2[nt * 4 + kq];
                sh[nt][0] = __hadd2(__floats2half2_rn(s[mi][nt][0], s[mi][nt][1]), m2);
                sh[nt][1] = __hadd2(__floats2half2_rn(s[mi][nt][2], s[mi][nt][3]), m2);
                hm0 = __hmax2(hm0, sh[nt][0]);
                hm1 = __hmax2(hm1, sh[nt][1]);
            }
            // pack row-g / row-g+8 maxima into one half2, reduce across 4 lanes
            __half2 rm = __halves2half2(
                __hmax(__low2half(hm0), __high2half(hm0)),
                __hmax(__low2half(hm1), __high2half(hm1)));
            {
                uint32_t u = h2u(rm), v;
                v = __shfl_xor_sync(0xffffffffu, u, 1);
                rm = __hmax2(rm, *(__half2*)&v);
                u = h2u(rm);
                v = __shfl_xor_sync(0xffffffffu, u, 2);
                rm = __hmax2(rm, *(__half2*)&v);
            }
            const float rmax0 = __low2float(rm);
            const float rmax1 = __high2float(rm);

            const float mn0 = fmaxf(mx[mi][0], rmax0);
            const float mn1 = fmaxf(mx[mi][1], rmax1);
            const float a0  = ex2f(mx[mi][0] - mn0);
            const float a1  = ex2f(mx[mi][1] - mn1);
            mx[mi][0] = mn0;
            mx[mi][1] = mn1;

            const __half2 hmn0 = __float2half2_rn(mn0);
            const __half2 hmn1 = __float2half2_rn(mn1);
            #pragma unroll
            for (int nt = 0; nt < 8; nt++) {
                ph[mi][nt][0] = h2u(h2exp2(__hsub2(sh[nt][0], hmn0)));
                ph[mi][nt][1] = h2u(h2exp2(__hsub2(sh[nt][1], hmn1)));
            }

            if (!__all_sync(0xffffffffu, (a0 == 1.f) & (a1 == 1.f))) {
                #pragma unroll
                for (int nt = 0; nt < 8; nt++) {
                    acc[mi][nt][0] *= a0; acc[mi][nt][1] *= a0;
                    acc[mi][nt][2] *= a1; acc[mi][nt][3] *= a1;
                }
                accS[mi][0] *= a0; accS[mi][1] *= a0;
                accS[mi][2] *= a1; accS[mi][3] *= a1;
            }
        }

        // ---- O += P V (+ row sums via constant-ones B) ----
        #pragma unroll
        for (int ks = 0; ks < 4; ks++) {
            const int kw = ks * 8 + kq;
            #pragma unroll
            for (int nt = 0; nt < 8; nt++) {
                const int rb = (nt * 8 + g) * KW + kw;
                uint32_t bb0 = Vs[rb];
                uint32_t bb1 = Vs[rb + 4];
                #pragma unroll
                for (int mi = 0; mi < 2; mi++)
                    MMA_F16(acc[mi][nt][0], acc[mi][nt][1],
                            acc[mi][nt][2], acc[mi][nt][3],
                            ph[mi][2 * ks][0],     ph[mi][2 * ks][1],
                            ph[mi][2 * ks + 1][0], ph[mi][2 * ks + 1][1],
                            bb0, bb1);
            }
            #pragma unroll
            for (int mi = 0; mi < 2; mi++)
                MMA_F16(accS[mi][0], accS[mi][1], accS[mi][2], accS[mi][3],
                        ph[mi][2 * ks][0],     ph[mi][2 * ks][1],
                        ph[mi][2 * ks + 1][0], ph[mi][2 * ks + 1][1],
                        ONES2, ONES2);
        }
    }

    // ---- Finalize: fp16 output (denominator from the ones-MMA tile) ----
    #pragma unroll
    for (int mi = 0; mi < 2; mi++) {
        const float inv0 = (accS[mi][0] > 0.f) ? 1.f / accS[mi][0] : 0.f;
        const float inv1 = (accS[mi][2] > 0.f) ? 1.f / accS[mi][2] : 0.f;
        const int row0 = qbase + wr + mi * 16 + g;
        #pragma unroll
        for (int nt = 0; nt < 8; nt++) {
            const int col = hcol + nt * 8 + 2 * kq;
            *(__half2*)(o16 + (size_t)row0 * DM + col) =
                __floats2half2_rn(acc[mi][nt][0] * inv0, acc[mi][nt][1] * inv0);
            *(__half2*)(o16 + (size_t)(row0 + 8) * DM + col) =
                __floats2half2_rn(acc[mi][nt][2] * inv1, acc[mi][nt][3] * inv1);
        }
    }
}

// ---------------------------------------------------------------------------
// Launch
// ---------------------------------------------------------------------------
extern "C" void kernel_launch(void* const* d_in, const int* in_sizes, int n_in,
                              void* d_out, int out_size)
{
    const float* Q    = (const float*)d_in[0];
    const float* K    = (const float*)d_in[1];
    const float* V    = (const float*)d_in[2];
    const int*   mask = (const int*)  d_in[3];
    const float* Wq   = (const float*)d_in[4];
    const float* bq   = (const float*)d_in[5];
    const float* Wk   = (const float*)d_in[6];
    const float* bk   = (const float*)d_in[7];
    const float* Wv   = (const float*)d_in[8];
    const float* bv   = (const float*)d_in[9];
    const float* Wo   = (const float*)d_in[10];
    const float* bo   = (const float*)d_in[11];
    float* out = (float*)d_out;

    __half *gin, *gwt, *gq16, *gk16, *gvt16, *gatt;
    cudaGetSymbolAddress((void**)&gin,   g_in16);
    cudaGetSymbolAddress((void**)&gwt,   g_wt16);
    cudaGetSymbolAddress((void**)&gq16,  g_q16);
    cudaGetSymbolAddress((void**)&gk16,  g_k16);
    cudaGetSymbolAddress((void**)&gvt16, g_vt16);
    cudaGetSymbolAddress((void**)&gatt,  g_att16);

    __half* inq = gin + 0 * (size_t)MROWS * DM;
    __half* ink = gin + 1 * (size_t)MROWS * DM;
    __half* inv = gin + 2 * (size_t)MROWS * DM;
    __half* wtq = gwt + 0 * (size_t)DM * DM;
    __half* wtk = gwt + 1 * (size_t)DM * DM;
    __half* wtv = gwt + 2 * (size_t)DM * DM;
    __half* wto = gwt + 3 * (size_t)DM * DM;

    cudaFuncSetAttribute(gemm_f16_k, cudaFuncAttributeMaxDynamicSharedMemorySize,
                         GEMM_SMEM);
    cudaFuncSetAttribute(attn_f16_k, cudaFuncAttributeMaxDynamicSharedMemorySize,
                         ATT_SMEM);

    cvt_in_k<<<1184, 256>>>(Q, K, V, gin);
    dim3 tgrid(DM / 32, DM / 32, 4);
    dim3 tblk(32, 8);
    round_wt16_k<<<tgrid, tblk>>>(Wq, Wk, Wv, Wo, gwt);

    dim3 qkv_grid(DM / 128, MROWS / 128, 3);  // (8, 64, 3)
    dim3 out_grid(DM / 128, MROWS / 128, 1);  // (8, 64, 1)
    dim3 attn_grid(NB * NH, SEQ / 128);       // (64, 16)

    gemm_f16_k<<<qkv_grid, 128, GEMM_SMEM>>>(inq, ink, inv, wtq, wtk, wtv,
                                             bq, bk, bv, nullptr,
                                             gq16, gk16, gvt16, 1);
    attn_f16_k<<<attn_grid, 128, ATT_SMEM>>>(gq16, gk16, gvt16, mask, gatt);
    gemm_f16_k<<<out_grid, 128, GEMM_SMEM>>>(gatt, gatt, gatt, wto, wto, wto,
                                             bo, bo, bo, out,
                                             nullptr, nullptr, nullptr, 0);
}

// round 17
// speedup vs baseline: 1.9735x; 1.0799x over previous
#include <cuda_runtime.h>
#include <cuda_fp16.h>
#include <math.h>
#include <stdint.h>

// Problem constants
#define NB   4
#define SEQ  2048
#define DM   1024
#define NH   16
#define HD   64
#define MROWS (NB*SEQ)          // 8192

// Q pre-scale: (1/sqrt(64)) * log2(e) so attention works in exp2 domain
#define QSCALE 0.18033688011111364f

// Scratch (device globals — no allocation allowed)
__device__ __half g_in16[3][MROWS*DM];   // fp16(Q,K,V inputs)
__device__ __half g_wt16[4][DM*DM];      // fp16 transposed weights [n][k]
__device__ __half g_q16 [MROWS*DM];      // fp16 q (pre-scaled by log2e/8)
__device__ __half g_k16 [MROWS*DM];      // fp16 k, natural [token][d]
__device__ __half g_vt16[MROWS*DM];      // fp16 v TRANSPOSED [d][token]
__device__ __half g_att16[MROWS*DM];     // fp16 attention output

__device__ __forceinline__ uint32_t smem_u32(const void* p) {
    uint32_t a;
    asm("{ .reg .u64 t; cvta.to.shared.u64 t, %1; cvt.u32.u64 %0, t; }"
        : "=r"(a) : "l"(p));
    return a;
}
__device__ __forceinline__ uint32_t h2u(__half2 h) {
    return *(uint32_t*)&h;
}
__device__ __forceinline__ float ex2f(float x) {
    float y;
    asm("ex2.approx.f32 %0, %1;" : "=f"(y) : "f"(x));
    return y;
}

#define CP_ASYNC16(dst, src) \
    asm volatile("cp.async.cg.shared.global [%0], [%1], 16;" \
                 :: "r"(dst), "l"(src) : "memory")
#define CP_COMMIT() asm volatile("cp.async.commit_group;" ::: "memory")
#define CP_WAIT0()  asm volatile("cp.async.wait_group 0;" ::: "memory")
#define CP_WAIT1()  asm volatile("cp.async.wait_group 1;" ::: "memory")

#define MMA_F16(c0, c1, c2, c3, a0, a1, a2, a3, b0, b1) \
    asm volatile("mma.sync.aligned.m16n8k16.row.col.f32.f16.f16.f32 " \
        "{%0,%1,%2,%3}, {%4,%5,%6,%7}, {%8,%9}, {%0,%1,%2,%3};" \
        : "+f"(c0), "+f"(c1), "+f"(c2), "+f"(c3) \
        : "r"(a0), "r"(a1), "r"(a2), "r"(a3), "r"(b0), "r"(b1))

// ---------------------------------------------------------------------------
// Input convert: g_in16[z] = fp16_rn(input_z), z in {Q,K,V}.
// ---------------------------------------------------------------------------
__global__ __launch_bounds__(256) void cvt_in_k(
    const float* __restrict__ Q, const float* __restrict__ K,
    const float* __restrict__ V, __half* __restrict__ D)
{
    const int n4 = MROWS * DM / 4;
    for (int i = blockIdx.x * blockDim.x + threadIdx.x; i < 3 * n4;
         i += gridDim.x * blockDim.x) {
        const int w = i / n4, j = i - w * n4;
        const float* S = (w == 0) ? Q : (w == 1) ? K : V;
        float4 v = *(const float4*)(S + 4 * (size_t)j);
        __half2* d = (__half2*)(D + (size_t)w * MROWS * DM + 4 * (size_t)j);
        d[0] = __floats2half2_rn(v.x, v.y);
        d[1] = __floats2half2_rn(v.z, v.w);
    }
}

// ---------------------------------------------------------------------------
// Weight transpose + fp16 round: D[z][n*DM+k] = fp16_rn(W_z[k*DM+n]).
// ---------------------------------------------------------------------------
__global__ __launch_bounds__(256) void round_wt16_k(
    const float* __restrict__ W0, const float* __restrict__ W1,
    const float* __restrict__ W2, const float* __restrict__ W3,
    __half* __restrict__ D)
{
    __shared__ float tile[32][33];
    const int z = blockIdx.z;
    const float* W = (z == 0) ? W0 : (z == 1) ? W1 : (z == 2) ? W2 : W3;
    __half* Dw = D + (size_t)z * DM * DM;

    const int tx = threadIdx.x, ty = threadIdx.y;
    const int x = blockIdx.x * 32 + tx;
    #pragma unroll
    for (int j = ty; j < 32; j += 8)
        tile[j][tx] = W[(size_t)(blockIdx.y * 32 + j) * DM + x];
    __syncthreads();
    const int x2 = blockIdx.y * 32 + tx;
    #pragma unroll
    for (int j = ty; j < 32; j += 8)
        Dw[(size_t)(blockIdx.x * 32 + j) * DM + x2] = __float2half_rn(tile[tx][j]);
}

// ---------------------------------------------------------------------------
// fp16 tensor-core GEMM (mma.m16n8k16), BK=64 halves, cp.async double-buffer.
// 128 threads = 4 warps (2m x 2n), warp 64x64, CTA 128x128, 16 k-chunks.
// Per chunk per warp: 128 LDS : 128 MMA; one wait+barrier per 64-k.
//   As[2][128][72h] : A chunk [m][k]   (frag bank 4g+kq, CF)
//   Bs[2][128][72h] : Wt chunk [n][k]
// qkv=1: z=0 -> fp16 out scaled QSCALE (Q); z=1 -> fp16 out (K);
//        z=2 -> fp16 out TRANSPOSED [d][token] (V).    qkv=0: fp32 out.
// ---------------------------------------------------------------------------
#define GKW 36                        // words per row (72 halves)
#define GSTGB (2 * 128 * GKW * 4)     // bytes per stage (A+B) = 36864
#define GOFF_A(s) ((s) * GSTGB)
#define GOFF_B(s) ((s) * GSTGB + 128 * GKW * 4)
#define GEMM_SMEM (2 * GSTGB)         // 73728 B

__global__ __launch_bounds__(128, 2) void gemm_f16_k(
    const __half* __restrict__ A0, const __half* __restrict__ A1,
    const __half* __restrict__ A2,
    const __half* __restrict__ W0, const __half* __restrict__ W1,
    const __half* __restrict__ W2,
    const float* __restrict__ b0_, const float* __restrict__ b1_,
    const float* __restrict__ b2_,
    float* __restrict__ C0,
    __half* __restrict__ H0, __half* __restrict__ H1, __half* __restrict__ H2,
    int qkv)
{
    extern __shared__ uint32_t smg[];
    const uint32_t sbase = smem_u32(smg);

    const int z = blockIdx.z;
    const __half* A    = (z == 0) ? A0 : (z == 1) ? A1 : A2;
    const __half* Wt   = (z == 0) ? W0 : (z == 1) ? W1 : W2;
    const float*  bias = (z == 0) ? b0_ : (z == 1) ? b1_ : b2_;
    __half*       H    = (z == 0) ? H0 : (z == 1) ? H1 : H2;

    const int t    = threadIdx.x;
    const int lane = t & 31;
    const int wid  = t >> 5;
    const int m0   = blockIdx.y * 128;
    const int n0   = blockIdx.x * 128;
    const int wm   = (wid & 1) * 64;
    const int wn   = (wid >> 1) * 64;
    const int g    = lane >> 2;
    const int kq   = lane & 3;

    // cp.async mapping: row = crow0 + i*16 (i=0..7), seg = 16B slice of 128B row
    const int crow0 = t >> 3;          // 0..15
    const int cseg  = t & 7;

    float acc[4][8][4];
    #pragma unroll
    for (int mi = 0; mi < 4; mi++)
        #pragma unroll
        for (int nj = 0; nj < 8; nj++)
            #pragma unroll
            for (int r = 0; r < 4; r++) acc[mi][nj][r] = 0.f;

    // ---- Prologue: chunk 0 ----
    #pragma unroll
    for (int i = 0; i < 8; i++) {
        const int row = crow0 + i * 16;
        CP_ASYNC16(sbase + GOFF_A(0) + row * 144 + cseg * 16,
                   A + (size_t)(m0 + row) * DM + cseg * 8);
        CP_ASYNC16(sbase + GOFF_B(0) + row * 144 + cseg * 16,
                   Wt + (size_t)(n0 + row) * DM + cseg * 8);
    }
    CP_COMMIT();

    #pragma unroll 1
    for (int kt = 0; kt < 16; kt++) {
        const int cur = kt & 1;
        const int nxt = cur ^ 1;

        CP_WAIT0();
        __syncthreads();

        if (kt + 1 < 16) {
            const int kf = (kt + 1) * 64;     // half offset
            #pragma unroll
            for (int i = 0; i < 8; i++) {
                const int row = crow0 + i * 16;
                CP_ASYNC16(sbase + GOFF_A(nxt) + row * 144 + cseg * 16,
                           A + (size_t)(m0 + row) * DM + kf + cseg * 8);
                CP_ASYNC16(sbase + GOFF_B(nxt) + row * 144 + cseg * 16,
                           Wt + (size_t)(n0 + row) * DM + kf + cseg * 8);
            }
            CP_COMMIT();
        }

        const uint32_t* As = smg + (GOFF_A(cur) >> 2);
        const uint32_t* Bs = smg + (GOFF_B(cur) >> 2);

        #pragma unroll
        for (int ks = 0; ks < 4; ks++) {      // four k16 steps per 64-half chunk
            const int kw = ks * 8 + kq;       // word offset within row
            uint32_t af[4][4];
            #pragma unroll
            for (int mi = 0; mi < 4; mi++) {
                const int w0 = (wm + mi * 16 + g) * GKW + kw;
                af[mi][0] = As[w0];
                af[mi][1] = As[w0 + 8 * GKW];
                af[mi][2] = As[w0 + 4];
                af[mi][3] = As[w0 + 8 * GKW + 4];
            }
            #pragma unroll
            for (int nj = 0; nj < 8; nj++) {
                const int wb = (wn + nj * 8 + g) * GKW + kw;
                uint32_t bb0 = Bs[wb];
                uint32_t bb1 = Bs[wb + 4];
                #pragma unroll
                for (int mi = 0; mi < 4; mi++)
                    MMA_F16(acc[mi][nj][0], acc[mi][nj][1],
                            acc[mi][nj][2], acc[mi][nj][3],
                            af[mi][0], af[mi][1], af[mi][2], af[mi][3],
                            bb0, bb1);
            }
        }
    }

    const float oscale = (qkv && z == 0) ? QSCALE : 1.0f;
    #pragma unroll
    for (int mi = 0; mi < 4; mi++) {
        const int row = m0 + wm + mi * 16 + g;
        #pragma unroll
        for (int nj = 0; nj < 8; nj++) {
            const int col = n0 + wn + nj * 8 + kq * 2;
            const float bx = bias[col], by = bias[col + 1];
            const float v0 = acc[mi][nj][0] + bx, v1 = acc[mi][nj][1] + by;
            const float v2 = acc[mi][nj][2] + bx, v3 = acc[mi][nj][3] + by;
            if (!qkv) {
                *(float2*)(C0 + (size_t)row * DM + col)       = make_float2(v0, v1);
                *(float2*)(C0 + (size_t)(row + 8) * DM + col) = make_float2(v2, v3);
            } else if (z < 2) {
                *(__half2*)(H + (size_t)row * DM + col) =
                    __floats2half2_rn(v0 * oscale, v1 * oscale);
                *(__half2*)(H + (size_t)(row + 8) * DM + col) =
                    __floats2half2_rn(v2 * oscale, v3 * oscale);
            } else {   // V: transposed [d][token]
                H[(size_t)col * MROWS + row]           = __float2half_rn(v0);
                H[(size_t)(col + 1) * MROWS + row]     = __float2half_rn(v1);
                H[(size_t)col * MROWS + row + 8]       = __float2half_rn(v2);
                H[(size_t)(col + 1) * MROWS + row + 8] = __float2half_rn(v3);
            }
        }
    }
}

// ---------------------------------------------------------------------------
// fp16 tensor-core flash attention (mma.m16n8k16), 3-stage cp.async pipeline.
// Unchanged from R16 (passing, 224us): half2 SIMD softmax in exp2 domain,
// ones-MMA row sums, rescale-skip vote.
// ---------------------------------------------------------------------------
#define KW 36                          // words per row (72 halves)
#define ASTG (2 * 64 * KW + 64)        // stage: K + V + madd = 4672 words
#define OFF_K(s)  ((s) * ASTG)
#define OFF_V(s)  ((s) * ASTG + 64 * KW)
#define OFF_M(s)  ((s) * ASTG + 2 * 64 * KW)
#define OFF_Q     (3 * ASTG)           // 14016
#define ATT_WORDS (OFF_Q + 128 * KW)   // 18624 words
#define ATT_SMEM  (ATT_WORDS * 4)      // 74496 B
#define ONES2 0x3C003C00u              // half2 {1.0, 1.0}
#define MSENT -30000.f                 // mask sentinel (finite in fp16)

__global__ __launch_bounds__(128, 2) void attn_f16_k(
    const __half* __restrict__ q, const __half* __restrict__ k,
    const __half* __restrict__ vt, const int* __restrict__ mask,
    __half* __restrict__ o16)
{
    extern __shared__ uint32_t smu[];
    const uint32_t sbase = smem_u32(smu);

    const int t    = threadIdx.x;
    const int lane = t & 31;
    const int wid  = t >> 5;           // 0..3
    const int g    = lane >> 2;
    const int kq   = lane & 3;
    const int bh   = blockIdx.x;
    const int b    = bh >> 4;
    const int h    = bh & 15;
    const int qt   = blockIdx.y;

    const int qbase = b * SEQ + qt * 128;
    const int kbase = b * SEQ;
    const int hcol  = h * HD;
    const int wr    = wid * 32;

    const int crow0 = t >> 3;          // 0..15
    const int cseg  = t & 7;

    // ---- Prologue: G0 = Q + chunk0 K/V; G1 = chunk1 K/V ----
    #pragma unroll
    for (int it = 0; it < 8; it++) {
        const int row = crow0 + it * 16;
        CP_ASYNC16(sbase + OFF_Q * 4 + row * 144 + cseg * 16,
                   q + (size_t)(qbase + row) * DM + hcol + cseg * 8);
    }
    #pragma unroll
    for (int it = 0; it < 4; it++) {
        const int row = crow0 + it * 16;
        CP_ASYNC16(sbase + OFF_K(0) * 4 + row * 144 + cseg * 16,
                   k + (size_t)(kbase + row) * DM + hcol + cseg * 8);
        CP_ASYNC16(sbase + OFF_V(0) * 4 + row * 144 + cseg * 16,
                   vt + (size_t)(hcol + row) * MROWS + kbase + cseg * 8);
    }
    CP_COMMIT();
    #pragma unroll
    for (int it = 0; it < 4; it++) {
        const int row = crow0 + it * 16;
        CP_ASYNC16(sbase + OFF_K(1) * 4 + row * 144 + cseg * 16,
                   k + (size_t)(kbase + 64 + row) * DM + hcol + cseg * 8);
        CP_ASYNC16(sbase + OFF_V(1) * 4 + row * 144 + cseg * 16,
                   vt + (size_t)(hcol + row) * MROWS + kbase + 64 + cseg * 8);
    }
    CP_COMMIT();
    if (t < 32) {
        #pragma unroll
        for (int pc = 0; pc < 2; pc++) {
            const int m0 = mask[b * SEQ + pc * 64 + 2 * t];
            const int m1 = mask[b * SEQ + pc * 64 + 2 * t + 1];
            ((__half2*)(smu + OFF_M(pc)))[t] =
                __floats2half2_rn(m0 ? 0.f : MSENT, m1 ? 0.f : MSENT);
        }
    }
    int mr0 = 0, mr1 = 0;
    if (t < 32) {
        mr0 = mask[b * SEQ + 128 + 2 * t];
        mr1 = mask[b * SEQ + 128 + 2 * t + 1];
    }

    CP_WAIT1();
    __syncthreads();

    // ---- Pull Q A-fragments ----
    uint32_t qf[2][4][4];
    {
        const uint32_t* Qw = smu + OFF_Q;
        #pragma unroll
        for (int mi = 0; mi < 2; mi++)
            #pragma unroll
            for (int ks = 0; ks < 4; ks++) {
                const int kw = ks * 8 + kq;
                const int r0 = (wr + mi * 16 + g) * KW;
                qf[mi][ks][0] = Qw[r0 + kw];
                qf[mi][ks][1] = Qw[r0 + 8 * KW + kw];
                qf[mi][ks][2] = Qw[r0 + kw + 4];
                qf[mi][ks][3] = Qw[r0 + 8 * KW + kw + 4];
            }
    }

    float mx[2][2];
    #pragma unroll
    for (int mi = 0; mi < 2; mi++) { mx[mi][0] = -1e30f; mx[mi][1] = -1e30f; }
    float acc[2][8][4];
    float accS[2][4];
    #pragma unroll
    for (int mi = 0; mi < 2; mi++) {
        #pragma unroll
        for (int nt = 0; nt < 8; nt++)
            #pragma unroll
            for (int j = 0; j < 4; j++) acc[mi][nt][j] = 0.f;
        #pragma unroll
        for (int j = 0; j < 4; j++) accS[mi][j] = 0.f;
    }

    #pragma unroll 1
    for (int kt = 0; kt < 32; kt++) {
        const int cur = kt % 3;

        if (kt > 0) {
            if (kt + 1 < 32) CP_WAIT1(); else CP_WAIT0();
            __syncthreads();
        }

        if (kt + 2 < 32) {
            const int stg = (kt + 2) % 3;
            const int kb2 = kbase + (kt + 2) * 64;
            #pragma unroll
            for (int it = 0; it < 4; it++) {
                const int row = crow0 + it * 16;
                CP_ASYNC16(sbase + OFF_K(stg) * 4 + row * 144 + cseg * 16,
                           k + (size_t)(kb2 + row) * DM + hcol + cseg * 8);
                CP_ASYNC16(sbase + OFF_V(stg) * 4 + row * 144 + cseg * 16,
                           vt + (size_t)(hcol + row) * MROWS + kb2 + cseg * 8);
            }
            CP_COMMIT();
            if (t < 32) {
                ((__half2*)(smu + OFF_M(stg)))[t] =
                    __floats2half2_rn(mr0 ? 0.f : MSENT, mr1 ? 0.f : MSENT);
                if (kt + 3 < 32) {
                    mr0 = mask[b * SEQ + (kt + 3) * 64 + 2 * t];
                    mr1 = mask[b * SEQ + (kt + 3) * 64 + 2 * t + 1];
                }
            }
        }

        const uint32_t* Ks = smu + OFF_K(cur);
        const uint32_t* Vs = smu + OFF_V(cur);
        const __half2* madd2 = (const __half2*)(smu + OFF_M(cur));

        // ---- S = (Q*log2e/8) K^T ----
        float s[2][8][4];
        #pragma unroll
        for (int mi = 0; mi < 2; mi++)
            #pragma unroll
            for (int nt = 0; nt < 8; nt++)
                #pragma unroll
                for (int j = 0; j < 4; j++) s[mi][nt][j] = 0.f;

        #pragma unroll
        for (int ks = 0; ks < 4; ks++) {
            const int kw = ks * 8 + kq;
            #pragma unroll
            for (int nt = 0; nt < 8; nt++) {
                const int rb = (nt * 8 + g) * KW + kw;
                uint32_t bb0 = Ks[rb];
                uint32_t bb1 = Ks[rb + 4];
                #pragma unroll
                for (int mi = 0; mi < 2; mi++)
                    MMA_F16(s[mi][nt][0], s[mi][nt][1], s[mi][nt][2], s[mi][nt][3],
                            qf[mi][ks][0], qf[mi][ks][1],
                            qf[mi][ks][2], qf[mi][ks][3], bb0, bb1);
            }
        }

        // ---- Online softmax: half2 SIMD datapath ----
        uint32_t ph[2][8][2];
        #pragma unroll
        for (int mi = 0; mi < 2; mi++) {
            __half2 sh[8][2];
            __half2 hm0 = __half2half2(__float2half_rn(-60000.f));
            __half2 hm1 = hm0;
            #pragma unroll
            for (int nt = 0; nt < 8; nt++) {
                const __half2 m2 = madd2[nt * 4 + kq];
                sh[nt][0] = __hadd2(__floats2half2_rn(s[mi][nt][0], s[mi][nt][1]), m2);
                sh[nt][1] = __hadd2(__floats2half2_rn(s[mi][nt][2], s[mi][nt][3]), m2);
                hm0 = __hmax2(hm0, sh[nt][0]);
                hm1 = __hmax2(hm1, sh[nt][1]);
            }
            __half2 rm = __halves2half2(
                __hmax(__low2half(hm0), __high2half(hm0)),
                __hmax(__low2half(hm1), __high2half(hm1)));
            {
                uint32_t u = h2u(rm), v;
                v = __shfl_xor_sync(0xffffffffu, u, 1);
                rm = __hmax2(rm, *(__half2*)&v);
                u = h2u(rm);
                v = __shfl_xor_sync(0xffffffffu, u, 2);
                rm = __hmax2(rm, *(__half2*)&v);
            }
            const float rmax0 = __low2float(rm);
            const float rmax1 = __high2float(rm);

            const float mn0 = fmaxf(mx[mi][0], rmax0);
            const float mn1 = fmaxf(mx[mi][1], rmax1);
            const float a0  = ex2f(mx[mi][0] - mn0);
            const float a1  = ex2f(mx[mi][1] - mn1);
            mx[mi][0] = mn0;
            mx[mi][1] = mn1;

            const __half2 hmn0 = __float2half2_rn(mn0);
            const __half2 hmn1 = __float2half2_rn(mn1);
            #pragma unroll
            for (int nt = 0; nt < 8; nt++) {
                ph[mi][nt][0] = h2u(h2exp2(__hsub2(sh[nt][0], hmn0)));
                ph[mi][nt][1] = h2u(h2exp2(__hsub2(sh[nt][1], hmn1)));
            }

            if (!__all_sync(0xffffffffu, (a0 == 1.f) & (a1 == 1.f))) {
                #pragma unroll
                for (int nt = 0; nt < 8; nt++) {
                    acc[mi][nt][0] *= a0; acc[mi][nt][1] *= a0;
                    acc[mi][nt][2] *= a1; acc[mi][nt][3] *= a1;
                }
                accS[mi][0] *= a0; accS[mi][1] *= a0;
                accS[mi][2] *= a1; accS[mi][3] *= a1;
            }
        }

        // ---- O += P V (+ row sums via constant-ones B) ----
        #pragma unroll
        for (int ks = 0; ks < 4; ks++) {
            const int kw = ks * 8 + kq;
            #pragma unroll
            for (int nt = 0; nt < 8; nt++) {
                const int rb = (nt * 8 + g) * KW + kw;
                uint32_t bb0 = Vs[rb];
                uint32_t bb1 = Vs[rb + 4];
                #pragma unroll
                for (int mi = 0; mi < 2; mi++)
                    MMA_F16(acc[mi][nt][0], acc[mi][nt][1],
                            acc[mi][nt][2], acc[mi][nt][3],
                            ph[mi][2 * ks][0],     ph[mi][2 * ks][1],
                            ph[mi][2 * ks + 1][0], ph[mi][2 * ks + 1][1],
                            bb0, bb1);
            }
            #pragma unroll
            for (int mi = 0; mi < 2; mi++)
                MMA_F16(accS[mi][0], accS[mi][1], accS[mi][2], accS[mi][3],
                        ph[mi][2 * ks][0],     ph[mi][2 * ks][1],
                        ph[mi][2 * ks + 1][0], ph[mi][2 * ks + 1][1],
                        ONES2, ONES2);
        }
    }

    // ---- Finalize: fp16 output (denominator from the ones-MMA tile) ----
    #pragma unroll
    for (int mi = 0; mi < 2; mi++) {
        const float inv0 = (accS[mi][0] > 0.f) ? 1.f / accS[mi][0] : 0.f;
        const float inv1 = (accS[mi][2] > 0.f) ? 1.f / accS[mi][2] : 0.f;
        const int row0 = qbase + wr + mi * 16 + g;
        #pragma unroll
        for (int nt = 0; nt < 8; nt++) {
            const int col = hcol + nt * 8 + 2 * kq;
            *(__half2*)(o16 + (size_t)row0 * DM + col) =
                __floats2half2_rn(acc[mi][nt][0] * inv0, acc[mi][nt][1] * inv0);
            *(__half2*)(o16 + (size_t)(row0 + 8) * DM + col) =
                __floats2half2_rn(acc[mi][nt][2] * inv1, acc[mi][nt][3] * inv1);
        }
    }
}

// ---------------------------------------------------------------------------
// Launch
// ---------------------------------------------------------------------------
extern "C" void kernel_launch(void* const* d_in, const int* in_sizes, int n_in,
                              void* d_out, int out_size)
{
    const float* Q    = (const float*)d_in[0];
    const float* K    = (const float*)d_in[1];
    const float* V    = (const float*)d_in[2];
    const int*   mask = (const int*)  d_in[3];
    const float* Wq   = (const float*)d_in[4];
    const float* bq   = (const float*)d_in[5];
    const float* Wk   = (const float*)d_in[6];
    const float* bk   = (const float*)d_in[7];
    const float* Wv   = (const float*)d_in[8];
    const float* bv   = (const float*)d_in[9];
    const float* Wo   = (const float*)d_in[10];
    const float* bo   = (const float*)d_in[11];
    float* out = (float*)d_out;

    __half *gin, *gwt, *gq16, *gk16, *gvt16, *gatt;
    cudaGetSymbolAddress((void**)&gin,   g_in16);
    cudaGetSymbolAddress((void**)&gwt,   g_wt16);
    cudaGetSymbolAddress((void**)&gq16,  g_q16);
    cudaGetSymbolAddress((void**)&gk16,  g_k16);
    cudaGetSymbolAddress((void**)&gvt16, g_vt16);
    cudaGetSymbolAddress((void**)&gatt,  g_att16);

    __half* inq = gin + 0 * (size_t)MROWS * DM;
    __half* ink = gin + 1 * (size_t)MROWS * DM;
    __half* inv = gin + 2 * (size_t)MROWS * DM;
    __half* wtq = gwt + 0 * (size_t)DM * DM;
    __half* wtk = gwt + 1 * (size_t)DM * DM;
    __half* wtv = gwt + 2 * (size_t)DM * DM;
    __half* wto = gwt + 3 * (size_t)DM * DM;

    cudaFuncSetAttribute(gemm_f16_k, cudaFuncAttributeMaxDynamicSharedMemorySize,
                         GEMM_SMEM);
    cudaFuncSetAttribute(attn_f16_k, cudaFuncAttributeMaxDynamicSharedMemorySize,
                         ATT_SMEM);

    cvt_in_k<<<1184, 256>>>(Q, K, V, gin);
    dim3 tgrid(DM / 32, DM / 32, 4);
    dim3 tblk(32, 8);
    round_wt16_k<<<tgrid, tblk>>>(Wq, Wk, Wv, Wo, gwt);

    dim3 qkv_grid(DM / 128, MROWS / 128, 3);  // (8, 64, 3)
    dim3 out_grid(DM / 128, MROWS / 128, 1);  // (8, 64, 1)
    dim3 attn_grid(NB * NH, SEQ / 128);       // (64, 16)

    gemm_f16_k<<<qkv_grid, 128, GEMM_SMEM>>>(inq, ink, inv, wtq, wtk, wtv,
                                             bq, bk, bv, nullptr,
                                             gq16, gk16, gvt16, 1);
    attn_f16_k<<<attn_grid, 128, ATT_SMEM>>>(gq16, gk16, gvt16, mask, gatt);
    gemm_f16_k<<<out_grid, 128, GEMM_SMEM>>>(gatt, gatt, gatt, wto, wto, wto,
                                             bo, bo, bo, out,
                                             nullptr, nullptr, nullptr, 0);
}